// round 8
// baseline (speedup 1.0000x reference)
#include <cuda_runtime.h>
#include <cuda_bf16.h>
#include <math.h>
#include <stdint.h>

#define BSZ   2
#define SEQ   2048
#define HID   2048
#define NH    32
#define NG    8
#define HD    64
#define KVD   512
#define MROWS 4096

// ---------------- scratch ---------------------------------------------------
__device__ __nv_bfloat16 s_x_hi [MROWS * HID];
__device__ __nv_bfloat16 s_x_lo [MROWS * HID];
__device__ __nv_bfloat16 s_wq_hi[HID * HID];
__device__ __nv_bfloat16 s_wq_lo[HID * HID];
__device__ __nv_bfloat16 s_wk_hi[KVD * HID];
__device__ __nv_bfloat16 s_wk_lo[KVD * HID];
__device__ __nv_bfloat16 s_wv_hi[KVD * HID];
__device__ __nv_bfloat16 s_wv_lo[KVD * HID];
__device__ __nv_bfloat16 s_wo_hi[HID * HID];
__device__ __nv_bfloat16 s_wo_lo[HID * HID];
__device__ float g_v  [MROWS * KVD];
__device__ __nv_bfloat16 s_qr_hi[BSZ * NH * SEQ * HD];
__device__ __nv_bfloat16 s_qr_lo[BSZ * NH * SEQ * HD];
__device__ __nv_bfloat16 s_kr_hi[BSZ * NG * SEQ * HD];
__device__ __nv_bfloat16 s_kr_lo[BSZ * NG * SEQ * HD];
__device__ __nv_bfloat16 s_vt_hi[BSZ * NG * HD * SEQ];   // [b,g,d,s]
__device__ __nv_bfloat16 s_vt_lo[BSZ * NG * HD * SEQ];
__device__ __nv_bfloat16 s_at_hi[MROWS * HID];
__device__ __nv_bfloat16 s_at_lo[MROWS * HID];
__device__ float g_att[MROWS * HID];   // fp32 attention output (for F-tiles of O-proj)

// ---------------- helpers ---------------------------------------------------
__device__ __forceinline__ void cp_async16(void* smem_ptr, const void* gptr) {
    uint32_t s = (uint32_t)__cvta_generic_to_shared(smem_ptr);
    asm volatile("cp.async.cg.shared.global [%0], [%1], 16;\n" :: "r"(s), "l"(gptr));
}
#define CP_COMMIT()  asm volatile("cp.async.commit_group;\n" ::: "memory")
#define CP_WAIT(n)   asm volatile("cp.async.wait_group %0;\n" :: "n"(n) : "memory")

#define MMA_BF16(Cc, Aa, Bb) asm volatile( \
    "mma.sync.aligned.m16n8k16.row.col.f32.bf16.bf16.f32 " \
    "{%0,%1,%2,%3},{%4,%5,%6,%7},{%8,%9},{%0,%1,%2,%3};\n" \
    : "+f"(Cc[0]), "+f"(Cc[1]), "+f"(Cc[2]), "+f"(Cc[3]) \
    : "r"(Aa[0]), "r"(Aa[1]), "r"(Aa[2]), "r"(Aa[3]), "r"(Bb[0]), "r"(Bb[1]))

#define FMA2(Cc, Aa, Bb) asm("fma.rn.f32x2 %0, %1, %2, %0;" \
    : "+l"(Cc) : "l"(Aa), "l"(Bb))

__device__ __forceinline__ uint32_t pack2(float x0, float x1, uint32_t& lo_out) {
    __nv_bfloat16 h0 = __float2bfloat16(x0);
    __nv_bfloat16 h1 = __float2bfloat16(x1);
    __nv_bfloat16 l0 = __float2bfloat16(x0 - __bfloat162float(h0));
    __nv_bfloat16 l1 = __float2bfloat16(x1 - __bfloat162float(h1));
    __nv_bfloat162 H = __halves2bfloat162(h0, h1);
    __nv_bfloat162 L = __halves2bfloat162(l0, l1);
    lo_out = *(uint32_t*)&L;
    return *(uint32_t*)&H;
}

// ---------------- elementwise split fp32 -> bf16 hi/lo ----------------------
__global__ void split_kernel(const float* __restrict__ in,
                             __nv_bfloat16* __restrict__ hi,
                             __nv_bfloat16* __restrict__ lo, int n)
{
    int i = (blockIdx.x * blockDim.x + threadIdx.x) * 2;
    if (i >= n) return;
    float2 v = *(const float2*)&in[i];
    uint32_t lw, hw = pack2(v.x, v.y, lw);
    *(uint32_t*)&hi[i] = hw;
    *(uint32_t*)&lo[i] = lw;
}

// ---------------- 3x bf16-split GEMM core macros ----------------------------
#define LDG_   40
#define GSTAGE (4 * 128 * LDG_)
#define GEMM_SMEM (2 * GSTAGE * 2)

#define G_PROLOG()                                                           \
    const int tid  = threadIdx.x;                                            \
    const int lane = tid & 31;                                               \
    const int w    = tid >> 5;                                               \
    const int wm   = w >> 2;                                                 \
    const int wn   = w & 3;                                                  \
    const int grp  = lane >> 2;                                              \
    const int tig  = lane & 3;                                               \
    float c[4][4][4];                                                        \
    _Pragma("unroll")                                                        \
    for (int mt = 0; mt < 4; mt++)                                           \
        _Pragma("unroll")                                                    \
        for (int nt = 0; nt < 4; nt++)                                       \
            _Pragma("unroll")                                                \
            for (int i = 0; i < 4; i++) c[mt][nt][i] = 0.f;

#define G_LOAD_STAGE(sidx, k0) do {                                          \
    __nv_bfloat16* Ash_ = smb + (sidx) * GSTAGE;                             \
    __nv_bfloat16* Asl_ = Ash_ + 128 * LDG_;                                 \
    __nv_bfloat16* Wsh_ = Asl_ + 128 * LDG_;                                 \
    __nv_bfloat16* Wsl_ = Wsh_ + 128 * LDG_;                                 \
    _Pragma("unroll")                                                        \
    for (int j_ = 0; j_ < 2; j_++) {                                         \
        int cch_ = tid + j_ * 256;                                           \
        int r_   = cch_ >> 2;                                                \
        int off_ = (cch_ & 3) * 8;                                           \
        cp_async16(Ash_ + r_ * LDG_ + off_, Ah + (size_t)(m0 + r_) * K + (k0) + off_); \
        cp_async16(Asl_ + r_ * LDG_ + off_, Al + (size_t)(m0 + r_) * K + (k0) + off_); \
        cp_async16(Wsh_ + r_ * LDG_ + off_, Wh + (size_t)(n0 + r_) * K + (k0) + off_); \
        cp_async16(Wsl_ + r_ * LDG_ + off_, Wl + (size_t)(n0 + r_) * K + (k0) + off_); \
    }                                                                        \
    CP_COMMIT();                                                             \
} while (0)

#define G_MAINLOOP()                                                         \
    G_LOAD_STAGE(0, 0);                                                      \
    const int NIT = K >> 5;                                                  \
    for (int it = 0; it < NIT; it++) {                                       \
        int s = it & 1;                                                      \
        if (it + 1 < NIT) { G_LOAD_STAGE(s ^ 1, (it + 1) << 5); CP_WAIT(1); }\
        else             { CP_WAIT(0); }                                     \
        __syncthreads();                                                     \
        const __nv_bfloat16* Ash = smb + s * GSTAGE;                         \
        const __nv_bfloat16* Asl = Ash + 128 * LDG_;                         \
        const __nv_bfloat16* Wsh = Asl + 128 * LDG_;                         \
        const __nv_bfloat16* Wsl = Wsh + 128 * LDG_;                         \
        _Pragma("unroll")                                                    \
        for (int kk = 0; kk < 2; kk++) {                                     \
            const int cc = kk * 16 + tig * 2;                                \
            uint32_t bh[4][2], bl[4][2];                                     \
            _Pragma("unroll")                                                \
            for (int nt = 0; nt < 4; nt++) {                                 \
                int r = wn * 32 + nt * 8 + grp;                              \
                bh[nt][0] = *(const uint32_t*)&Wsh[r * LDG_ + cc];           \
                bh[nt][1] = *(const uint32_t*)&Wsh[r * LDG_ + cc + 8];       \
                bl[nt][0] = *(const uint32_t*)&Wsl[r * LDG_ + cc];           \
                bl[nt][1] = *(const uint32_t*)&Wsl[r * LDG_ + cc + 8];       \
            }                                                                \
            _Pragma("unroll")                                                \
            for (int mt = 0; mt < 4; mt++) {                                 \
                int r = wm * 64 + mt * 16 + grp;                             \
                uint32_t ah[4], al[4];                                       \
                ah[0] = *(const uint32_t*)&Ash[r * LDG_ + cc];               \
                ah[1] = *(const uint32_t*)&Ash[(r + 8) * LDG_ + cc];         \
                ah[2] = *(const uint32_t*)&Ash[r * LDG_ + cc + 8];           \
                ah[3] = *(const uint32_t*)&Ash[(r + 8) * LDG_ + cc + 8];     \
                al[0] = *(const uint32_t*)&Asl[r * LDG_ + cc];               \
                al[1] = *(const uint32_t*)&Asl[(r + 8) * LDG_ + cc];         \
                al[2] = *(const uint32_t*)&Asl[r * LDG_ + cc + 8];           \
                al[3] = *(const uint32_t*)&Asl[(r + 8) * LDG_ + cc + 8];     \
                _Pragma("unroll")                                            \
                for (int nt = 0; nt < 4; nt++) {                             \
                    MMA_BF16(c[mt][nt], ah, bh[nt]);                         \
                    MMA_BF16(c[mt][nt], ah, bl[nt]);                         \
                    MMA_BF16(c[mt][nt], al, bh[nt]);                         \
                }                                                            \
            }                                                                \
        }                                                                    \
        __syncthreads();                                                     \
    }

// ---------------- F-path (fp32 FFMA2) core macros ---------------------------
// 128x128 tile, K-step 16, double-buffered fp32 smem, 8x8/thread via f32x2.
#define F_PROLOG()                                                           \
    const int tid = threadIdx.x;                                             \
    const int ftx = tid & 15, fty = tid >> 4;                                \
    const int fr0 = tid >> 2, fkq = (tid & 3) * 4;                           \
    unsigned long long c2[4][8];                                             \
    _Pragma("unroll")                                                        \
    for (int i = 0; i < 4; i++)                                              \
        _Pragma("unroll")                                                    \
        for (int j = 0; j < 8; j++) c2[i][j] = 0ULL;                         \
    float* As = (float*)smraw;                                               \
    float* Ws = As + 2 * 2048;                                               \
    float4 ra0, ra1, rw0, rw1;

#define F_LDG(k0) do {                                                       \
    ra0 = *(const float4*)&Af[(size_t)(m0 + fr0)      * K + (k0) + fkq];     \
    ra1 = *(const float4*)&Af[(size_t)(m0 + fr0 + 64) * K + (k0) + fkq];     \
    rw0 = *(const float4*)&Wf[(size_t)(n0 + fr0)      * K + (k0) + fkq];     \
    rw1 = *(const float4*)&Wf[(size_t)(n0 + fr0 + 64) * K + (k0) + fkq];     \
} while (0)

#define F_STS(sidx) do {                                                     \
    float* as_ = As + (sidx) * 2048;                                         \
    float* ws_ = Ws + (sidx) * 2048;                                         \
    as_[(fkq+0)*128 + fr0] = ra0.x; as_[(fkq+1)*128 + fr0] = ra0.y;          \
    as_[(fkq+2)*128 + fr0] = ra0.z; as_[(fkq+3)*128 + fr0] = ra0.w;          \
    as_[(fkq+0)*128 + fr0+64] = ra1.x; as_[(fkq+1)*128 + fr0+64] = ra1.y;    \
    as_[(fkq+2)*128 + fr0+64] = ra1.z; as_[(fkq+3)*128 + fr0+64] = ra1.w;    \
    ws_[(fkq+0)*128 + fr0] = rw0.x; ws_[(fkq+1)*128 + fr0] = rw0.y;          \
    ws_[(fkq+2)*128 + fr0] = rw0.z; ws_[(fkq+3)*128 + fr0] = rw0.w;          \
    ws_[(fkq+0)*128 + fr0+64] = rw1.x; ws_[(fkq+1)*128 + fr0+64] = rw1.y;    \
    ws_[(fkq+2)*128 + fr0+64] = rw1.z; ws_[(fkq+3)*128 + fr0+64] = rw1.w;    \
} while (0)

#define F_COMPUTE(sidx) do {                                                 \
    const float* as_ = As + (sidx) * 2048;                                   \
    const float* ws_ = Ws + (sidx) * 2048;                                   \
    _Pragma("unroll")                                                        \
    for (int k = 0; k < 16; k++) {                                           \
        unsigned long long a2[4], bd[8];                                     \
        _Pragma("unroll")                                                    \
        for (int i = 0; i < 4; i++)                                          \
            a2[i] = *(const unsigned long long*)&as_[k*128 + fty*8 + 2*i];   \
        uint4 b0_ = *(const uint4*)&ws_[k*128 + ftx*8];                      \
        uint4 b1_ = *(const uint4*)&ws_[k*128 + ftx*8 + 4];                  \
        asm("mov.b64 %0,{%1,%1};" : "=l"(bd[0]) : "r"(b0_.x));               \
        asm("mov.b64 %0,{%1,%1};" : "=l"(bd[1]) : "r"(b0_.y));               \
        asm("mov.b64 %0,{%1,%1};" : "=l"(bd[2]) : "r"(b0_.z));               \
        asm("mov.b64 %0,{%1,%1};" : "=l"(bd[3]) : "r"(b0_.w));               \
        asm("mov.b64 %0,{%1,%1};" : "=l"(bd[4]) : "r"(b1_.x));               \
        asm("mov.b64 %0,{%1,%1};" : "=l"(bd[5]) : "r"(b1_.y));               \
        asm("mov.b64 %0,{%1,%1};" : "=l"(bd[6]) : "r"(b1_.z));               \
        asm("mov.b64 %0,{%1,%1};" : "=l"(bd[7]) : "r"(b1_.w));               \
        _Pragma("unroll")                                                    \
        for (int i = 0; i < 4; i++)                                          \
            _Pragma("unroll")                                                \
            for (int j = 0; j < 8; j++) FMA2(c2[i][j], a2[i], bd[j]);        \
    }                                                                        \
} while (0)

#define F_MAINLOOP() do {                                                    \
    F_LDG(0); F_STS(0); __syncthreads();                                     \
    const int FNIT = K >> 4;                                                 \
    for (int it = 0; it < FNIT; it++) {                                      \
        if (it + 1 < FNIT) F_LDG((it + 1) << 4);                             \
        F_COMPUTE(it & 1);                                                   \
        __syncthreads();                                                     \
        if (it + 1 < FNIT) { F_STS((it + 1) & 1); __syncthreads(); }         \
    }                                                                        \
} while (0)

#define F_GET(i_, j_, p_, dst_) do {                                         \
    uint32_t lo_, hi_;                                                       \
    asm("mov.b64 {%0,%1}, %2;" : "=r"(lo_), "=r"(hi_) : "l"(c2[i_][j_]));    \
    dst_ = __uint_as_float((p_) ? hi_ : lo_);                                \
} while (0)

// ---------------- plain tensor-only GEMM (V-proj) ---------------------------
__global__ __launch_bounds__(256, 1) void gemm_bf16x3(
    const __nv_bfloat16* __restrict__ Ah, const __nv_bfloat16* __restrict__ Al,
    const __nv_bfloat16* __restrict__ Wh, const __nv_bfloat16* __restrict__ Wl,
    const float* __restrict__ bias, float* __restrict__ C,
    int M, int N, int K)
{
    extern __shared__ __nv_bfloat16 smb[];
    const int m0 = blockIdx.y * 128;
    const int n0 = blockIdx.x * 128;
    G_PROLOG();
    G_MAINLOOP();
#pragma unroll
    for (int mt = 0; mt < 4; mt++) {
#pragma unroll
        for (int nt = 0; nt < 4; nt++) {
            int row = m0 + wm * 64 + mt * 16 + grp;
            int col = n0 + wn * 32 + nt * 8 + tig * 2;
            float2 bv = *(const float2*)&bias[col];
            *(float2*)&C[(size_t)row * N + col] =
                make_float2(c[mt][nt][0] + bv.x, c[mt][nt][1] + bv.y);
            *(float2*)&C[(size_t)(row + 8) * N + col] =
                make_float2(c[mt][nt][2] + bv.x, c[mt][nt][3] + bv.y);
        }
    }
}

// ---------------- tensor-only rope GEMM (K-proj) -----------------------------
__global__ __launch_bounds__(256, 1) void gemm_rope(
    const __nv_bfloat16* __restrict__ Ah, const __nv_bfloat16* __restrict__ Al,
    const __nv_bfloat16* __restrict__ Wh, const __nv_bfloat16* __restrict__ Wl,
    const float* __restrict__ bias, const float* __restrict__ freqs,
    __nv_bfloat16* __restrict__ dsth, __nv_bfloat16* __restrict__ dstl,
    int nheads, int K)
{
    extern __shared__ __nv_bfloat16 smb[];
    const int m0 = blockIdx.y * 128;
    const int n0 = blockIdx.x * 128;
    G_PROLOG();
    G_MAINLOOP();
#pragma unroll
    for (int mt = 0; mt < 4; mt++) {
        int row = m0 + wm * 64 + mt * 16 + grp;
        int b_  = row >> 11;
        int s_  = row & (SEQ - 1);
#pragma unroll
        for (int nt = 0; nt < 4; nt++) {
            int col = n0 + wn * 32 + nt * 8 + tig * 2;
            int h_  = col >> 6;
            int d_  = col & 63;
            float2 bv = *(const float2*)&bias[col];
            float2 f0 = *(const float2*)&freqs[s_ * HD + d_];
            float2 f1 = *(const float2*)&freqs[(s_ + 8) * HD + d_];
            float v0 = c[mt][nt][0] + bv.x, v1 = c[mt][nt][1] + bv.y;
            float v2 = c[mt][nt][2] + bv.x, v3 = c[mt][nt][3] + bv.y;
            uint32_t lw0, hw0 = pack2(v0 * f0.x - v1 * f0.y, v0 * f0.y + v1 * f0.x, lw0);
            uint32_t lw1, hw1 = pack2(v2 * f1.x - v3 * f1.y, v2 * f1.y + v3 * f1.x, lw1);
            size_t o0 = ((size_t)(b_ * nheads + h_) * SEQ + s_) * HD + d_;
            size_t o1 = o0 + (size_t)8 * HD;
            *(uint32_t*)&dsth[o0] = hw0;
            *(uint32_t*)&dstl[o0] = lw0;
            *(uint32_t*)&dsth[o1] = hw1;
            *(uint32_t*)&dstl[o1] = lw1;
        }
    }
}

// ---------------- HYBRID plain GEMM (O-proj): tensor + FFMA2 CTAs ------------
__global__ __launch_bounds__(256, 2) void gemm_hyb_plain(
    const __nv_bfloat16* __restrict__ Ah, const __nv_bfloat16* __restrict__ Al,
    const float* __restrict__ Af,
    const __nv_bfloat16* __restrict__ Wh, const __nv_bfloat16* __restrict__ Wl,
    const float* __restrict__ Wf,
    const float* __restrict__ bias, float* __restrict__ C,
    int M, int N, int K)
{
    extern __shared__ char smraw[];
    const int m0 = blockIdx.y * 128;
    const int n0 = blockIdx.x * 128;
    const int bid = blockIdx.y * gridDim.x + blockIdx.x;
    if (((bid % 7) & 1) == 0) {
        // ---- tensor role ----
        __nv_bfloat16* smb = (__nv_bfloat16*)smraw;
        G_PROLOG();
        G_MAINLOOP();
#pragma unroll
        for (int mt = 0; mt < 4; mt++) {
#pragma unroll
            for (int nt = 0; nt < 4; nt++) {
                int row = m0 + wm * 64 + mt * 16 + grp;
                int col = n0 + wn * 32 + nt * 8 + tig * 2;
                float2 bv = *(const float2*)&bias[col];
                *(float2*)&C[(size_t)row * N + col] =
                    make_float2(c[mt][nt][0] + bv.x, c[mt][nt][1] + bv.y);
                *(float2*)&C[(size_t)(row + 8) * N + col] =
                    make_float2(c[mt][nt][2] + bv.x, c[mt][nt][3] + bv.y);
            }
        }
    } else {
        // ---- FFMA2 role ----
        F_PROLOG();
        F_MAINLOOP();
#pragma unroll
        for (int i = 0; i < 4; i++) {
#pragma unroll
            for (int p = 0; p < 2; p++) {
                int row = m0 + fty * 8 + 2 * i + p;
#pragma unroll
                for (int j = 0; j < 8; j++) {
                    float v; F_GET(i, j, p, v);
                    int col = n0 + ftx * 8 + j;
                    C[(size_t)row * N + col] = v + bias[col];
                }
            }
        }
    }
}

// ---------------- HYBRID rope GEMM (Q-proj) ----------------------------------
__global__ __launch_bounds__(256, 2) void gemm_hyb_rope(
    const __nv_bfloat16* __restrict__ Ah, const __nv_bfloat16* __restrict__ Al,
    const float* __restrict__ Af,
    const __nv_bfloat16* __restrict__ Wh, const __nv_bfloat16* __restrict__ Wl,
    const float* __restrict__ Wf,
    const float* __restrict__ bias, const float* __restrict__ freqs,
    __nv_bfloat16* __restrict__ dsth, __nv_bfloat16* __restrict__ dstl,
    int nheads, int K)
{
    extern __shared__ char smraw[];
    const int m0 = blockIdx.y * 128;
    const int n0 = blockIdx.x * 128;
    const int bid = blockIdx.y * gridDim.x + blockIdx.x;
    if (((bid % 7) & 1) == 0) {
        __nv_bfloat16* smb = (__nv_bfloat16*)smraw;
        G_PROLOG();
        G_MAINLOOP();
#pragma unroll
        for (int mt = 0; mt < 4; mt++) {
            int row = m0 + wm * 64 + mt * 16 + grp;
            int b_  = row >> 11;
            int s_  = row & (SEQ - 1);
#pragma unroll
            for (int nt = 0; nt < 4; nt++) {
                int col = n0 + wn * 32 + nt * 8 + tig * 2;
                int h_  = col >> 6;
                int d_  = col & 63;
                float2 bv = *(const float2*)&bias[col];
                float2 f0 = *(const float2*)&freqs[s_ * HD + d_];
                float2 f1 = *(const float2*)&freqs[(s_ + 8) * HD + d_];
                float v0 = c[mt][nt][0] + bv.x, v1 = c[mt][nt][1] + bv.y;
                float v2 = c[mt][nt][2] + bv.x, v3 = c[mt][nt][3] + bv.y;
                uint32_t lw0, hw0 = pack2(v0 * f0.x - v1 * f0.y, v0 * f0.y + v1 * f0.x, lw0);
                uint32_t lw1, hw1 = pack2(v2 * f1.x - v3 * f1.y, v2 * f1.y + v3 * f1.x, lw1);
                size_t o0 = ((size_t)(b_ * nheads + h_) * SEQ + s_) * HD + d_;
                size_t o1 = o0 + (size_t)8 * HD;
                *(uint32_t*)&dsth[o0] = hw0;
                *(uint32_t*)&dstl[o0] = lw0;
                *(uint32_t*)&dsth[o1] = hw1;
                *(uint32_t*)&dstl[o1] = lw1;
            }
        }
    } else {
        F_PROLOG();
        F_MAINLOOP();
#pragma unroll
        for (int i = 0; i < 4; i++) {
#pragma unroll
            for (int p = 0; p < 2; p++) {
                int row = m0 + fty * 8 + 2 * i + p;
                int b_  = row >> 11;
                int s_  = row & (SEQ - 1);
#pragma unroll
                for (int jp = 0; jp < 4; jp++) {
                    int c0 = n0 + ftx * 8 + 2 * jp;
                    int h_ = c0 >> 6;
                    int d_ = c0 & 63;
                    float v0, v1;
                    F_GET(i, 2 * jp, p, v0);
                    F_GET(i, 2 * jp + 1, p, v1);
                    v0 += bias[c0];
                    v1 += bias[c0 + 1];
                    float2 f = *(const float2*)&freqs[s_ * HD + d_];
                    uint32_t lw, hw = pack2(v0 * f.x - v1 * f.y, v0 * f.y + v1 * f.x, lw);
                    size_t o = ((size_t)(b_ * nheads + h_) * SEQ + s_) * HD + d_;
                    *(uint32_t*)&dsth[o] = hw;
                    *(uint32_t*)&dstl[o] = lw;
                }
            }
        }
    }
}

// V: [b,s,g*64+d] fp32  ->  [b,g,d,s] bf16 hi/lo
__global__ void transpose_v_split(const float* __restrict__ vlin,
                                  __nv_bfloat16* __restrict__ vhi,
                                  __nv_bfloat16* __restrict__ vlo)
{
    int idx = blockIdx.x * blockDim.x + threadIdx.x;
    if (idx >= BSZ * NG * HD * (SEQ / 2)) return;
    int s2 = idx & (SEQ / 2 - 1);
    int d  = (idx >> 10) & (HD - 1);
    int g  = (idx >> 16) & (NG - 1);
    int b  = idx >> 19;
    int s  = s2 * 2;
    float v0 = vlin[(size_t)(b * SEQ + s)     * KVD + g * HD + d];
    float v1 = vlin[(size_t)(b * SEQ + s + 1) * KVD + g * HD + d];
    size_t off = ((size_t)(b * NG + g) * HD + d) * SEQ + s;
    uint32_t lw, hw = pack2(v0, v1, lw);
    *(uint32_t*)&vhi[off] = hw;
    *(uint32_t*)&vlo[off] = lw;
}

// ---------------- flash attention, bf16x3 mma --------------------------------
#define LDB_ 72
#define ATT_SMEM ((2 * 128 * LDB_ + 4 * 64 * LDB_) * 2)

__global__ __launch_bounds__(256, 1) void flash_attn_bf16(
    const __nv_bfloat16* __restrict__ qhi, const __nv_bfloat16* __restrict__ qlo,
    const __nv_bfloat16* __restrict__ khi, const __nv_bfloat16* __restrict__ klo,
    const __nv_bfloat16* __restrict__ vhi, const __nv_bfloat16* __restrict__ vlo,
    __nv_bfloat16* __restrict__ ath, __nv_bfloat16* __restrict__ atl,
    float* __restrict__ attf)
{
    extern __shared__ __nv_bfloat16 smb[];
    __nv_bfloat16* Qh = smb;
    __nv_bfloat16* Ql = Qh + 128 * LDB_;
    __nv_bfloat16* Kh = Ql + 128 * LDB_;
    __nv_bfloat16* Kl = Kh + 64 * LDB_;
    __nv_bfloat16* Vh = Kl + 64 * LDB_;
    __nv_bfloat16* Vl = Vh + 64 * LDB_;

    const int tid  = threadIdx.x;
    const int lane = tid & 31;
    const int w    = tid >> 5;
    const int grp  = lane >> 2;
    const int tig  = lane & 3;
    const int qb   = gridDim.x - 1 - blockIdx.x;
    const int bh_  = blockIdx.y;
    const int b    = bh_ >> 5;
    const int h    = bh_ & 31;
    const int g    = h >> 2;
    const int q0   = qb * 128;
    const size_t qoff  = ((size_t)(b * NH + h) * SEQ + q0) * HD;
    const size_t kvoff = (size_t)(b * NG + g) * SEQ * HD;
    const size_t vtoff = (size_t)(b * NG + g) * HD * SEQ;

    for (int i = tid; i < 1024; i += 256) {
        int r = i >> 3, off = (i & 7) * 8;
        *(uint4*)&Qh[r * LDB_ + off] = *(const uint4*)&qhi[qoff + (size_t)r * HD + off];
        *(uint4*)&Ql[r * LDB_ + off] = *(const uint4*)&qlo[qoff + (size_t)r * HD + off];
    }
    __syncthreads();

    uint32_t qfh[4][4], qfl[4][4];
    {
        int r = w * 16 + grp;
#pragma unroll
        for (int kk = 0; kk < 4; kk++) {
            int cc = kk * 16 + tig * 2;
            qfh[kk][0] = *(const uint32_t*)&Qh[r * LDB_ + cc];
            qfh[kk][1] = *(const uint32_t*)&Qh[(r + 8) * LDB_ + cc];
            qfh[kk][2] = *(const uint32_t*)&Qh[r * LDB_ + cc + 8];
            qfh[kk][3] = *(const uint32_t*)&Qh[(r + 8) * LDB_ + cc + 8];
            qfl[kk][0] = *(const uint32_t*)&Ql[r * LDB_ + cc];
            qfl[kk][1] = *(const uint32_t*)&Ql[(r + 8) * LDB_ + cc];
            qfl[kk][2] = *(const uint32_t*)&Ql[r * LDB_ + cc + 8];
            qfl[kk][3] = *(const uint32_t*)&Ql[(r + 8) * LDB_ + cc + 8];
        }
    }

    float oacc[8][4];
#pragma unroll
    for (int nt = 0; nt < 8; nt++)
#pragma unroll
        for (int i = 0; i < 4; i++) oacc[nt][i] = 0.f;

    float m0 = -1e30f, m1 = -1e30f, l0 = 0.f, l1 = 0.f;
    const int gq0 = q0 + w * 16 + grp;
    const int gq1 = gq0 + 8;
    const float scale = 0.125f;

    const int nkb = 2 * qb + 2;
    for (int kb = 0; kb < nkb; kb++) {
        const int j0 = kb * 64;
        __syncthreads();
        for (int i = tid; i < 512; i += 256) {
            int r = i >> 3, off = (i & 7) * 8;
            *(uint4*)&Kh[r * LDB_ + off] = *(const uint4*)&khi[kvoff + (size_t)(j0 + r) * HD + off];
            *(uint4*)&Kl[r * LDB_ + off] = *(const uint4*)&klo[kvoff + (size_t)(j0 + r) * HD + off];
            *(uint4*)&Vh[r * LDB_ + off] = *(const uint4*)&vhi[vtoff + (size_t)r * SEQ + j0 + off];
            *(uint4*)&Vl[r * LDB_ + off] = *(const uint4*)&vlo[vtoff + (size_t)r * SEQ + j0 + off];
        }
        __syncthreads();

        float sacc[8][4];
#pragma unroll
        for (int nt = 0; nt < 8; nt++)
#pragma unroll
            for (int i = 0; i < 4; i++) sacc[nt][i] = 0.f;

#pragma unroll
        for (int kk = 0; kk < 4; kk++) {
            int cc = kk * 16 + tig * 2;
#pragma unroll
            for (int nt = 0; nt < 8; nt++) {
                int r = nt * 8 + grp;
                uint32_t bh2[2], bl2[2];
                bh2[0] = *(const uint32_t*)&Kh[r * LDB_ + cc];
                bh2[1] = *(const uint32_t*)&Kh[r * LDB_ + cc + 8];
                bl2[0] = *(const uint32_t*)&Kl[r * LDB_ + cc];
                bl2[1] = *(const uint32_t*)&Kl[r * LDB_ + cc + 8];
                MMA_BF16(sacc[nt], qfh[kk], bh2);
                MMA_BF16(sacc[nt], qfh[kk], bl2);
                MMA_BF16(sacc[nt], qfl[kk], bh2);
            }
        }

        const int colb = j0 + tig * 2;
#pragma unroll
        for (int nt = 0; nt < 8; nt++) {
            int c0g = colb + nt * 8, c1g = c0g + 1;
            sacc[nt][0] = sacc[nt][0] * scale + ((c0g <= gq0) ? 0.f : -1e9f);
            sacc[nt][1] = sacc[nt][1] * scale + ((c1g <= gq0) ? 0.f : -1e9f);
            sacc[nt][2] = sacc[nt][2] * scale + ((c0g <= gq1) ? 0.f : -1e9f);
            sacc[nt][3] = sacc[nt][3] * scale + ((c1g <= gq1) ? 0.f : -1e9f);
        }

        float mx0 = -1e30f, mx1 = -1e30f;
#pragma unroll
        for (int nt = 0; nt < 8; nt++) {
            mx0 = fmaxf(mx0, fmaxf(sacc[nt][0], sacc[nt][1]));
            mx1 = fmaxf(mx1, fmaxf(sacc[nt][2], sacc[nt][3]));
        }
        mx0 = fmaxf(mx0, __shfl_xor_sync(0xffffffffu, mx0, 1));
        mx0 = fmaxf(mx0, __shfl_xor_sync(0xffffffffu, mx0, 2));
        mx1 = fmaxf(mx1, __shfl_xor_sync(0xffffffffu, mx1, 1));
        mx1 = fmaxf(mx1, __shfl_xor_sync(0xffffffffu, mx1, 2));

        float mn0 = fmaxf(m0, mx0), mn1 = fmaxf(m1, mx1);
        float al0 = __expf(m0 - mn0), al1 = __expf(m1 - mn1);
        m0 = mn0; m1 = mn1;

        float ls0 = 0.f, ls1 = 0.f;
#pragma unroll
        for (int nt = 0; nt < 8; nt++) {
            float p00 = __expf(sacc[nt][0] - mn0);
            float p01 = __expf(sacc[nt][1] - mn0);
            float p10 = __expf(sacc[nt][2] - mn1);
            float p11 = __expf(sacc[nt][3] - mn1);
            sacc[nt][0] = p00; sacc[nt][1] = p01;
            sacc[nt][2] = p10; sacc[nt][3] = p11;
            ls0 += p00 + p01; ls1 += p10 + p11;
        }
        ls0 += __shfl_xor_sync(0xffffffffu, ls0, 1);
        ls0 += __shfl_xor_sync(0xffffffffu, ls0, 2);
        ls1 += __shfl_xor_sync(0xffffffffu, ls1, 1);
        ls1 += __shfl_xor_sync(0xffffffffu, ls1, 2);
        l0 = l0 * al0 + ls0;
        l1 = l1 * al1 + ls1;

#pragma unroll
        for (int nt = 0; nt < 8; nt++) {
            oacc[nt][0] *= al0; oacc[nt][1] *= al0;
            oacc[nt][2] *= al1; oacc[nt][3] *= al1;
        }

        {
            int pr = w * 16 + grp;
#pragma unroll
            for (int nt = 0; nt < 8; nt++) {
                int pc = nt * 8 + tig * 2;
                uint32_t lw0, hw0 = pack2(sacc[nt][0], sacc[nt][1], lw0);
                uint32_t lw1, hw1 = pack2(sacc[nt][2], sacc[nt][3], lw1);
                *(uint32_t*)&Qh[pr * LDB_ + pc]       = hw0;
                *(uint32_t*)&Ql[pr * LDB_ + pc]       = lw0;
                *(uint32_t*)&Qh[(pr + 8) * LDB_ + pc] = hw1;
                *(uint32_t*)&Ql[(pr + 8) * LDB_ + pc] = lw1;
            }
        }
        __syncwarp();

        {
            int pr = w * 16 + grp;
#pragma unroll
            for (int kk = 0; kk < 4; kk++) {
                int cc = kk * 16 + tig * 2;
                uint32_t ah[4], al_[4];
                ah[0]  = *(const uint32_t*)&Qh[pr * LDB_ + cc];
                ah[1]  = *(const uint32_t*)&Qh[(pr + 8) * LDB_ + cc];
                ah[2]  = *(const uint32_t*)&Qh[pr * LDB_ + cc + 8];
                ah[3]  = *(const uint32_t*)&Qh[(pr + 8) * LDB_ + cc + 8];
                al_[0] = *(const uint32_t*)&Ql[pr * LDB_ + cc];
                al_[1] = *(const uint32_t*)&Ql[(pr + 8) * LDB_ + cc];
                al_[2] = *(const uint32_t*)&Ql[pr * LDB_ + cc + 8];
                al_[3] = *(const uint32_t*)&Ql[(pr + 8) * LDB_ + cc + 8];
#pragma unroll
                for (int nt = 0; nt < 8; nt++) {
                    int r = nt * 8 + grp;
                    uint32_t bh2[2], bl2[2];
                    bh2[0] = *(const uint32_t*)&Vh[r * LDB_ + cc];
                    bh2[1] = *(const uint32_t*)&Vh[r * LDB_ + cc + 8];
                    bl2[0] = *(const uint32_t*)&Vl[r * LDB_ + cc];
                    bl2[1] = *(const uint32_t*)&Vl[r * LDB_ + cc + 8];
                    MMA_BF16(oacc[nt], ah, bh2);
                    MMA_BF16(oacc[nt], ah, bl2);
                    MMA_BF16(oacc[nt], al_, bh2);
                }
            }
        }
        __syncwarp();
    }

    // epilogue: normalize; emit bf16 hi/lo AND fp32 (fp32 feeds F-tiles of O-proj)
    float inv0 = 1.f / l0, inv1 = 1.f / l1;
    int row0 = q0 + w * 16 + grp;
#pragma unroll
    for (int nt = 0; nt < 8; nt++) {
        int col = h * HD + nt * 8 + tig * 2;
        size_t i0 = (size_t)(b * SEQ + row0) * HID + col;
        size_t i1 = (size_t)(b * SEQ + row0 + 8) * HID + col;
        float a0 = oacc[nt][0] * inv0, a1 = oacc[nt][1] * inv0;
        float a2 = oacc[nt][2] * inv1, a3 = oacc[nt][3] * inv1;
        uint32_t lw0, hw0 = pack2(a0, a1, lw0);
        uint32_t lw1, hw1 = pack2(a2, a3, lw1);
        *(uint32_t*)&ath[i0] = hw0;
        *(uint32_t*)&atl[i0] = lw0;
        *(uint32_t*)&ath[i1] = hw1;
        *(uint32_t*)&atl[i1] = lw1;
        *(float2*)&attf[i0] = make_float2(a0, a1);
        *(float2*)&attf[i1] = make_float2(a2, a3);
    }
}

// ---------------- launch ----------------------------------------------------
extern "C" void kernel_launch(void* const* d_in, const int* in_sizes, int n_in,
                              void* d_out, int out_size)
{
    const float* x     = (const float*)d_in[0];
    const float* freqs = (const float*)d_in[1];
    const float* wq = (const float*)d_in[3];
    const float* bq = (const float*)d_in[4];
    const float* wk = (const float*)d_in[5];
    const float* bk = (const float*)d_in[6];
    const float* wv = (const float*)d_in[7];
    const float* bv = (const float*)d_in[8];
    const float* wo = (const float*)d_in[9];
    const float* bo = (const float*)d_in[10];
    float* out = (float*)d_out;

    __nv_bfloat16 *xh, *xl, *wqh, *wql, *wkh, *wkl, *wvh, *wvl, *woh, *wol;
    __nv_bfloat16 *qrh, *qrl, *krh, *krl, *vth, *vtl, *ath, *atl;
    float *pv, *pattf;
    cudaGetSymbolAddress((void**)&xh,  s_x_hi);  cudaGetSymbolAddress((void**)&xl,  s_x_lo);
    cudaGetSymbolAddress((void**)&wqh, s_wq_hi); cudaGetSymbolAddress((void**)&wql, s_wq_lo);
    cudaGetSymbolAddress((void**)&wkh, s_wk_hi); cudaGetSymbolAddress((void**)&wkl, s_wk_lo);
    cudaGetSymbolAddress((void**)&wvh, s_wv_hi); cudaGetSymbolAddress((void**)&wvl, s_wv_lo);
    cudaGetSymbolAddress((void**)&woh, s_wo_hi); cudaGetSymbolAddress((void**)&wol, s_wo_lo);
    cudaGetSymbolAddress((void**)&qrh, s_qr_hi); cudaGetSymbolAddress((void**)&qrl, s_qr_lo);
    cudaGetSymbolAddress((void**)&krh, s_kr_hi); cudaGetSymbolAddress((void**)&krl, s_kr_lo);
    cudaGetSymbolAddress((void**)&vth, s_vt_hi); cudaGetSymbolAddress((void**)&vtl, s_vt_lo);
    cudaGetSymbolAddress((void**)&ath, s_at_hi); cudaGetSymbolAddress((void**)&atl, s_at_lo);
    cudaGetSymbolAddress((void**)&pv,  g_v);
    cudaGetSymbolAddress((void**)&pattf, g_att);

    cudaFuncSetAttribute(gemm_bf16x3,
                         cudaFuncAttributeMaxDynamicSharedMemorySize, GEMM_SMEM);
    cudaFuncSetAttribute(gemm_rope,
                         cudaFuncAttributeMaxDynamicSharedMemorySize, GEMM_SMEM);
    cudaFuncSetAttribute(gemm_hyb_plain,
                         cudaFuncAttributeMaxDynamicSharedMemorySize, GEMM_SMEM);
    cudaFuncSetAttribute(gemm_hyb_rope,
                         cudaFuncAttributeMaxDynamicSharedMemorySize, GEMM_SMEM);
    cudaFuncSetAttribute(flash_attn_bf16,
                         cudaFuncAttributeMaxDynamicSharedMemorySize, ATT_SMEM);

    // splits
    split_kernel<<<(MROWS * HID / 2 + 255) / 256, 256>>>(x,  xh,  xl,  MROWS * HID);
    split_kernel<<<(HID * HID / 2 + 255) / 256, 256>>>(wq, wqh, wql, HID * HID);
    split_kernel<<<(KVD * HID / 2 + 255) / 256, 256>>>(wk, wkh, wkl, KVD * HID);
    split_kernel<<<(KVD * HID / 2 + 255) / 256, 256>>>(wv, wvh, wvl, KVD * HID);
    split_kernel<<<(HID * HID / 2 + 255) / 256, 256>>>(wo, woh, wol, HID * HID);

    // Q projection: HYBRID (tensor + FFMA2 CTAs), fused bias+RoPE+split
    gemm_hyb_rope<<<dim3(HID / 128, MROWS / 128), 256, GEMM_SMEM>>>(
        xh, xl, x, wqh, wql, wq, bq, freqs, qrh, qrl, NH, HID);
    // K projection: tensor-only (grid underfills the GPU; hybrid would slow it)
    gemm_rope<<<dim3(KVD / 128, MROWS / 128), 256, GEMM_SMEM>>>(
        xh, xl, wkh, wkl, bk, freqs, krh, krl, NG, HID);
    // V projection: tensor-only
    gemm_bf16x3<<<dim3(KVD / 128, MROWS / 128), 256, GEMM_SMEM>>>(
        xh, xl, wvh, wvl, bv, pv, MROWS, KVD, HID);
    transpose_v_split<<<(BSZ * NG * HD * (SEQ / 2)) / 256, 256>>>(pv, vth, vtl);

    // attention (emits bf16 hi/lo AND fp32 copies of output)
    flash_attn_bf16<<<dim3(SEQ / 128, BSZ * NH), 256, ATT_SMEM>>>(
        qrh, qrl, krh, krl, vth, vtl, ath, atl, pattf);

    // O projection: HYBRID
    gemm_hyb_plain<<<dim3(HID / 128, MROWS / 128), 256, GEMM_SMEM>>>(
        ath, atl, pattf, woh, wol, wo, bo, out, MROWS, HID, HID);
}

// round 9
// speedup vs baseline: 1.4537x; 1.4537x over previous
#include <cuda_runtime.h>
#include <cuda_bf16.h>
#include <math.h>
#include <stdint.h>

#define BSZ   2
#define SEQ   2048
#define HID   2048
#define NH    32
#define NG    8
#define HD    64
#define KVD   512
#define MROWS 4096

// ---------------- scratch ---------------------------------------------------
__device__ __nv_bfloat16 s_x_hi [MROWS * HID];
__device__ __nv_bfloat16 s_x_lo [MROWS * HID];
__device__ __nv_bfloat16 s_wq_hi[HID * HID];
__device__ __nv_bfloat16 s_wq_lo[HID * HID];
__device__ __nv_bfloat16 s_wk_hi[KVD * HID];
__device__ __nv_bfloat16 s_wk_lo[KVD * HID];
__device__ __nv_bfloat16 s_wv_hi[KVD * HID];
__device__ __nv_bfloat16 s_wv_lo[KVD * HID];
__device__ __nv_bfloat16 s_wo_hi[HID * HID];
__device__ __nv_bfloat16 s_wo_lo[HID * HID];
__device__ float g_v  [MROWS * KVD];
__device__ __nv_bfloat16 s_qr_hi[BSZ * NH * SEQ * HD];
__device__ __nv_bfloat16 s_qr_lo[BSZ * NH * SEQ * HD];
__device__ __nv_bfloat16 s_kr_hi[BSZ * NG * SEQ * HD];
__device__ __nv_bfloat16 s_kr_lo[BSZ * NG * SEQ * HD];
__device__ __nv_bfloat16 s_vt_hi[BSZ * NG * HD * SEQ];   // [b,g,d,s]
__device__ __nv_bfloat16 s_vt_lo[BSZ * NG * HD * SEQ];
__device__ __nv_bfloat16 s_at_hi[MROWS * HID];
__device__ __nv_bfloat16 s_at_lo[MROWS * HID];

// ---------------- helpers ---------------------------------------------------
__device__ __forceinline__ void cp_async16(void* smem_ptr, const void* gptr) {
    uint32_t s = (uint32_t)__cvta_generic_to_shared(smem_ptr);
    asm volatile("cp.async.cg.shared.global [%0], [%1], 16;\n" :: "r"(s), "l"(gptr));
}
#define CP_COMMIT()  asm volatile("cp.async.commit_group;\n" ::: "memory")
#define CP_WAIT(n)   asm volatile("cp.async.wait_group %0;\n" :: "n"(n) : "memory")

#define MMA_BF16(Cc, Aa, Bb) asm volatile( \
    "mma.sync.aligned.m16n8k16.row.col.f32.bf16.bf16.f32 " \
    "{%0,%1,%2,%3},{%4,%5,%6,%7},{%8,%9},{%0,%1,%2,%3};\n" \
    : "+f"(Cc[0]), "+f"(Cc[1]), "+f"(Cc[2]), "+f"(Cc[3]) \
    : "r"(Aa[0]), "r"(Aa[1]), "r"(Aa[2]), "r"(Aa[3]), "r"(Bb[0]), "r"(Bb[1]))

__device__ __forceinline__ uint32_t pack2(float x0, float x1, uint32_t& lo_out) {
    __nv_bfloat16 h0 = __float2bfloat16(x0);
    __nv_bfloat16 h1 = __float2bfloat16(x1);
    __nv_bfloat16 l0 = __float2bfloat16(x0 - __bfloat162float(h0));
    __nv_bfloat16 l1 = __float2bfloat16(x1 - __bfloat162float(h1));
    __nv_bfloat162 H = __halves2bfloat162(h0, h1);
    __nv_bfloat162 L = __halves2bfloat162(l0, l1);
    lo_out = *(uint32_t*)&L;
    return *(uint32_t*)&H;
}

// ---------------- merged split: x + wq + wk + wv + wo -----------------------
#define NX   (MROWS * HID)          // 8388608
#define NWQ  (HID * HID)            // 4194304
#define NWKV (KVD * HID)            // 1048576
#define SEG1 (NX)
#define SEG2 (SEG1 + NWQ)
#define SEG3 (SEG2 + NWKV)
#define SEG4 (SEG3 + NWKV)
#define SEG5 (SEG4 + NWQ)           // total 18874368

__global__ void split_all(
    const float* __restrict__ x,  const float* __restrict__ wq,
    const float* __restrict__ wk, const float* __restrict__ wv,
    const float* __restrict__ wo,
    __nv_bfloat16* __restrict__ xh,  __nv_bfloat16* __restrict__ xl,
    __nv_bfloat16* __restrict__ wqh, __nv_bfloat16* __restrict__ wql,
    __nv_bfloat16* __restrict__ wkh, __nv_bfloat16* __restrict__ wkl,
    __nv_bfloat16* __restrict__ wvh, __nv_bfloat16* __restrict__ wvl,
    __nv_bfloat16* __restrict__ woh, __nv_bfloat16* __restrict__ wol)
{
    int i = (blockIdx.x * blockDim.x + threadIdx.x) * 2;
    if (i >= SEG5) return;
    const float* src; __nv_bfloat16 *hi, *lo; int off;
    if      (i < SEG1) { src = x;  hi = xh;  lo = xl;  off = i; }
    else if (i < SEG2) { src = wq; hi = wqh; lo = wql; off = i - SEG1; }
    else if (i < SEG3) { src = wk; hi = wkh; lo = wkl; off = i - SEG2; }
    else if (i < SEG4) { src = wv; hi = wvh; lo = wvl; off = i - SEG3; }
    else               { src = wo; hi = woh; lo = wol; off = i - SEG4; }
    float2 v = *(const float2*)&src[off];
    uint32_t lw, hw = pack2(v.x, v.y, lw);
    *(uint32_t*)&hi[off] = hw;
    *(uint32_t*)&lo[off] = lw;
}

// ---------------- 3x bf16-split GEMM core macros ----------------------------
#define LDG_   40
#define GSTAGE (4 * 128 * LDG_)
#define GEMM_SMEM (2 * GSTAGE * 2)

#define G_PROLOG()                                                           \
    const int tid  = threadIdx.x;                                            \
    const int lane = tid & 31;                                               \
    const int w    = tid >> 5;                                               \
    const int wm   = w >> 2;                                                 \
    const int wn   = w & 3;                                                  \
    const int grp  = lane >> 2;                                              \
    const int tig  = lane & 3;                                               \
    float c[4][4][4];                                                        \
    _Pragma("unroll")                                                        \
    for (int mt = 0; mt < 4; mt++)                                           \
        _Pragma("unroll")                                                    \
        for (int nt = 0; nt < 4; nt++)                                       \
            _Pragma("unroll")                                                \
            for (int i = 0; i < 4; i++) c[mt][nt][i] = 0.f;

#define G_LOAD_STAGE(sidx, k0) do {                                          \
    __nv_bfloat16* Ash_ = smb + (sidx) * GSTAGE;                             \
    __nv_bfloat16* Asl_ = Ash_ + 128 * LDG_;                                 \
    __nv_bfloat16* Wsh_ = Asl_ + 128 * LDG_;                                 \
    __nv_bfloat16* Wsl_ = Wsh_ + 128 * LDG_;                                 \
    _Pragma("unroll")                                                        \
    for (int j_ = 0; j_ < 2; j_++) {                                         \
        int cch_ = tid + j_ * 256;                                           \
        int r_   = cch_ >> 2;                                                \
        int off_ = (cch_ & 3) * 8;                                           \
        cp_async16(Ash_ + r_ * LDG_ + off_, Ah + (size_t)(m0 + r_) * K + (k0) + off_); \
        cp_async16(Asl_ + r_ * LDG_ + off_, Al + (size_t)(m0 + r_) * K + (k0) + off_); \
        cp_async16(Wsh_ + r_ * LDG_ + off_, Wh + (size_t)(n0 + r_) * K + (k0) + off_); \
        cp_async16(Wsl_ + r_ * LDG_ + off_, Wl + (size_t)(n0 + r_) * K + (k0) + off_); \
    }                                                                        \
    CP_COMMIT();                                                             \
} while (0)

#define G_MAINLOOP()                                                         \
    G_LOAD_STAGE(0, 0);                                                      \
    const int NIT = K >> 5;                                                  \
    for (int it = 0; it < NIT; it++) {                                       \
        int s = it & 1;                                                      \
        if (it + 1 < NIT) { G_LOAD_STAGE(s ^ 1, (it + 1) << 5); CP_WAIT(1); }\
        else             { CP_WAIT(0); }                                     \
        __syncthreads();                                                     \
        const __nv_bfloat16* Ash = smb + s * GSTAGE;                         \
        const __nv_bfloat16* Asl = Ash + 128 * LDG_;                         \
        const __nv_bfloat16* Wsh = Asl + 128 * LDG_;                         \
        const __nv_bfloat16* Wsl = Wsh + 128 * LDG_;                         \
        _Pragma("unroll")                                                    \
        for (int kk = 0; kk < 2; kk++) {                                     \
            const int cc = kk * 16 + tig * 2;                                \
            uint32_t bh[4][2], bl[4][2];                                     \
            _Pragma("unroll")                                                \
            for (int nt = 0; nt < 4; nt++) {                                 \
                int r = wn * 32 + nt * 8 + grp;                              \
                bh[nt][0] = *(const uint32_t*)&Wsh[r * LDG_ + cc];           \
                bh[nt][1] = *(const uint32_t*)&Wsh[r * LDG_ + cc + 8];       \
                bl[nt][0] = *(const uint32_t*)&Wsl[r * LDG_ + cc];           \
                bl[nt][1] = *(const uint32_t*)&Wsl[r * LDG_ + cc + 8];       \
            }                                                                \
            _Pragma("unroll")                                                \
            for (int mt = 0; mt < 4; mt++) {                                 \
                int r = wm * 64 + mt * 16 + grp;                             \
                uint32_t ah[4], al[4];                                       \
                ah[0] = *(const uint32_t*)&Ash[r * LDG_ + cc];               \
                ah[1] = *(const uint32_t*)&Ash[(r + 8) * LDG_ + cc];         \
                ah[2] = *(const uint32_t*)&Ash[r * LDG_ + cc + 8];           \
                ah[3] = *(const uint32_t*)&Ash[(r + 8) * LDG_ + cc + 8];     \
                al[0] = *(const uint32_t*)&Asl[r * LDG_ + cc];               \
                al[1] = *(const uint32_t*)&Asl[(r + 8) * LDG_ + cc];         \
                al[2] = *(const uint32_t*)&Asl[r * LDG_ + cc + 8];           \
                al[3] = *(const uint32_t*)&Asl[(r + 8) * LDG_ + cc + 8];     \
                _Pragma("unroll")                                            \
                for (int nt = 0; nt < 4; nt++) {                             \
                    MMA_BF16(c[mt][nt], ah, bh[nt]);                         \
                    MMA_BF16(c[mt][nt], ah, bl[nt]);                         \
                    MMA_BF16(c[mt][nt], al, bh[nt]);                         \
                }                                                            \
            }                                                                \
        }                                                                    \
        __syncthreads();                                                     \
    }

// ---------------- UNIFIED Q/K/V projection (one launch, 768 CTAs) ----------
// blocks [0,512): Q-proj (rope epilogue, NH heads)
// blocks [512,640): K-proj (rope epilogue, NG heads)
// blocks [640,768): V-proj (plain fp32 epilogue)
__global__ __launch_bounds__(256, 1) void gemm_qkv(
    const __nv_bfloat16* __restrict__ xh,  const __nv_bfloat16* __restrict__ xl,
    const __nv_bfloat16* __restrict__ wqh, const __nv_bfloat16* __restrict__ wql,
    const float* __restrict__ bq,
    const __nv_bfloat16* __restrict__ wkh, const __nv_bfloat16* __restrict__ wkl,
    const float* __restrict__ bk,
    const __nv_bfloat16* __restrict__ wvh, const __nv_bfloat16* __restrict__ wvl,
    const float* __restrict__ bv,
    const float* __restrict__ freqs,
    __nv_bfloat16* __restrict__ qrh, __nv_bfloat16* __restrict__ qrl,
    __nv_bfloat16* __restrict__ krh, __nv_bfloat16* __restrict__ krl,
    float* __restrict__ vout)
{
    extern __shared__ __nv_bfloat16 smb[];
    const int id = blockIdx.x;
    const __nv_bfloat16 *Ah = xh, *Al = xl, *Wh, *Wl;
    const float* bias;
    int m0, n0, role;
    if (id < 512)      { role = 0; m0 = (id >> 4) * 128; n0 = (id & 15) * 128;
                         Wh = wqh; Wl = wql; bias = bq; }
    else if (id < 640) { int t = id - 512; role = 1; m0 = (t >> 2) * 128; n0 = (t & 3) * 128;
                         Wh = wkh; Wl = wkl; bias = bk; }
    else               { int t = id - 640; role = 2; m0 = (t >> 2) * 128; n0 = (t & 3) * 128;
                         Wh = wvh; Wl = wvl; bias = bv; }
    const int K = HID;

    G_PROLOG();
    G_MAINLOOP();

    if (role == 2) {
        // V: plain fp32 + bias, N = KVD
#pragma unroll
        for (int mt = 0; mt < 4; mt++) {
#pragma unroll
            for (int nt = 0; nt < 4; nt++) {
                int row = m0 + wm * 64 + mt * 16 + grp;
                int col = n0 + wn * 32 + nt * 8 + tig * 2;
                float2 bv2 = *(const float2*)&bias[col];
                *(float2*)&vout[(size_t)row * KVD + col] =
                    make_float2(c[mt][nt][0] + bv2.x, c[mt][nt][1] + bv2.y);
                *(float2*)&vout[(size_t)(row + 8) * KVD + col] =
                    make_float2(c[mt][nt][2] + bv2.x, c[mt][nt][3] + bv2.y);
            }
        }
    } else {
        const int nheads = (role == 0) ? NH : NG;
        __nv_bfloat16* dsth = (role == 0) ? qrh : krh;
        __nv_bfloat16* dstl = (role == 0) ? qrl : krl;
#pragma unroll
        for (int mt = 0; mt < 4; mt++) {
            int row = m0 + wm * 64 + mt * 16 + grp;
            int b_  = row >> 11;
            int s_  = row & (SEQ - 1);
#pragma unroll
            for (int nt = 0; nt < 4; nt++) {
                int col = n0 + wn * 32 + nt * 8 + tig * 2;
                int h_  = col >> 6;
                int d_  = col & 63;
                float2 bv2 = *(const float2*)&bias[col];
                float2 f0 = *(const float2*)&freqs[s_ * HD + d_];
                float2 f1 = *(const float2*)&freqs[(s_ + 8) * HD + d_];
                float v0 = c[mt][nt][0] + bv2.x, v1 = c[mt][nt][1] + bv2.y;
                float v2 = c[mt][nt][2] + bv2.x, v3 = c[mt][nt][3] + bv2.y;
                uint32_t lw0, hw0 = pack2(v0 * f0.x - v1 * f0.y, v0 * f0.y + v1 * f0.x, lw0);
                uint32_t lw1, hw1 = pack2(v2 * f1.x - v3 * f1.y, v2 * f1.y + v3 * f1.x, lw1);
                size_t o0 = ((size_t)(b_ * nheads + h_) * SEQ + s_) * HD + d_;
                size_t o1 = o0 + (size_t)8 * HD;
                *(uint32_t*)&dsth[o0] = hw0;
                *(uint32_t*)&dstl[o0] = lw0;
                *(uint32_t*)&dsth[o1] = hw1;
                *(uint32_t*)&dstl[o1] = lw1;
            }
        }
    }
}

// ---------------- O projection (tensor-only, fp32 out) ----------------------
__global__ __launch_bounds__(256, 1) void gemm_bf16x3(
    const __nv_bfloat16* __restrict__ Ah, const __nv_bfloat16* __restrict__ Al,
    const __nv_bfloat16* __restrict__ Wh, const __nv_bfloat16* __restrict__ Wl,
    const float* __restrict__ bias, float* __restrict__ C,
    int M, int N, int K)
{
    extern __shared__ __nv_bfloat16 smb[];
    const int m0 = blockIdx.y * 128;
    const int n0 = blockIdx.x * 128;
    G_PROLOG();
    G_MAINLOOP();
#pragma unroll
    for (int mt = 0; mt < 4; mt++) {
#pragma unroll
        for (int nt = 0; nt < 4; nt++) {
            int row = m0 + wm * 64 + mt * 16 + grp;
            int col = n0 + wn * 32 + nt * 8 + tig * 2;
            float2 bv = *(const float2*)&bias[col];
            *(float2*)&C[(size_t)row * N + col] =
                make_float2(c[mt][nt][0] + bv.x, c[mt][nt][1] + bv.y);
            *(float2*)&C[(size_t)(row + 8) * N + col] =
                make_float2(c[mt][nt][2] + bv.x, c[mt][nt][3] + bv.y);
        }
    }
}

// V: [b,s,g*64+d] fp32  ->  [b,g,d,s] bf16 hi/lo
__global__ void transpose_v_split(const float* __restrict__ vlin,
                                  __nv_bfloat16* __restrict__ vhi,
                                  __nv_bfloat16* __restrict__ vlo)
{
    int idx = blockIdx.x * blockDim.x + threadIdx.x;
    if (idx >= BSZ * NG * HD * (SEQ / 2)) return;
    int s2 = idx & (SEQ / 2 - 1);
    int d  = (idx >> 10) & (HD - 1);
    int g  = (idx >> 16) & (NG - 1);
    int b  = idx >> 19;
    int s  = s2 * 2;
    float v0 = vlin[(size_t)(b * SEQ + s)     * KVD + g * HD + d];
    float v1 = vlin[(size_t)(b * SEQ + s + 1) * KVD + g * HD + d];
    size_t off = ((size_t)(b * NG + g) * HD + d) * SEQ + s;
    uint32_t lw, hw = pack2(v0, v1, lw);
    *(uint32_t*)&vhi[off] = hw;
    *(uint32_t*)&vlo[off] = lw;
}

// ---------------- flash attention, bf16x3 mma --------------------------------
#define LDB_ 72
#define ATT_SMEM ((2 * 128 * LDB_ + 4 * 64 * LDB_) * 2)

__global__ __launch_bounds__(256, 1) void flash_attn_bf16(
    const __nv_bfloat16* __restrict__ qhi, const __nv_bfloat16* __restrict__ qlo,
    const __nv_bfloat16* __restrict__ khi, const __nv_bfloat16* __restrict__ klo,
    const __nv_bfloat16* __restrict__ vhi, const __nv_bfloat16* __restrict__ vlo,
    __nv_bfloat16* __restrict__ ath, __nv_bfloat16* __restrict__ atl)
{
    extern __shared__ __nv_bfloat16 smb[];
    __nv_bfloat16* Qh = smb;
    __nv_bfloat16* Ql = Qh + 128 * LDB_;
    __nv_bfloat16* Kh = Ql + 128 * LDB_;
    __nv_bfloat16* Kl = Kh + 64 * LDB_;
    __nv_bfloat16* Vh = Kl + 64 * LDB_;
    __nv_bfloat16* Vl = Vh + 64 * LDB_;

    const int tid  = threadIdx.x;
    const int lane = tid & 31;
    const int w    = tid >> 5;
    const int grp  = lane >> 2;
    const int tig  = lane & 3;
    const int qb   = gridDim.x - 1 - blockIdx.x;   // heavy tiles first
    const int bh_  = blockIdx.y;
    const int b    = bh_ >> 5;
    const int h    = bh_ & 31;
    const int g    = h >> 2;
    const int q0   = qb * 128;
    const size_t qoff  = ((size_t)(b * NH + h) * SEQ + q0) * HD;
    const size_t kvoff = (size_t)(b * NG + g) * SEQ * HD;
    const size_t vtoff = (size_t)(b * NG + g) * HD * SEQ;

    for (int i = tid; i < 1024; i += 256) {
        int r = i >> 3, off = (i & 7) * 8;
        *(uint4*)&Qh[r * LDB_ + off] = *(const uint4*)&qhi[qoff + (size_t)r * HD + off];
        *(uint4*)&Ql[r * LDB_ + off] = *(const uint4*)&qlo[qoff + (size_t)r * HD + off];
    }
    __syncthreads();

    uint32_t qfh[4][4], qfl[4][4];
    {
        int r = w * 16 + grp;
#pragma unroll
        for (int kk = 0; kk < 4; kk++) {
            int cc = kk * 16 + tig * 2;
            qfh[kk][0] = *(const uint32_t*)&Qh[r * LDB_ + cc];
            qfh[kk][1] = *(const uint32_t*)&Qh[(r + 8) * LDB_ + cc];
            qfh[kk][2] = *(const uint32_t*)&Qh[r * LDB_ + cc + 8];
            qfh[kk][3] = *(const uint32_t*)&Qh[(r + 8) * LDB_ + cc + 8];
            qfl[kk][0] = *(const uint32_t*)&Ql[r * LDB_ + cc];
            qfl[kk][1] = *(const uint32_t*)&Ql[(r + 8) * LDB_ + cc];
            qfl[kk][2] = *(const uint32_t*)&Ql[r * LDB_ + cc + 8];
            qfl[kk][3] = *(const uint32_t*)&Ql[(r + 8) * LDB_ + cc + 8];
        }
    }

    float oacc[8][4];
#pragma unroll
    for (int nt = 0; nt < 8; nt++)
#pragma unroll
        for (int i = 0; i < 4; i++) oacc[nt][i] = 0.f;

    float m0 = -1e30f, m1 = -1e30f, l0 = 0.f, l1 = 0.f;
    const int gq0 = q0 + w * 16 + grp;
    const int gq1 = gq0 + 8;
    const float scale = 0.125f;

    const int nkb = 2 * qb + 2;
    for (int kb = 0; kb < nkb; kb++) {
        const int j0 = kb * 64;
        __syncthreads();
        for (int i = tid; i < 512; i += 256) {
            int r = i >> 3, off = (i & 7) * 8;
            *(uint4*)&Kh[r * LDB_ + off] = *(const uint4*)&khi[kvoff + (size_t)(j0 + r) * HD + off];
            *(uint4*)&Kl[r * LDB_ + off] = *(const uint4*)&klo[kvoff + (size_t)(j0 + r) * HD + off];
            *(uint4*)&Vh[r * LDB_ + off] = *(const uint4*)&vhi[vtoff + (size_t)r * SEQ + j0 + off];
            *(uint4*)&Vl[r * LDB_ + off] = *(const uint4*)&vlo[vtoff + (size_t)r * SEQ + j0 + off];
        }
        __syncthreads();

        float sacc[8][4];
#pragma unroll
        for (int nt = 0; nt < 8; nt++)
#pragma unroll
            for (int i = 0; i < 4; i++) sacc[nt][i] = 0.f;

#pragma unroll
        for (int kk = 0; kk < 4; kk++) {
            int cc = kk * 16 + tig * 2;
#pragma unroll
            for (int nt = 0; nt < 8; nt++) {
                int r = nt * 8 + grp;
                uint32_t bh2[2], bl2[2];
                bh2[0] = *(const uint32_t*)&Kh[r * LDB_ + cc];
                bh2[1] = *(const uint32_t*)&Kh[r * LDB_ + cc + 8];
                bl2[0] = *(const uint32_t*)&Kl[r * LDB_ + cc];
                bl2[1] = *(const uint32_t*)&Kl[r * LDB_ + cc + 8];
                MMA_BF16(sacc[nt], qfh[kk], bh2);
                MMA_BF16(sacc[nt], qfh[kk], bl2);
                MMA_BF16(sacc[nt], qfl[kk], bh2);
            }
        }

        const int colb = j0 + tig * 2;
#pragma unroll
        for (int nt = 0; nt < 8; nt++) {
            int c0g = colb + nt * 8, c1g = c0g + 1;
            sacc[nt][0] = sacc[nt][0] * scale + ((c0g <= gq0) ? 0.f : -1e9f);
            sacc[nt][1] = sacc[nt][1] * scale + ((c1g <= gq0) ? 0.f : -1e9f);
            sacc[nt][2] = sacc[nt][2] * scale + ((c0g <= gq1) ? 0.f : -1e9f);
            sacc[nt][3] = sacc[nt][3] * scale + ((c1g <= gq1) ? 0.f : -1e9f);
        }

        float mx0 = -1e30f, mx1 = -1e30f;
#pragma unroll
        for (int nt = 0; nt < 8; nt++) {
            mx0 = fmaxf(mx0, fmaxf(sacc[nt][0], sacc[nt][1]));
            mx1 = fmaxf(mx1, fmaxf(sacc[nt][2], sacc[nt][3]));
        }
        mx0 = fmaxf(mx0, __shfl_xor_sync(0xffffffffu, mx0, 1));
        mx0 = fmaxf(mx0, __shfl_xor_sync(0xffffffffu, mx0, 2));
        mx1 = fmaxf(mx1, __shfl_xor_sync(0xffffffffu, mx1, 1));
        mx1 = fmaxf(mx1, __shfl_xor_sync(0xffffffffu, mx1, 2));

        float mn0 = fmaxf(m0, mx0), mn1 = fmaxf(m1, mx1);
        float al0 = __expf(m0 - mn0), al1 = __expf(m1 - mn1);
        m0 = mn0; m1 = mn1;

        float ls0 = 0.f, ls1 = 0.f;
#pragma unroll
        for (int nt = 0; nt < 8; nt++) {
            float p00 = __expf(sacc[nt][0] - mn0);
            float p01 = __expf(sacc[nt][1] - mn0);
            float p10 = __expf(sacc[nt][2] - mn1);
            float p11 = __expf(sacc[nt][3] - mn1);
            sacc[nt][0] = p00; sacc[nt][1] = p01;
            sacc[nt][2] = p10; sacc[nt][3] = p11;
            ls0 += p00 + p01; ls1 += p10 + p11;
        }
        ls0 += __shfl_xor_sync(0xffffffffu, ls0, 1);
        ls0 += __shfl_xor_sync(0xffffffffu, ls0, 2);
        ls1 += __shfl_xor_sync(0xffffffffu, ls1, 1);
        ls1 += __shfl_xor_sync(0xffffffffu, ls1, 2);
        l0 = l0 * al0 + ls0;
        l1 = l1 * al1 + ls1;

#pragma unroll
        for (int nt = 0; nt < 8; nt++) {
            oacc[nt][0] *= al0; oacc[nt][1] *= al0;
            oacc[nt][2] *= al1; oacc[nt][3] *= al1;
        }

        {
            int pr = w * 16 + grp;
#pragma unroll
            for (int nt = 0; nt < 8; nt++) {
                int pc = nt * 8 + tig * 2;
                uint32_t lw0, hw0 = pack2(sacc[nt][0], sacc[nt][1], lw0);
                uint32_t lw1, hw1 = pack2(sacc[nt][2], sacc[nt][3], lw1);
                *(uint32_t*)&Qh[pr * LDB_ + pc]       = hw0;
                *(uint32_t*)&Ql[pr * LDB_ + pc]       = lw0;
                *(uint32_t*)&Qh[(pr + 8) * LDB_ + pc] = hw1;
                *(uint32_t*)&Ql[(pr + 8) * LDB_ + pc] = lw1;
            }
        }
        __syncwarp();

        {
            int pr = w * 16 + grp;
#pragma unroll
            for (int kk = 0; kk < 4; kk++) {
                int cc = kk * 16 + tig * 2;
                uint32_t ah[4], al_[4];
                ah[0]  = *(const uint32_t*)&Qh[pr * LDB_ + cc];
                ah[1]  = *(const uint32_t*)&Qh[(pr + 8) * LDB_ + cc];
                ah[2]  = *(const uint32_t*)&Qh[pr * LDB_ + cc + 8];
                ah[3]  = *(const uint32_t*)&Qh[(pr + 8) * LDB_ + cc + 8];
                al_[0] = *(const uint32_t*)&Ql[pr * LDB_ + cc];
                al_[1] = *(const uint32_t*)&Ql[(pr + 8) * LDB_ + cc];
                al_[2] = *(const uint32_t*)&Ql[pr * LDB_ + cc + 8];
                al_[3] = *(const uint32_t*)&Ql[(pr + 8) * LDB_ + cc + 8];
#pragma unroll
                for (int nt = 0; nt < 8; nt++) {
                    int r = nt * 8 + grp;
                    uint32_t bh2[2], bl2[2];
                    bh2[0] = *(const uint32_t*)&Vh[r * LDB_ + cc];
                    bh2[1] = *(const uint32_t*)&Vh[r * LDB_ + cc + 8];
                    bl2[0] = *(const uint32_t*)&Vl[r * LDB_ + cc];
                    bl2[1] = *(const uint32_t*)&Vl[r * LDB_ + cc + 8];
                    MMA_BF16(oacc[nt], ah, bh2);
                    MMA_BF16(oacc[nt], ah, bl2);
                    MMA_BF16(oacc[nt], al_, bh2);
                }
            }
        }
        __syncwarp();
    }

    // epilogue: normalize + split directly (feeds O-projection)
    float inv0 = 1.f / l0, inv1 = 1.f / l1;
    int row0 = q0 + w * 16 + grp;
#pragma unroll
    for (int nt = 0; nt < 8; nt++) {
        int col = h * HD + nt * 8 + tig * 2;
        size_t i0 = (size_t)(b * SEQ + row0) * HID + col;
        size_t i1 = (size_t)(b * SEQ + row0 + 8) * HID + col;
        uint32_t lw0, hw0 = pack2(oacc[nt][0] * inv0, oacc[nt][1] * inv0, lw0);
        uint32_t lw1, hw1 = pack2(oacc[nt][2] * inv1, oacc[nt][3] * inv1, lw1);
        *(uint32_t*)&ath[i0] = hw0;
        *(uint32_t*)&atl[i0] = lw0;
        *(uint32_t*)&ath[i1] = hw1;
        *(uint32_t*)&atl[i1] = lw1;
    }
}

// ---------------- launch ----------------------------------------------------
extern "C" void kernel_launch(void* const* d_in, const int* in_sizes, int n_in,
                              void* d_out, int out_size)
{
    const float* x     = (const float*)d_in[0];
    const float* freqs = (const float*)d_in[1];
    const float* wq = (const float*)d_in[3];
    const float* bq = (const float*)d_in[4];
    const float* wk = (const float*)d_in[5];
    const float* bk = (const float*)d_in[6];
    const float* wv = (const float*)d_in[7];
    const float* bv = (const float*)d_in[8];
    const float* wo = (const float*)d_in[9];
    const float* bo = (const float*)d_in[10];
    float* out = (float*)d_out;

    __nv_bfloat16 *xh, *xl, *wqh, *wql, *wkh, *wkl, *wvh, *wvl, *woh, *wol;
    __nv_bfloat16 *qrh, *qrl, *krh, *krl, *vth, *vtl, *ath, *atl;
    float *pv;
    cudaGetSymbolAddress((void**)&xh,  s_x_hi);  cudaGetSymbolAddress((void**)&xl,  s_x_lo);
    cudaGetSymbolAddress((void**)&wqh, s_wq_hi); cudaGetSymbolAddress((void**)&wql, s_wq_lo);
    cudaGetSymbolAddress((void**)&wkh, s_wk_hi); cudaGetSymbolAddress((void**)&wkl, s_wk_lo);
    cudaGetSymbolAddress((void**)&wvh, s_wv_hi); cudaGetSymbolAddress((void**)&wvl, s_wv_lo);
    cudaGetSymbolAddress((void**)&woh, s_wo_hi); cudaGetSymbolAddress((void**)&wol, s_wo_lo);
    cudaGetSymbolAddress((void**)&qrh, s_qr_hi); cudaGetSymbolAddress((void**)&qrl, s_qr_lo);
    cudaGetSymbolAddress((void**)&krh, s_kr_hi); cudaGetSymbolAddress((void**)&krl, s_kr_lo);
    cudaGetSymbolAddress((void**)&vth, s_vt_hi); cudaGetSymbolAddress((void**)&vtl, s_vt_lo);
    cudaGetSymbolAddress((void**)&ath, s_at_hi); cudaGetSymbolAddress((void**)&atl, s_at_lo);
    cudaGetSymbolAddress((void**)&pv,  g_v);

    cudaFuncSetAttribute(gemm_qkv,
                         cudaFuncAttributeMaxDynamicSharedMemorySize, GEMM_SMEM);
    cudaFuncSetAttribute(gemm_bf16x3,
                         cudaFuncAttributeMaxDynamicSharedMemorySize, GEMM_SMEM);
    cudaFuncSetAttribute(flash_attn_bf16,
                         cudaFuncAttributeMaxDynamicSharedMemorySize, ATT_SMEM);

    // one merged split pass (x + all 4 weights)
    split_all<<<(SEG5 / 2 + 255) / 256, 256>>>(
        x, wq, wk, wv, wo,
        xh, xl, wqh, wql, wkh, wkl, wvh, wvl, woh, wol);

    // unified Q/K/V projection (768 CTAs, one launch)
    gemm_qkv<<<768, 256, GEMM_SMEM>>>(
        xh, xl, wqh, wql, bq, wkh, wkl, bk, wvh, wvl, bv,
        freqs, qrh, qrl, krh, krl, pv);

    transpose_v_split<<<(BSZ * NG * HD * (SEQ / 2)) / 256, 256>>>(pv, vth, vtl);

    // attention (writes split output directly)
    flash_attn_bf16<<<dim3(SEQ / 128, BSZ * NH), 256, ATT_SMEM>>>(
        qrh, qrl, krh, krl, vth, vtl, ath, atl);

    // output projection
    gemm_bf16x3<<<dim3(HID / 128, MROWS / 128), 256, GEMM_SMEM>>>(
        ath, atl, woh, wol, bo, out, MROWS, HID, HID);
}

// round 11
// speedup vs baseline: 1.5702x; 1.0801x over previous
#include <cuda_runtime.h>
#include <cuda_bf16.h>
#include <math.h>
#include <stdint.h>

#define BSZ   2
#define SEQ   2048
#define HID   2048
#define NH    32
#define NG    8
#define HD    64
#define KVD   512
#define MROWS 4096

// ---------------- scratch ---------------------------------------------------
__device__ __nv_bfloat16 s_x_hi [MROWS * HID];
__device__ __nv_bfloat16 s_x_lo [MROWS * HID];
__device__ __nv_bfloat16 s_wq_hi[HID * HID];
__device__ __nv_bfloat16 s_wq_lo[HID * HID];
__device__ __nv_bfloat16 s_wk_hi[KVD * HID];
__device__ __nv_bfloat16 s_wk_lo[KVD * HID];
__device__ __nv_bfloat16 s_wv_hi[KVD * HID];
__device__ __nv_bfloat16 s_wv_lo[KVD * HID];
__device__ __nv_bfloat16 s_wo_hi[HID * HID];
__device__ __nv_bfloat16 s_wo_lo[HID * HID];
__device__ float g_v  [MROWS * KVD];
__device__ __nv_bfloat16 s_qr_hi[BSZ * NH * SEQ * HD];
__device__ __nv_bfloat16 s_qr_lo[BSZ * NH * SEQ * HD];
__device__ __nv_bfloat16 s_kr_hi[BSZ * NG * SEQ * HD];
__device__ __nv_bfloat16 s_kr_lo[BSZ * NG * SEQ * HD];
__device__ __nv_bfloat16 s_vt_hi[BSZ * NG * HD * SEQ];   // [b,g,d,s]
__device__ __nv_bfloat16 s_vt_lo[BSZ * NG * HD * SEQ];
__device__ __nv_bfloat16 s_at_hi[MROWS * HID];
__device__ __nv_bfloat16 s_at_lo[MROWS * HID];

// ---------------- helpers ---------------------------------------------------
__device__ __forceinline__ void cp_async16(void* smem_ptr, const void* gptr) {
    uint32_t s = (uint32_t)__cvta_generic_to_shared(smem_ptr);
    asm volatile("cp.async.cg.shared.global [%0], [%1], 16;\n" :: "r"(s), "l"(gptr));
}
#define CP_COMMIT()  asm volatile("cp.async.commit_group;\n" ::: "memory")
#define CP_WAIT(n)   asm volatile("cp.async.wait_group %0;\n" :: "n"(n) : "memory")

#define MMA_BF16(Cc, Aa, Bb) asm volatile( \
    "mma.sync.aligned.m16n8k16.row.col.f32.bf16.bf16.f32 " \
    "{%0,%1,%2,%3},{%4,%5,%6,%7},{%8,%9},{%0,%1,%2,%3};\n" \
    : "+f"(Cc[0]), "+f"(Cc[1]), "+f"(Cc[2]), "+f"(Cc[3]) \
    : "r"(Aa[0]), "r"(Aa[1]), "r"(Aa[2]), "r"(Aa[3]), "r"(Bb[0]), "r"(Bb[1]))

__device__ __forceinline__ uint32_t pack2(float x0, float x1, uint32_t& lo_out) {
    __nv_bfloat16 h0 = __float2bfloat16(x0);
    __nv_bfloat16 h1 = __float2bfloat16(x1);
    __nv_bfloat16 l0 = __float2bfloat16(x0 - __bfloat162float(h0));
    __nv_bfloat16 l1 = __float2bfloat16(x1 - __bfloat162float(h1));
    __nv_bfloat162 H = __halves2bfloat162(h0, h1);
    __nv_bfloat162 L = __halves2bfloat162(l0, l1);
    lo_out = *(uint32_t*)&L;
    return *(uint32_t*)&H;
}

// ---------------- merged split: x + wq + wk + wv + wo -----------------------
#define NX   (MROWS * HID)
#define NWQ  (HID * HID)
#define NWKV (KVD * HID)
#define SEG1 (NX)
#define SEG2 (SEG1 + NWQ)
#define SEG3 (SEG2 + NWKV)
#define SEG4 (SEG3 + NWKV)
#define SEG5 (SEG4 + NWQ)

__global__ void split_all(
    const float* __restrict__ x,  const float* __restrict__ wq,
    const float* __restrict__ wk, const float* __restrict__ wv,
    const float* __restrict__ wo,
    __nv_bfloat16* __restrict__ xh,  __nv_bfloat16* __restrict__ xl,
    __nv_bfloat16* __restrict__ wqh, __nv_bfloat16* __restrict__ wql,
    __nv_bfloat16* __restrict__ wkh, __nv_bfloat16* __restrict__ wkl,
    __nv_bfloat16* __restrict__ wvh, __nv_bfloat16* __restrict__ wvl,
    __nv_bfloat16* __restrict__ woh, __nv_bfloat16* __restrict__ wol)
{
    int i = (blockIdx.x * blockDim.x + threadIdx.x) * 2;
    if (i >= SEG5) return;
    const float* src; __nv_bfloat16 *hi, *lo; int off;
    if      (i < SEG1) { src = x;  hi = xh;  lo = xl;  off = i; }
    else if (i < SEG2) { src = wq; hi = wqh; lo = wql; off = i - SEG1; }
    else if (i < SEG3) { src = wk; hi = wkh; lo = wkl; off = i - SEG2; }
    else if (i < SEG4) { src = wv; hi = wvh; lo = wvl; off = i - SEG3; }
    else               { src = wo; hi = woh; lo = wol; off = i - SEG4; }
    float2 v = *(const float2*)&src[off];
    uint32_t lw, hw = pack2(v.x, v.y, lw);
    *(uint32_t*)&hi[off] = hw;
    *(uint32_t*)&lo[off] = lw;
}

// ---------------- 3x bf16-split GEMM core macros ----------------------------
#define LDG_   40
#define GSTAGE (4 * 128 * LDG_)
#define GEMM_SMEM (2 * GSTAGE * 2)

#define G_PROLOG()                                                           \
    const int tid  = threadIdx.x;                                            \
    const int lane = tid & 31;                                               \
    const int w    = tid >> 5;                                               \
    const int wm   = w >> 2;                                                 \
    const int wn   = w & 3;                                                  \
    const int grp  = lane >> 2;                                              \
    const int tig  = lane & 3;                                               \
    float c[4][4][4];                                                        \
    _Pragma("unroll")                                                        \
    for (int mt = 0; mt < 4; mt++)                                           \
        _Pragma("unroll")                                                    \
        for (int nt = 0; nt < 4; nt++)                                       \
            _Pragma("unroll")                                                \
            for (int i = 0; i < 4; i++) c[mt][nt][i] = 0.f;

#define G_LOAD_STAGE(sidx, k0) do {                                          \
    __nv_bfloat16* Ash_ = smb + (sidx) * GSTAGE;                             \
    __nv_bfloat16* Asl_ = Ash_ + 128 * LDG_;                                 \
    __nv_bfloat16* Wsh_ = Asl_ + 128 * LDG_;                                 \
    __nv_bfloat16* Wsl_ = Wsh_ + 128 * LDG_;                                 \
    _Pragma("unroll")                                                        \
    for (int j_ = 0; j_ < 2; j_++) {                                         \
        int cch_ = tid + j_ * 256;                                           \
        int r_   = cch_ >> 2;                                                \
        int off_ = (cch_ & 3) * 8;                                           \
        cp_async16(Ash_ + r_ * LDG_ + off_, Ah + (size_t)(m0 + r_) * K + (k0) + off_); \
        cp_async16(Asl_ + r_ * LDG_ + off_, Al + (size_t)(m0 + r_) * K + (k0) + off_); \
        cp_async16(Wsh_ + r_ * LDG_ + off_, Wh + (size_t)(n0 + r_) * K + (k0) + off_); \
        cp_async16(Wsl_ + r_ * LDG_ + off_, Wl + (size_t)(n0 + r_) * K + (k0) + off_); \
    }                                                                        \
    CP_COMMIT();                                                             \
} while (0)

#define G_MAINLOOP()                                                         \
    G_LOAD_STAGE(0, 0);                                                      \
    const int NIT = K >> 5;                                                  \
    for (int it = 0; it < NIT; it++) {                                       \
        int s = it & 1;                                                      \
        if (it + 1 < NIT) { G_LOAD_STAGE(s ^ 1, (it + 1) << 5); CP_WAIT(1); }\
        else             { CP_WAIT(0); }                                     \
        __syncthreads();                                                     \
        const __nv_bfloat16* Ash = smb + s * GSTAGE;                         \
        const __nv_bfloat16* Asl = Ash + 128 * LDG_;                         \
        const __nv_bfloat16* Wsh = Asl + 128 * LDG_;                         \
        const __nv_bfloat16* Wsl = Wsh + 128 * LDG_;                         \
        _Pragma("unroll")                                                    \
        for (int kk = 0; kk < 2; kk++) {                                     \
            const int cc = kk * 16 + tig * 2;                                \
            uint32_t bh[4][2], bl[4][2];                                     \
            _Pragma("unroll")                                                \
            for (int nt = 0; nt < 4; nt++) {                                 \
                int r = wn * 32 + nt * 8 + grp;                              \
                bh[nt][0] = *(const uint32_t*)&Wsh[r * LDG_ + cc];           \
                bh[nt][1] = *(const uint32_t*)&Wsh[r * LDG_ + cc + 8];       \
                bl[nt][0] = *(const uint32_t*)&Wsl[r * LDG_ + cc];           \
                bl[nt][1] = *(const uint32_t*)&Wsl[r * LDG_ + cc + 8];       \
            }                                                                \
            _Pragma("unroll")                                                \
            for (int mt = 0; mt < 4; mt++) {                                 \
                int r = wm * 64 + mt * 16 + grp;                             \
                uint32_t ah[4], al[4];                                       \
                ah[0] = *(const uint32_t*)&Ash[r * LDG_ + cc];               \
                ah[1] = *(const uint32_t*)&Ash[(r + 8) * LDG_ + cc];         \
                ah[2] = *(const uint32_t*)&Ash[r * LDG_ + cc + 8];           \
                ah[3] = *(const uint32_t*)&Ash[(r + 8) * LDG_ + cc + 8];     \
                al[0] = *(const uint32_t*)&Asl[r * LDG_ + cc];               \
                al[1] = *(const uint32_t*)&Asl[(r + 8) * LDG_ + cc];         \
                al[2] = *(const uint32_t*)&Asl[r * LDG_ + cc + 8];           \
                al[3] = *(const uint32_t*)&Asl[(r + 8) * LDG_ + cc + 8];     \
                _Pragma("unroll")                                            \
                for (int nt = 0; nt < 4; nt++) {                             \
                    MMA_BF16(c[mt][nt], ah, bh[nt]);                         \
                    MMA_BF16(c[mt][nt], ah, bl[nt]);                         \
                    MMA_BF16(c[mt][nt], al, bh[nt]);                         \
                }                                                            \
            }                                                                \
        }                                                                    \
        __syncthreads();                                                     \
    }

// ---------------- UNIFIED Q/K/V projection (one launch, 768 CTAs) ----------
__global__ __launch_bounds__(256, 2) void gemm_qkv(
    const __nv_bfloat16* __restrict__ xh,  const __nv_bfloat16* __restrict__ xl,
    const __nv_bfloat16* __restrict__ wqh, const __nv_bfloat16* __restrict__ wql,
    const float* __restrict__ bq,
    const __nv_bfloat16* __restrict__ wkh, const __nv_bfloat16* __restrict__ wkl,
    const float* __restrict__ bk,
    const __nv_bfloat16* __restrict__ wvh, const __nv_bfloat16* __restrict__ wvl,
    const float* __restrict__ bv,
    const float* __restrict__ freqs,
    __nv_bfloat16* __restrict__ qrh, __nv_bfloat16* __restrict__ qrl,
    __nv_bfloat16* __restrict__ krh, __nv_bfloat16* __restrict__ krl,
    float* __restrict__ vout)
{
    extern __shared__ __nv_bfloat16 smb[];
    const int id = blockIdx.x;
    const __nv_bfloat16 *Ah = xh, *Al = xl, *Wh, *Wl;
    const float* bias;
    int m0, n0, role;
    if (id < 512)      { role = 0; m0 = (id >> 4) * 128; n0 = (id & 15) * 128;
                         Wh = wqh; Wl = wql; bias = bq; }
    else if (id < 640) { int t = id - 512; role = 1; m0 = (t >> 2) * 128; n0 = (t & 3) * 128;
                         Wh = wkh; Wl = wkl; bias = bk; }
    else               { int t = id - 640; role = 2; m0 = (t >> 2) * 128; n0 = (t & 3) * 128;
                         Wh = wvh; Wl = wvl; bias = bv; }
    const int K = HID;

    G_PROLOG();
    G_MAINLOOP();

    if (role == 2) {
#pragma unroll
        for (int mt = 0; mt < 4; mt++) {
#pragma unroll
            for (int nt = 0; nt < 4; nt++) {
                int row = m0 + wm * 64 + mt * 16 + grp;
                int col = n0 + wn * 32 + nt * 8 + tig * 2;
                float2 bv2 = *(const float2*)&bias[col];
                *(float2*)&vout[(size_t)row * KVD + col] =
                    make_float2(c[mt][nt][0] + bv2.x, c[mt][nt][1] + bv2.y);
                *(float2*)&vout[(size_t)(row + 8) * KVD + col] =
                    make_float2(c[mt][nt][2] + bv2.x, c[mt][nt][3] + bv2.y);
            }
        }
    } else {
        const int nheads = (role == 0) ? NH : NG;
        __nv_bfloat16* dsth = (role == 0) ? qrh : krh;
        __nv_bfloat16* dstl = (role == 0) ? qrl : krl;
#pragma unroll
        for (int mt = 0; mt < 4; mt++) {
            int row = m0 + wm * 64 + mt * 16 + grp;
            int b_  = row >> 11;
            int s_  = row & (SEQ - 1);
#pragma unroll
            for (int nt = 0; nt < 4; nt++) {
                int col = n0 + wn * 32 + nt * 8 + tig * 2;
                int h_  = col >> 6;
                int d_  = col & 63;
                float2 bv2 = *(const float2*)&bias[col];
                float2 f0 = *(const float2*)&freqs[s_ * HD + d_];
                float2 f1 = *(const float2*)&freqs[(s_ + 8) * HD + d_];
                float v0 = c[mt][nt][0] + bv2.x, v1 = c[mt][nt][1] + bv2.y;
                float v2 = c[mt][nt][2] + bv2.x, v3 = c[mt][nt][3] + bv2.y;
                uint32_t lw0, hw0 = pack2(v0 * f0.x - v1 * f0.y, v0 * f0.y + v1 * f0.x, lw0);
                uint32_t lw1, hw1 = pack2(v2 * f1.x - v3 * f1.y, v2 * f1.y + v3 * f1.x, lw1);
                size_t o0 = ((size_t)(b_ * nheads + h_) * SEQ + s_) * HD + d_;
                size_t o1 = o0 + (size_t)8 * HD;
                *(uint32_t*)&dsth[o0] = hw0;
                *(uint32_t*)&dstl[o0] = lw0;
                *(uint32_t*)&dsth[o1] = hw1;
                *(uint32_t*)&dstl[o1] = lw1;
            }
        }
    }
}

// ---------------- O projection ----------------------------------------------
__global__ __launch_bounds__(256, 2) void gemm_bf16x3(
    const __nv_bfloat16* __restrict__ Ah, const __nv_bfloat16* __restrict__ Al,
    const __nv_bfloat16* __restrict__ Wh, const __nv_bfloat16* __restrict__ Wl,
    const float* __restrict__ bias, float* __restrict__ C,
    int M, int N, int K)
{
    extern __shared__ __nv_bfloat16 smb[];
    const int m0 = blockIdx.y * 128;
    const int n0 = blockIdx.x * 128;
    G_PROLOG();
    G_MAINLOOP();
#pragma unroll
    for (int mt = 0; mt < 4; mt++) {
#pragma unroll
        for (int nt = 0; nt < 4; nt++) {
            int row = m0 + wm * 64 + mt * 16 + grp;
            int col = n0 + wn * 32 + nt * 8 + tig * 2;
            float2 bv = *(const float2*)&bias[col];
            *(float2*)&C[(size_t)row * N + col] =
                make_float2(c[mt][nt][0] + bv.x, c[mt][nt][1] + bv.y);
            *(float2*)&C[(size_t)(row + 8) * N + col] =
                make_float2(c[mt][nt][2] + bv.x, c[mt][nt][3] + bv.y);
        }
    }
}

// V: [b,s,g*64+d] fp32  ->  [b,g,d,s] bf16 hi/lo
__global__ void transpose_v_split(const float* __restrict__ vlin,
                                  __nv_bfloat16* __restrict__ vhi,
                                  __nv_bfloat16* __restrict__ vlo)
{
    int idx = blockIdx.x * blockDim.x + threadIdx.x;
    if (idx >= BSZ * NG * HD * (SEQ / 2)) return;
    int s2 = idx & (SEQ / 2 - 1);
    int d  = (idx >> 10) & (HD - 1);
    int g  = (idx >> 16) & (NG - 1);
    int b  = idx >> 19;
    int s  = s2 * 2;
    float v0 = vlin[(size_t)(b * SEQ + s)     * KVD + g * HD + d];
    float v1 = vlin[(size_t)(b * SEQ + s + 1) * KVD + g * HD + d];
    size_t off = ((size_t)(b * NG + g) * HD + d) * SEQ + s;
    uint32_t lw, hw = pack2(v0, v1, lw);
    *(uint32_t*)&vhi[off] = hw;
    *(uint32_t*)&vlo[off] = lw;
}

// ---------------- flash attention, bf16x3 mma (unchanged, known-good) --------
#define LDB_ 72
#define ATT_SMEM ((2 * 128 * LDB_ + 4 * 64 * LDB_) * 2)

__global__ __launch_bounds__(256, 1) void flash_attn_bf16(
    const __nv_bfloat16* __restrict__ qhi, const __nv_bfloat16* __restrict__ qlo,
    const __nv_bfloat16* __restrict__ khi, const __nv_bfloat16* __restrict__ klo,
    const __nv_bfloat16* __restrict__ vhi, const __nv_bfloat16* __restrict__ vlo,
    __nv_bfloat16* __restrict__ ath, __nv_bfloat16* __restrict__ atl)
{
    extern __shared__ __nv_bfloat16 smb[];
    __nv_bfloat16* Qh = smb;
    __nv_bfloat16* Ql = Qh + 128 * LDB_;
    __nv_bfloat16* Kh = Ql + 128 * LDB_;
    __nv_bfloat16* Kl = Kh + 64 * LDB_;
    __nv_bfloat16* Vh = Kl + 64 * LDB_;
    __nv_bfloat16* Vl = Vh + 64 * LDB_;

    const int tid  = threadIdx.x;
    const int lane = tid & 31;
    const int w    = tid >> 5;
    const int grp  = lane >> 2;
    const int tig  = lane & 3;
    const int qb   = gridDim.x - 1 - blockIdx.x;
    const int bh_  = blockIdx.y;
    const int b    = bh_ >> 5;
    const int h    = bh_ & 31;
    const int g    = h >> 2;
    const int q0   = qb * 128;
    const size_t qoff  = ((size_t)(b * NH + h) * SEQ + q0) * HD;
    const size_t kvoff = (size_t)(b * NG + g) * SEQ * HD;
    const size_t vtoff = (size_t)(b * NG + g) * HD * SEQ;

    for (int i = tid; i < 1024; i += 256) {
        int r = i >> 3, off = (i & 7) * 8;
        *(uint4*)&Qh[r * LDB_ + off] = *(const uint4*)&qhi[qoff + (size_t)r * HD + off];
        *(uint4*)&Ql[r * LDB_ + off] = *(const uint4*)&qlo[qoff + (size_t)r * HD + off];
    }
    __syncthreads();

    uint32_t qfh[4][4], qfl[4][4];
    {
        int r = w * 16 + grp;
#pragma unroll
        for (int kk = 0; kk < 4; kk++) {
            int cc = kk * 16 + tig * 2;
            qfh[kk][0] = *(const uint32_t*)&Qh[r * LDB_ + cc];
            qfh[kk][1] = *(const uint32_t*)&Qh[(r + 8) * LDB_ + cc];
            qfh[kk][2] = *(const uint32_t*)&Qh[r * LDB_ + cc + 8];
            qfh[kk][3] = *(const uint32_t*)&Qh[(r + 8) * LDB_ + cc + 8];
            qfl[kk][0] = *(const uint32_t*)&Ql[r * LDB_ + cc];
            qfl[kk][1] = *(const uint32_t*)&Ql[(r + 8) * LDB_ + cc];
            qfl[kk][2] = *(const uint32_t*)&Ql[r * LDB_ + cc + 8];
            qfl[kk][3] = *(const uint32_t*)&Ql[(r + 8) * LDB_ + cc + 8];
        }
    }

    float oacc[8][4];
#pragma unroll
    for (int nt = 0; nt < 8; nt++)
#pragma unroll
        for (int i = 0; i < 4; i++) oacc[nt][i] = 0.f;

    float m0 = -1e30f, m1 = -1e30f, l0 = 0.f, l1 = 0.f;
    const int gq0 = q0 + w * 16 + grp;
    const int gq1 = gq0 + 8;
    const float scale = 0.125f;

    const int nkb = 2 * qb + 2;
    for (int kb = 0; kb < nkb; kb++) {
        const int j0 = kb * 64;
        __syncthreads();
        for (int i = tid; i < 512; i += 256) {
            int r = i >> 3, off = (i & 7) * 8;
            *(uint4*)&Kh[r * LDB_ + off] = *(const uint4*)&khi[kvoff + (size_t)(j0 + r) * HD + off];
            *(uint4*)&Kl[r * LDB_ + off] = *(const uint4*)&klo[kvoff + (size_t)(j0 + r) * HD + off];
            *(uint4*)&Vh[r * LDB_ + off] = *(const uint4*)&vhi[vtoff + (size_t)r * SEQ + j0 + off];
            *(uint4*)&Vl[r * LDB_ + off] = *(const uint4*)&vlo[vtoff + (size_t)r * SEQ + j0 + off];
        }
        __syncthreads();

        float sacc[8][4];
#pragma unroll
        for (int nt = 0; nt < 8; nt++)
#pragma unroll
            for (int i = 0; i < 4; i++) sacc[nt][i] = 0.f;

#pragma unroll
        for (int kk = 0; kk < 4; kk++) {
            int cc = kk * 16 + tig * 2;
#pragma unroll
            for (int nt = 0; nt < 8; nt++) {
                int r = nt * 8 + grp;
                uint32_t bh2[2], bl2[2];
                bh2[0] = *(const uint32_t*)&Kh[r * LDB_ + cc];
                bh2[1] = *(const uint32_t*)&Kh[r * LDB_ + cc + 8];
                bl2[0] = *(const uint32_t*)&Kl[r * LDB_ + cc];
                bl2[1] = *(const uint32_t*)&Kl[r * LDB_ + cc + 8];
                MMA_BF16(sacc[nt], qfh[kk], bh2);
                MMA_BF16(sacc[nt], qfh[kk], bl2);
                MMA_BF16(sacc[nt], qfl[kk], bh2);
            }
        }

        const int colb = j0 + tig * 2;
#pragma unroll
        for (int nt = 0; nt < 8; nt++) {
            int c0g = colb + nt * 8, c1g = c0g + 1;
            sacc[nt][0] = sacc[nt][0] * scale + ((c0g <= gq0) ? 0.f : -1e9f);
            sacc[nt][1] = sacc[nt][1] * scale + ((c1g <= gq0) ? 0.f : -1e9f);
            sacc[nt][2] = sacc[nt][2] * scale + ((c0g <= gq1) ? 0.f : -1e9f);
            sacc[nt][3] = sacc[nt][3] * scale + ((c1g <= gq1) ? 0.f : -1e9f);
        }

        float mx0 = -1e30f, mx1 = -1e30f;
#pragma unroll
        for (int nt = 0; nt < 8; nt++) {
            mx0 = fmaxf(mx0, fmaxf(sacc[nt][0], sacc[nt][1]));
            mx1 = fmaxf(mx1, fmaxf(sacc[nt][2], sacc[nt][3]));
        }
        mx0 = fmaxf(mx0, __shfl_xor_sync(0xffffffffu, mx0, 1));
        mx0 = fmaxf(mx0, __shfl_xor_sync(0xffffffffu, mx0, 2));
        mx1 = fmaxf(mx1, __shfl_xor_sync(0xffffffffu, mx1, 1));
        mx1 = fmaxf(mx1, __shfl_xor_sync(0xffffffffu, mx1, 2));

        float mn0 = fmaxf(m0, mx0), mn1 = fmaxf(m1, mx1);
        float al0 = __expf(m0 - mn0), al1 = __expf(m1 - mn1);
        m0 = mn0; m1 = mn1;

        float ls0 = 0.f, ls1 = 0.f;
#pragma unroll
        for (int nt = 0; nt < 8; nt++) {
            float p00 = __expf(sacc[nt][0] - mn0);
            float p01 = __expf(sacc[nt][1] - mn0);
            float p10 = __expf(sacc[nt][2] - mn1);
            float p11 = __expf(sacc[nt][3] - mn1);
            sacc[nt][0] = p00; sacc[nt][1] = p01;
            sacc[nt][2] = p10; sacc[nt][3] = p11;
            ls0 += p00 + p01; ls1 += p10 + p11;
        }
        ls0 += __shfl_xor_sync(0xffffffffu, ls0, 1);
        ls0 += __shfl_xor_sync(0xffffffffu, ls0, 2);
        ls1 += __shfl_xor_sync(0xffffffffu, ls1, 1);
        ls1 += __shfl_xor_sync(0xffffffffu, ls1, 2);
        l0 = l0 * al0 + ls0;
        l1 = l1 * al1 + ls1;

#pragma unroll
        for (int nt = 0; nt < 8; nt++) {
            oacc[nt][0] *= al0; oacc[nt][1] *= al0;
            oacc[nt][2] *= al1; oacc[nt][3] *= al1;
        }

        {
            int pr = w * 16 + grp;
#pragma unroll
            for (int nt = 0; nt < 8; nt++) {
                int pc = nt * 8 + tig * 2;
                uint32_t lw0, hw0 = pack2(sacc[nt][0], sacc[nt][1], lw0);
                uint32_t lw1, hw1 = pack2(sacc[nt][2], sacc[nt][3], lw1);
                *(uint32_t*)&Qh[pr * LDB_ + pc]       = hw0;
                *(uint32_t*)&Ql[pr * LDB_ + pc]       = lw0;
                *(uint32_t*)&Qh[(pr + 8) * LDB_ + pc] = hw1;
                *(uint32_t*)&Ql[(pr + 8) * LDB_ + pc] = lw1;
            }
        }
        __syncwarp();

        {
            int pr = w * 16 + grp;
#pragma unroll
            for (int kk = 0; kk < 4; kk++) {
                int cc = kk * 16 + tig * 2;
                uint32_t ah[4], al_[4];
                ah[0]  = *(const uint32_t*)&Qh[pr * LDB_ + cc];
                ah[1]  = *(const uint32_t*)&Qh[(pr + 8) * LDB_ + cc];
                ah[2]  = *(const uint32_t*)&Qh[pr * LDB_ + cc + 8];
                ah[3]  = *(const uint32_t*)&Qh[(pr + 8) * LDB_ + cc + 8];
                al_[0] = *(const uint32_t*)&Ql[pr * LDB_ + cc];
                al_[1] = *(const uint32_t*)&Ql[(pr + 8) * LDB_ + cc];
                al_[2] = *(const uint32_t*)&Ql[pr * LDB_ + cc + 8];
                al_[3] = *(const uint32_t*)&Ql[(pr + 8) * LDB_ + cc + 8];
#pragma unroll
                for (int nt = 0; nt < 8; nt++) {
                    int r = nt * 8 + grp;
                    uint32_t bh2[2], bl2[2];
                    bh2[0] = *(const uint32_t*)&Vh[r * LDB_ + cc];
                    bh2[1] = *(const uint32_t*)&Vh[r * LDB_ + cc + 8];
                    bl2[0] = *(const uint32_t*)&Vl[r * LDB_ + cc];
                    bl2[1] = *(const uint32_t*)&Vl[r * LDB_ + cc + 8];
                    MMA_BF16(oacc[nt], ah, bh2);
                    MMA_BF16(oacc[nt], ah, bl2);
                    MMA_BF16(oacc[nt], al_, bh2);
                }
            }
        }
        __syncwarp();
    }

    float inv0 = 1.f / l0, inv1 = 1.f / l1;
    int row0 = q0 + w * 16 + grp;
#pragma unroll
    for (int nt = 0; nt < 8; nt++) {
        int col = h * HD + nt * 8 + tig * 2;
        size_t i0 = (size_t)(b * SEQ + row0) * HID + col;
        size_t i1 = (size_t)(b * SEQ + row0 + 8) * HID + col;
        uint32_t lw0, hw0 = pack2(oacc[nt][0] * inv0, oacc[nt][1] * inv0, lw0);
        uint32_t lw1, hw1 = pack2(oacc[nt][2] * inv1, oacc[nt][3] * inv1, lw1);
        *(uint32_t*)&ath[i0] = hw0;
        *(uint32_t*)&atl[i0] = lw0;
        *(uint32_t*)&ath[i1] = hw1;
        *(uint32_t*)&atl[i1] = lw1;
    }
}

// ---------------- launch ----------------------------------------------------
extern "C" void kernel_launch(void* const* d_in, const int* in_sizes, int n_in,
                              void* d_out, int out_size)
{
    const float* x     = (const float*)d_in[0];
    const float* freqs = (const float*)d_in[1];
    const float* wq = (const float*)d_in[3];
    const float* bq = (const float*)d_in[4];
    const float* wk = (const float*)d_in[5];
    const float* bk = (const float*)d_in[6];
    const float* wv = (const float*)d_in[7];
    const float* bv = (const float*)d_in[8];
    const float* wo = (const float*)d_in[9];
    const float* bo = (const float*)d_in[10];
    float* out = (float*)d_out;

    __nv_bfloat16 *xh, *xl, *wqh, *wql, *wkh, *wkl, *wvh, *wvl, *woh, *wol;
    __nv_bfloat16 *qrh, *qrl, *krh, *krl, *vth, *vtl, *ath, *atl;
    float *pv;
    cudaGetSymbolAddress((void**)&xh,  s_x_hi);  cudaGetSymbolAddress((void**)&xl,  s_x_lo);
    cudaGetSymbolAddress((void**)&wqh, s_wq_hi); cudaGetSymbolAddress((void**)&wql, s_wq_lo);
    cudaGetSymbolAddress((void**)&wkh, s_wk_hi); cudaGetSymbolAddress((void**)&wkl, s_wk_lo);
    cudaGetSymbolAddress((void**)&wvh, s_wv_hi); cudaGetSymbolAddress((void**)&wvl, s_wv_lo);
    cudaGetSymbolAddress((void**)&woh, s_wo_hi); cudaGetSymbolAddress((void**)&wol, s_wo_lo);
    cudaGetSymbolAddress((void**)&qrh, s_qr_hi); cudaGetSymbolAddress((void**)&qrl, s_qr_lo);
    cudaGetSymbolAddress((void**)&krh, s_kr_hi); cudaGetSymbolAddress((void**)&krl, s_kr_lo);
    cudaGetSymbolAddress((void**)&vth, s_vt_hi); cudaGetSymbolAddress((void**)&vtl, s_vt_lo);
    cudaGetSymbolAddress((void**)&ath, s_at_hi); cudaGetSymbolAddress((void**)&atl, s_at_lo);
    cudaGetSymbolAddress((void**)&pv,  g_v);

    cudaFuncSetAttribute(gemm_qkv,
                         cudaFuncAttributeMaxDynamicSharedMemorySize, GEMM_SMEM);
    cudaFuncSetAttribute(gemm_bf16x3,
                         cudaFuncAttributeMaxDynamicSharedMemorySize, GEMM_SMEM);
    cudaFuncSetAttribute(flash_attn_bf16,
                         cudaFuncAttributeMaxDynamicSharedMemorySize, ATT_SMEM);

    split_all<<<(SEG5 / 2 + 255) / 256, 256>>>(
        x, wq, wk, wv, wo,
        xh, xl, wqh, wql, wkh, wkl, wvh, wvl, woh, wol);

    gemm_qkv<<<768, 256, GEMM_SMEM>>>(
        xh, xl, wqh, wql, bq, wkh, wkl, bk, wvh, wvl, bv,
        freqs, qrh, qrl, krh, krl, pv);

    transpose_v_split<<<(BSZ * NG * HD * (SEQ / 2)) / 256, 256>>>(pv, vth, vtl);

    flash_attn_bf16<<<dim3(SEQ / 128, BSZ * NH), 256, ATT_SMEM>>>(
        qrh, qrl, krh, krl, vth, vtl, ath, atl);

    gemm_bf16x3<<<dim3(HID / 128, MROWS / 128), 256, GEMM_SMEM>>>(
        ath, atl, woh, wol, bo, out, MROWS, HID, HID);
}

// round 12
// speedup vs baseline: 1.6829x; 1.0717x over previous
#include <cuda_runtime.h>
#include <cuda_bf16.h>
#include <math.h>
#include <stdint.h>

#define BSZ   2
#define SEQ   2048
#define HID   2048
#define NH    32
#define NG    8
#define HD    64
#define KVD   512
#define MROWS 4096

// ---------------- scratch ---------------------------------------------------
__device__ __nv_bfloat16 s_x_hi [MROWS * HID];
__device__ __nv_bfloat16 s_x_lo [MROWS * HID];
__device__ __nv_bfloat16 s_wq_hi[HID * HID];
__device__ __nv_bfloat16 s_wq_lo[HID * HID];
__device__ __nv_bfloat16 s_wk_hi[KVD * HID];
__device__ __nv_bfloat16 s_wk_lo[KVD * HID];
__device__ __nv_bfloat16 s_wv_hi[KVD * HID];
__device__ __nv_bfloat16 s_wv_lo[KVD * HID];
__device__ __nv_bfloat16 s_wo_hi[HID * HID];
__device__ __nv_bfloat16 s_wo_lo[HID * HID];
__device__ float g_v  [MROWS * KVD];
__device__ __nv_bfloat16 s_qr_hi[BSZ * NH * SEQ * HD];
__device__ __nv_bfloat16 s_qr_lo[BSZ * NH * SEQ * HD];
__device__ __nv_bfloat16 s_kr_hi[BSZ * NG * SEQ * HD];
__device__ __nv_bfloat16 s_kr_lo[BSZ * NG * SEQ * HD];
__device__ __nv_bfloat16 s_vt_hi[BSZ * NG * HD * SEQ];   // [b,g,d,s]
__device__ __nv_bfloat16 s_vt_lo[BSZ * NG * HD * SEQ];
__device__ __nv_bfloat16 s_at_hi[MROWS * HID];
__device__ __nv_bfloat16 s_at_lo[MROWS * HID];

// ---------------- helpers ---------------------------------------------------
__device__ __forceinline__ void cp_async16(void* smem_ptr, const void* gptr) {
    uint32_t s = (uint32_t)__cvta_generic_to_shared(smem_ptr);
    asm volatile("cp.async.cg.shared.global [%0], [%1], 16;\n" :: "r"(s), "l"(gptr));
}
#define CP_COMMIT()  asm volatile("cp.async.commit_group;\n" ::: "memory")
#define CP_WAIT(n)   asm volatile("cp.async.wait_group %0;\n" :: "n"(n) : "memory")

#define MMA_BF16(Cc, Aa, Bb) asm volatile( \
    "mma.sync.aligned.m16n8k16.row.col.f32.bf16.bf16.f32 " \
    "{%0,%1,%2,%3},{%4,%5,%6,%7},{%8,%9},{%0,%1,%2,%3};\n" \
    : "+f"(Cc[0]), "+f"(Cc[1]), "+f"(Cc[2]), "+f"(Cc[3]) \
    : "r"(Aa[0]), "r"(Aa[1]), "r"(Aa[2]), "r"(Aa[3]), "r"(Bb[0]), "r"(Bb[1]))

__device__ __forceinline__ uint32_t pack2(float x0, float x1, uint32_t& lo_out) {
    __nv_bfloat16 h0 = __float2bfloat16(x0);
    __nv_bfloat16 h1 = __float2bfloat16(x1);
    __nv_bfloat16 l0 = __float2bfloat16(x0 - __bfloat162float(h0));
    __nv_bfloat16 l1 = __float2bfloat16(x1 - __bfloat162float(h1));
    __nv_bfloat162 H = __halves2bfloat162(h0, h1);
    __nv_bfloat162 L = __halves2bfloat162(l0, l1);
    lo_out = *(uint32_t*)&L;
    return *(uint32_t*)&H;
}

// ---------------- merged split: x + wq + wk + wv + wo -----------------------
#define NX   (MROWS * HID)
#define NWQ  (HID * HID)
#define NWKV (KVD * HID)
#define SEG1 (NX)
#define SEG2 (SEG1 + NWQ)
#define SEG3 (SEG2 + NWKV)
#define SEG4 (SEG3 + NWKV)
#define SEG5 (SEG4 + NWQ)

__global__ void split_all(
    const float* __restrict__ x,  const float* __restrict__ wq,
    const float* __restrict__ wk, const float* __restrict__ wv,
    const float* __restrict__ wo,
    __nv_bfloat16* __restrict__ xh,  __nv_bfloat16* __restrict__ xl,
    __nv_bfloat16* __restrict__ wqh, __nv_bfloat16* __restrict__ wql,
    __nv_bfloat16* __restrict__ wkh, __nv_bfloat16* __restrict__ wkl,
    __nv_bfloat16* __restrict__ wvh, __nv_bfloat16* __restrict__ wvl,
    __nv_bfloat16* __restrict__ woh, __nv_bfloat16* __restrict__ wol)
{
    int i = (blockIdx.x * blockDim.x + threadIdx.x) * 2;
    if (i >= SEG5) return;
    const float* src; __nv_bfloat16 *hi, *lo; int off;
    if      (i < SEG1) { src = x;  hi = xh;  lo = xl;  off = i; }
    else if (i < SEG2) { src = wq; hi = wqh; lo = wql; off = i - SEG1; }
    else if (i < SEG3) { src = wk; hi = wkh; lo = wkl; off = i - SEG2; }
    else if (i < SEG4) { src = wv; hi = wvh; lo = wvl; off = i - SEG3; }
    else               { src = wo; hi = woh; lo = wol; off = i - SEG4; }
    float2 v = *(const float2*)&src[off];
    uint32_t lw, hw = pack2(v.x, v.y, lw);
    *(uint32_t*)&hi[off] = hw;
    *(uint32_t*)&lo[off] = lw;
}

// ---------------- 3x bf16-split GEMM core macros ----------------------------
#define LDG_   40
#define GSTAGE (4 * 128 * LDG_)
#define GEMM_SMEM (2 * GSTAGE * 2)

#define G_PROLOG()                                                           \
    const int tid  = threadIdx.x;                                            \
    const int lane = tid & 31;                                               \
    const int w    = tid >> 5;                                               \
    const int wm   = w >> 2;                                                 \
    const int wn   = w & 3;                                                  \
    const int grp  = lane >> 2;                                              \
    const int tig  = lane & 3;                                               \
    float c[4][4][4];                                                        \
    _Pragma("unroll")                                                        \
    for (int mt = 0; mt < 4; mt++)                                           \
        _Pragma("unroll")                                                    \
        for (int nt = 0; nt < 4; nt++)                                       \
            _Pragma("unroll")                                                \
            for (int i = 0; i < 4; i++) c[mt][nt][i] = 0.f;

#define G_LOAD_STAGE(sidx, k0) do {                                          \
    __nv_bfloat16* Ash_ = smb + (sidx) * GSTAGE;                             \
    __nv_bfloat16* Asl_ = Ash_ + 128 * LDG_;                                 \
    __nv_bfloat16* Wsh_ = Asl_ + 128 * LDG_;                                 \
    __nv_bfloat16* Wsl_ = Wsh_ + 128 * LDG_;                                 \
    _Pragma("unroll")                                                        \
    for (int j_ = 0; j_ < 2; j_++) {                                         \
        int cch_ = tid + j_ * 256;                                           \
        int r_   = cch_ >> 2;                                                \
        int off_ = (cch_ & 3) * 8;                                           \
        cp_async16(Ash_ + r_ * LDG_ + off_, Ah + (size_t)(m0 + r_) * K + (k0) + off_); \
        cp_async16(Asl_ + r_ * LDG_ + off_, Al + (size_t)(m0 + r_) * K + (k0) + off_); \
        cp_async16(Wsh_ + r_ * LDG_ + off_, Wh + (size_t)(n0 + r_) * K + (k0) + off_); \
        cp_async16(Wsl_ + r_ * LDG_ + off_, Wl + (size_t)(n0 + r_) * K + (k0) + off_); \
    }                                                                        \
    CP_COMMIT();                                                             \
} while (0)

#define G_MAINLOOP()                                                         \
    G_LOAD_STAGE(0, 0);                                                      \
    const int NIT = K >> 5;                                                  \
    for (int it = 0; it < NIT; it++) {                                       \
        int s = it & 1;                                                      \
        if (it + 1 < NIT) { G_LOAD_STAGE(s ^ 1, (it + 1) << 5); CP_WAIT(1); }\
        else             { CP_WAIT(0); }                                     \
        __syncthreads();                                                     \
        const __nv_bfloat16* Ash = smb + s * GSTAGE;                         \
        const __nv_bfloat16* Asl = Ash + 128 * LDG_;                         \
        const __nv_bfloat16* Wsh = Asl + 128 * LDG_;                         \
        const __nv_bfloat16* Wsl = Wsh + 128 * LDG_;                         \
        _Pragma("unroll")                                                    \
        for (int kk = 0; kk < 2; kk++) {                                     \
            const int cc = kk * 16 + tig * 2;                                \
            uint32_t bh[4][2], bl[4][2];                                     \
            _Pragma("unroll")                                                \
            for (int nt = 0; nt < 4; nt++) {                                 \
                int r = wn * 32 + nt * 8 + grp;                              \
                bh[nt][0] = *(const uint32_t*)&Wsh[r * LDG_ + cc];           \
                bh[nt][1] = *(const uint32_t*)&Wsh[r * LDG_ + cc + 8];       \
                bl[nt][0] = *(const uint32_t*)&Wsl[r * LDG_ + cc];           \
                bl[nt][1] = *(const uint32_t*)&Wsl[r * LDG_ + cc + 8];       \
            }                                                                \
            _Pragma("unroll")                                                \
            for (int mt = 0; mt < 4; mt++) {                                 \
                int r = wm * 64 + mt * 16 + grp;                             \
                uint32_t ah[4], al[4];                                       \
                ah[0] = *(const uint32_t*)&Ash[r * LDG_ + cc];               \
                ah[1] = *(const uint32_t*)&Ash[(r + 8) * LDG_ + cc];         \
                ah[2] = *(const uint32_t*)&Ash[r * LDG_ + cc + 8];           \
                ah[3] = *(const uint32_t*)&Ash[(r + 8) * LDG_ + cc + 8];     \
                al[0] = *(const uint32_t*)&Asl[r * LDG_ + cc];               \
                al[1] = *(const uint32_t*)&Asl[(r + 8) * LDG_ + cc];         \
                al[2] = *(const uint32_t*)&Asl[r * LDG_ + cc + 8];           \
                al[3] = *(const uint32_t*)&Asl[(r + 8) * LDG_ + cc + 8];     \
                _Pragma("unroll")                                            \
                for (int nt = 0; nt < 4; nt++) {                             \
                    MMA_BF16(c[mt][nt], ah, bh[nt]);                         \
                    MMA_BF16(c[mt][nt], ah, bl[nt]);                         \
                    MMA_BF16(c[mt][nt], al, bh[nt]);                         \
                }                                                            \
            }                                                                \
        }                                                                    \
        __syncthreads();                                                     \
    }

// ---------------- UNIFIED Q/K/V projection (one launch, 768 CTAs) ----------
__global__ __launch_bounds__(256, 2) void gemm_qkv(
    const __nv_bfloat16* __restrict__ xh,  const __nv_bfloat16* __restrict__ xl,
    const __nv_bfloat16* __restrict__ wqh, const __nv_bfloat16* __restrict__ wql,
    const float* __restrict__ bq,
    const __nv_bfloat16* __restrict__ wkh, const __nv_bfloat16* __restrict__ wkl,
    const float* __restrict__ bk,
    const __nv_bfloat16* __restrict__ wvh, const __nv_bfloat16* __restrict__ wvl,
    const float* __restrict__ bv,
    const float* __restrict__ freqs,
    __nv_bfloat16* __restrict__ qrh, __nv_bfloat16* __restrict__ qrl,
    __nv_bfloat16* __restrict__ krh, __nv_bfloat16* __restrict__ krl,
    float* __restrict__ vout)
{
    extern __shared__ __nv_bfloat16 smb[];
    const int id = blockIdx.x;
    const __nv_bfloat16 *Ah = xh, *Al = xl, *Wh, *Wl;
    const float* bias;
    int m0, n0, role;
    if (id < 512)      { role = 0; m0 = (id >> 4) * 128; n0 = (id & 15) * 128;
                         Wh = wqh; Wl = wql; bias = bq; }
    else if (id < 640) { int t = id - 512; role = 1; m0 = (t >> 2) * 128; n0 = (t & 3) * 128;
                         Wh = wkh; Wl = wkl; bias = bk; }
    else               { int t = id - 640; role = 2; m0 = (t >> 2) * 128; n0 = (t & 3) * 128;
                         Wh = wvh; Wl = wvl; bias = bv; }
    const int K = HID;

    G_PROLOG();
    G_MAINLOOP();

    if (role == 2) {
#pragma unroll
        for (int mt = 0; mt < 4; mt++) {
#pragma unroll
            for (int nt = 0; nt < 4; nt++) {
                int row = m0 + wm * 64 + mt * 16 + grp;
                int col = n0 + wn * 32 + nt * 8 + tig * 2;
                float2 bv2 = *(const float2*)&bias[col];
                *(float2*)&vout[(size_t)row * KVD + col] =
                    make_float2(c[mt][nt][0] + bv2.x, c[mt][nt][1] + bv2.y);
                *(float2*)&vout[(size_t)(row + 8) * KVD + col] =
                    make_float2(c[mt][nt][2] + bv2.x, c[mt][nt][3] + bv2.y);
            }
        }
    } else {
        const int nheads = (role == 0) ? NH : NG;
        __nv_bfloat16* dsth = (role == 0) ? qrh : krh;
        __nv_bfloat16* dstl = (role == 0) ? qrl : krl;
#pragma unroll
        for (int mt = 0; mt < 4; mt++) {
            int row = m0 + wm * 64 + mt * 16 + grp;
            int b_  = row >> 11;
            int s_  = row & (SEQ - 1);
#pragma unroll
            for (int nt = 0; nt < 4; nt++) {
                int col = n0 + wn * 32 + nt * 8 + tig * 2;
                int h_  = col >> 6;
                int d_  = col & 63;
                float2 bv2 = *(const float2*)&bias[col];
                float2 f0 = *(const float2*)&freqs[s_ * HD + d_];
                float2 f1 = *(const float2*)&freqs[(s_ + 8) * HD + d_];
                float v0 = c[mt][nt][0] + bv2.x, v1 = c[mt][nt][1] + bv2.y;
                float v2 = c[mt][nt][2] + bv2.x, v3 = c[mt][nt][3] + bv2.y;
                uint32_t lw0, hw0 = pack2(v0 * f0.x - v1 * f0.y, v0 * f0.y + v1 * f0.x, lw0);
                uint32_t lw1, hw1 = pack2(v2 * f1.x - v3 * f1.y, v2 * f1.y + v3 * f1.x, lw1);
                size_t o0 = ((size_t)(b_ * nheads + h_) * SEQ + s_) * HD + d_;
                size_t o1 = o0 + (size_t)8 * HD;
                *(uint32_t*)&dsth[o0] = hw0;
                *(uint32_t*)&dstl[o0] = lw0;
                *(uint32_t*)&dsth[o1] = hw1;
                *(uint32_t*)&dstl[o1] = lw1;
            }
        }
    }
}

// ---------------- O projection ----------------------------------------------
__global__ __launch_bounds__(256, 2) void gemm_bf16x3(
    const __nv_bfloat16* __restrict__ Ah, const __nv_bfloat16* __restrict__ Al,
    const __nv_bfloat16* __restrict__ Wh, const __nv_bfloat16* __restrict__ Wl,
    const float* __restrict__ bias, float* __restrict__ C,
    int M, int N, int K)
{
    extern __shared__ __nv_bfloat16 smb[];
    const int m0 = blockIdx.y * 128;
    const int n0 = blockIdx.x * 128;
    G_PROLOG();
    G_MAINLOOP();
#pragma unroll
    for (int mt = 0; mt < 4; mt++) {
#pragma unroll
        for (int nt = 0; nt < 4; nt++) {
            int row = m0 + wm * 64 + mt * 16 + grp;
            int col = n0 + wn * 32 + nt * 8 + tig * 2;
            float2 bv = *(const float2*)&bias[col];
            *(float2*)&C[(size_t)row * N + col] =
                make_float2(c[mt][nt][0] + bv.x, c[mt][nt][1] + bv.y);
            *(float2*)&C[(size_t)(row + 8) * N + col] =
                make_float2(c[mt][nt][2] + bv.x, c[mt][nt][3] + bv.y);
        }
    }
}

// V: [b,s,g*64+d] fp32  ->  [b,g,d,s] bf16 hi/lo
__global__ void transpose_v_split(const float* __restrict__ vlin,
                                  __nv_bfloat16* __restrict__ vhi,
                                  __nv_bfloat16* __restrict__ vlo)
{
    int idx = blockIdx.x * blockDim.x + threadIdx.x;
    if (idx >= BSZ * NG * HD * (SEQ / 2)) return;
    int s2 = idx & (SEQ / 2 - 1);
    int d  = (idx >> 10) & (HD - 1);
    int g  = (idx >> 16) & (NG - 1);
    int b  = idx >> 19;
    int s  = s2 * 2;
    float v0 = vlin[(size_t)(b * SEQ + s)     * KVD + g * HD + d];
    float v1 = vlin[(size_t)(b * SEQ + s + 1) * KVD + g * HD + d];
    size_t off = ((size_t)(b * NG + g) * HD + d) * SEQ + s;
    uint32_t lw, hw = pack2(v0, v1, lw);
    *(uint32_t*)&vhi[off] = hw;
    *(uint32_t*)&vlo[off] = lw;
}

// ---------------- flash attention: in-register P, 2 CTAs/SM ------------------
#define LDB_ 72
#define ATT_SMEM ((2 * 128 * LDB_ + 4 * 64 * LDB_) * 2)

__global__ __launch_bounds__(256, 2) void flash_attn_bf16(
    const __nv_bfloat16* __restrict__ qhi, const __nv_bfloat16* __restrict__ qlo,
    const __nv_bfloat16* __restrict__ khi, const __nv_bfloat16* __restrict__ klo,
    const __nv_bfloat16* __restrict__ vhi, const __nv_bfloat16* __restrict__ vlo,
    __nv_bfloat16* __restrict__ ath, __nv_bfloat16* __restrict__ atl)
{
    extern __shared__ __nv_bfloat16 smb[];
    __nv_bfloat16* Qh = smb;                    // [128][LDB_], preserved all kernel
    __nv_bfloat16* Ql = Qh + 128 * LDB_;
    __nv_bfloat16* Kh = Ql + 128 * LDB_;
    __nv_bfloat16* Kl = Kh + 64 * LDB_;
    __nv_bfloat16* Vh = Kl + 64 * LDB_;
    __nv_bfloat16* Vl = Vh + 64 * LDB_;

    const int tid  = threadIdx.x;
    const int lane = tid & 31;
    const int w    = tid >> 5;
    const int grp  = lane >> 2;
    const int tig  = lane & 3;
    const int qb   = gridDim.x - 1 - blockIdx.x;   // heavy tiles first
    const int bh_  = blockIdx.y;
    const int b    = bh_ >> 5;
    const int h    = bh_ & 31;
    const int g    = h >> 2;
    const int q0   = qb * 128;
    const size_t qoff  = ((size_t)(b * NH + h) * SEQ + q0) * HD;
    const size_t kvoff = (size_t)(b * NG + g) * SEQ * HD;
    const size_t vtoff = (size_t)(b * NG + g) * HD * SEQ;

    for (int i = tid; i < 1024; i += 256) {
        int r = i >> 3, off = (i & 7) * 8;
        *(uint4*)&Qh[r * LDB_ + off] = *(const uint4*)&qhi[qoff + (size_t)r * HD + off];
        *(uint4*)&Ql[r * LDB_ + off] = *(const uint4*)&qlo[qoff + (size_t)r * HD + off];
    }
    __syncthreads();

    float oacc[8][4];
#pragma unroll
    for (int nt = 0; nt < 8; nt++)
#pragma unroll
        for (int i = 0; i < 4; i++) oacc[nt][i] = 0.f;

    float m0 = -1e30f, m1 = -1e30f, l0 = 0.f, l1 = 0.f;
    const int gq0 = q0 + w * 16 + grp;
    const int gq1 = gq0 + 8;
    const float scale = 0.125f;
    const int pr = w * 16 + grp;    // this thread's Q row base in smem

    const int nkb = 2 * qb + 2;
    for (int kb = 0; kb < nkb; kb++) {
        const int j0 = kb * 64;
        __syncthreads();
        for (int i = tid; i < 512; i += 256) {
            int r = i >> 3, off = (i & 7) * 8;
            *(uint4*)&Kh[r * LDB_ + off] = *(const uint4*)&khi[kvoff + (size_t)(j0 + r) * HD + off];
            *(uint4*)&Kl[r * LDB_ + off] = *(const uint4*)&klo[kvoff + (size_t)(j0 + r) * HD + off];
            *(uint4*)&Vh[r * LDB_ + off] = *(const uint4*)&vhi[vtoff + (size_t)r * SEQ + j0 + off];
            *(uint4*)&Vl[r * LDB_ + off] = *(const uint4*)&vlo[vtoff + (size_t)r * SEQ + j0 + off];
        }
        __syncthreads();

        // ---- S = Q K^T (Q fragments reloaded from intact smem) ----
        float sacc[8][4];
#pragma unroll
        for (int nt = 0; nt < 8; nt++)
#pragma unroll
            for (int i = 0; i < 4; i++) sacc[nt][i] = 0.f;

#pragma unroll
        for (int kk = 0; kk < 4; kk++) {
            int cc = kk * 16 + tig * 2;
            uint32_t qh2[4], ql2[4];
            qh2[0] = *(const uint32_t*)&Qh[pr * LDB_ + cc];
            qh2[1] = *(const uint32_t*)&Qh[(pr + 8) * LDB_ + cc];
            qh2[2] = *(const uint32_t*)&Qh[pr * LDB_ + cc + 8];
            qh2[3] = *(const uint32_t*)&Qh[(pr + 8) * LDB_ + cc + 8];
            ql2[0] = *(const uint32_t*)&Ql[pr * LDB_ + cc];
            ql2[1] = *(const uint32_t*)&Ql[(pr + 8) * LDB_ + cc];
            ql2[2] = *(const uint32_t*)&Ql[pr * LDB_ + cc + 8];
            ql2[3] = *(const uint32_t*)&Ql[(pr + 8) * LDB_ + cc + 8];
#pragma unroll
            for (int nt = 0; nt < 8; nt++) {
                int r = nt * 8 + grp;
                uint32_t bh2[2], bl2[2];
                bh2[0] = *(const uint32_t*)&Kh[r * LDB_ + cc];
                bh2[1] = *(const uint32_t*)&Kh[r * LDB_ + cc + 8];
                bl2[0] = *(const uint32_t*)&Kl[r * LDB_ + cc];
                bl2[1] = *(const uint32_t*)&Kl[r * LDB_ + cc + 8];
                MMA_BF16(sacc[nt], qh2, bh2);
                MMA_BF16(sacc[nt], qh2, bl2);
                MMA_BF16(sacc[nt], ql2, bh2);
            }
        }

        // ---- scale + causal mask ----
        const int colb = j0 + tig * 2;
#pragma unroll
        for (int nt = 0; nt < 8; nt++) {
            int c0g = colb + nt * 8, c1g = c0g + 1;
            sacc[nt][0] = sacc[nt][0] * scale + ((c0g <= gq0) ? 0.f : -1e9f);
            sacc[nt][1] = sacc[nt][1] * scale + ((c1g <= gq0) ? 0.f : -1e9f);
            sacc[nt][2] = sacc[nt][2] * scale + ((c0g <= gq1) ? 0.f : -1e9f);
            sacc[nt][3] = sacc[nt][3] * scale + ((c1g <= gq1) ? 0.f : -1e9f);
        }

        // ---- online softmax ----
        float mx0 = -1e30f, mx1 = -1e30f;
#pragma unroll
        for (int nt = 0; nt < 8; nt++) {
            mx0 = fmaxf(mx0, fmaxf(sacc[nt][0], sacc[nt][1]));
            mx1 = fmaxf(mx1, fmaxf(sacc[nt][2], sacc[nt][3]));
        }
        mx0 = fmaxf(mx0, __shfl_xor_sync(0xffffffffu, mx0, 1));
        mx0 = fmaxf(mx0, __shfl_xor_sync(0xffffffffu, mx0, 2));
        mx1 = fmaxf(mx1, __shfl_xor_sync(0xffffffffu, mx1, 1));
        mx1 = fmaxf(mx1, __shfl_xor_sync(0xffffffffu, mx1, 2));

        float mn0 = fmaxf(m0, mx0), mn1 = fmaxf(m1, mx1);
        float al0 = __expf(m0 - mn0), al1 = __expf(m1 - mn1);
        m0 = mn0; m1 = mn1;

        float ls0 = 0.f, ls1 = 0.f;
#pragma unroll
        for (int nt = 0; nt < 8; nt++) {
            float p00 = __expf(sacc[nt][0] - mn0);
            float p01 = __expf(sacc[nt][1] - mn0);
            float p10 = __expf(sacc[nt][2] - mn1);
            float p11 = __expf(sacc[nt][3] - mn1);
            sacc[nt][0] = p00; sacc[nt][1] = p01;
            sacc[nt][2] = p10; sacc[nt][3] = p11;
            ls0 += p00 + p01; ls1 += p10 + p11;
        }
        ls0 += __shfl_xor_sync(0xffffffffu, ls0, 1);
        ls0 += __shfl_xor_sync(0xffffffffu, ls0, 2);
        ls1 += __shfl_xor_sync(0xffffffffu, ls1, 1);
        ls1 += __shfl_xor_sync(0xffffffffu, ls1, 2);
        l0 = l0 * al0 + ls0;
        l1 = l1 * al1 + ls1;

#pragma unroll
        for (int nt = 0; nt < 8; nt++) {
            oacc[nt][0] *= al0; oacc[nt][1] *= al0;
            oacc[nt][2] *= al1; oacc[nt][3] *= al1;
        }

        // ---- O += P V, P consumed directly from registers ----
        // A-frag for k-chunk kk (cols 16kk..16kk+15):
        //   ah[0] = {P[pr, 16kk+tig*2],   P[pr, 16kk+tig*2+1]}    = sacc[2kk][0..1]
        //   ah[1] = row pr+8                                      = sacc[2kk][2..3]
        //   ah[2] = cols +8                                       = sacc[2kk+1][0..1]
        //   ah[3] = row pr+8, cols +8                             = sacc[2kk+1][2..3]
#pragma unroll
        for (int kk = 0; kk < 4; kk++) {
            uint32_t ah[4], al_[4];
            ah[0] = pack2(sacc[2*kk][0],   sacc[2*kk][1],   al_[0]);
            ah[1] = pack2(sacc[2*kk][2],   sacc[2*kk][3],   al_[1]);
            ah[2] = pack2(sacc[2*kk+1][0], sacc[2*kk+1][1], al_[2]);
            ah[3] = pack2(sacc[2*kk+1][2], sacc[2*kk+1][3], al_[3]);
            int cc = kk * 16 + tig * 2;
#pragma unroll
            for (int nt = 0; nt < 8; nt++) {
                int r = nt * 8 + grp;
                uint32_t bh2[2], bl2[2];
                bh2[0] = *(const uint32_t*)&Vh[r * LDB_ + cc];
                bh2[1] = *(const uint32_t*)&Vh[r * LDB_ + cc + 8];
                bl2[0] = *(const uint32_t*)&Vl[r * LDB_ + cc];
                bl2[1] = *(const uint32_t*)&Vl[r * LDB_ + cc + 8];
                MMA_BF16(oacc[nt], ah, bh2);
                MMA_BF16(oacc[nt], ah, bl2);
                MMA_BF16(oacc[nt], al_, bh2);
            }
        }
    }

    // ---- epilogue: normalize + split directly (feeds O-projection) ----
    float inv0 = 1.f / l0, inv1 = 1.f / l1;
    int row0 = q0 + w * 16 + grp;
#pragma unroll
    for (int nt = 0; nt < 8; nt++) {
        int col = h * HD + nt * 8 + tig * 2;
        size_t i0 = (size_t)(b * SEQ + row0) * HID + col;
        size_t i1 = (size_t)(b * SEQ + row0 + 8) * HID + col;
        uint32_t lw0, hw0 = pack2(oacc[nt][0] * inv0, oacc[nt][1] * inv0, lw0);
        uint32_t lw1, hw1 = pack2(oacc[nt][2] * inv1, oacc[nt][3] * inv1, lw1);
        *(uint32_t*)&ath[i0] = hw0;
        *(uint32_t*)&atl[i0] = lw0;
        *(uint32_t*)&ath[i1] = hw1;
        *(uint32_t*)&atl[i1] = lw1;
    }
}

// ---------------- launch ----------------------------------------------------
extern "C" void kernel_launch(void* const* d_in, const int* in_sizes, int n_in,
                              void* d_out, int out_size)
{
    const float* x     = (const float*)d_in[0];
    const float* freqs = (const float*)d_in[1];
    const float* wq = (const float*)d_in[3];
    const float* bq = (const float*)d_in[4];
    const float* wk = (const float*)d_in[5];
    const float* bk = (const float*)d_in[6];
    const float* wv = (const float*)d_in[7];
    const float* bv = (const float*)d_in[8];
    const float* wo = (const float*)d_in[9];
    const float* bo = (const float*)d_in[10];
    float* out = (float*)d_out;

    __nv_bfloat16 *xh, *xl, *wqh, *wql, *wkh, *wkl, *wvh, *wvl, *woh, *wol;
    __nv_bfloat16 *qrh, *qrl, *krh, *krl, *vth, *vtl, *ath, *atl;
    float *pv;
    cudaGetSymbolAddress((void**)&xh,  s_x_hi);  cudaGetSymbolAddress((void**)&xl,  s_x_lo);
    cudaGetSymbolAddress((void**)&wqh, s_wq_hi); cudaGetSymbolAddress((void**)&wql, s_wq_lo);
    cudaGetSymbolAddress((void**)&wkh, s_wk_hi); cudaGetSymbolAddress((void**)&wkl, s_wk_lo);
    cudaGetSymbolAddress((void**)&wvh, s_wv_hi); cudaGetSymbolAddress((void**)&wvl, s_wv_lo);
    cudaGetSymbolAddress((void**)&woh, s_wo_hi); cudaGetSymbolAddress((void**)&wol, s_wo_lo);
    cudaGetSymbolAddress((void**)&qrh, s_qr_hi); cudaGetSymbolAddress((void**)&qrl, s_qr_lo);
    cudaGetSymbolAddress((void**)&krh, s_kr_hi); cudaGetSymbolAddress((void**)&krl, s_kr_lo);
    cudaGetSymbolAddress((void**)&vth, s_vt_hi); cudaGetSymbolAddress((void**)&vtl, s_vt_lo);
    cudaGetSymbolAddress((void**)&ath, s_at_hi); cudaGetSymbolAddress((void**)&atl, s_at_lo);
    cudaGetSymbolAddress((void**)&pv,  g_v);

    cudaFuncSetAttribute(gemm_qkv,
                         cudaFuncAttributeMaxDynamicSharedMemorySize, GEMM_SMEM);
    cudaFuncSetAttribute(gemm_bf16x3,
                         cudaFuncAttributeMaxDynamicSharedMemorySize, GEMM_SMEM);
    cudaFuncSetAttribute(flash_attn_bf16,
                         cudaFuncAttributeMaxDynamicSharedMemorySize, ATT_SMEM);

    split_all<<<(SEG5 / 2 + 255) / 256, 256>>>(
        x, wq, wk, wv, wo,
        xh, xl, wqh, wql, wkh, wkl, wvh, wvl, woh, wol);

    gemm_qkv<<<768, 256, GEMM_SMEM>>>(
        xh, xl, wqh, wql, bq, wkh, wkl, bk, wvh, wvl, bv,
        freqs, qrh, qrl, krh, krl, pv);

    transpose_v_split<<<(BSZ * NG * HD * (SEQ / 2)) / 256, 256>>>(pv, vth, vtl);

    flash_attn_bf16<<<dim3(SEQ / 128, BSZ * NH), 256, ATT_SMEM>>>(
        qrh, qrl, krh, krl, vth, vtl, ath, atl);

    gemm_bf16x3<<<dim3(HID / 128, MROWS / 128), 256, GEMM_SMEM>>>(
        ath, atl, woh, wol, bo, out, MROWS, HID, HID);
}

// round 14
// speedup vs baseline: 1.7408x; 1.0344x over previous
#include <cuda_runtime.h>
#include <cuda_bf16.h>
#include <math.h>
#include <stdint.h>

#define BSZ   2
#define SEQ   2048
#define HID   2048
#define NH    32
#define NG    8
#define HD    64
#define KVD   512
#define MROWS 4096

// ---------------- scratch ---------------------------------------------------
__device__ __nv_bfloat16 s_x_hi [MROWS * HID];
__device__ __nv_bfloat16 s_x_lo [MROWS * HID];
__device__ __nv_bfloat16 s_wq_hi[HID * HID];
__device__ __nv_bfloat16 s_wq_lo[HID * HID];
__device__ __nv_bfloat16 s_wk_hi[KVD * HID];
__device__ __nv_bfloat16 s_wk_lo[KVD * HID];
__device__ __nv_bfloat16 s_wv_hi[KVD * HID];
__device__ __nv_bfloat16 s_wv_lo[KVD * HID];
__device__ __nv_bfloat16 s_wo_hi[HID * HID];
__device__ __nv_bfloat16 s_wo_lo[HID * HID];
__device__ float g_v  [MROWS * KVD];
__device__ __nv_bfloat16 s_qr_hi[BSZ * NH * SEQ * HD];
__device__ __nv_bfloat16 s_qr_lo[BSZ * NH * SEQ * HD];
__device__ __nv_bfloat16 s_kr_hi[BSZ * NG * SEQ * HD];
__device__ __nv_bfloat16 s_kr_lo[BSZ * NG * SEQ * HD];
__device__ __nv_bfloat16 s_vt_hi[BSZ * NG * HD * SEQ];   // [b,g,d,s]
__device__ __nv_bfloat16 s_vt_lo[BSZ * NG * HD * SEQ];
__device__ __nv_bfloat16 s_at_hi[MROWS * HID];
__device__ __nv_bfloat16 s_at_lo[MROWS * HID];

// ---------------- helpers ---------------------------------------------------
__device__ __forceinline__ void cp_async16(void* smem_ptr, const void* gptr) {
    uint32_t s = (uint32_t)__cvta_generic_to_shared(smem_ptr);
    asm volatile("cp.async.cg.shared.global [%0], [%1], 16;\n" :: "r"(s), "l"(gptr));
}
#define CP_COMMIT()  asm volatile("cp.async.commit_group;\n" ::: "memory")
#define CP_WAIT(n)   asm volatile("cp.async.wait_group %0;\n" :: "n"(n) : "memory")

#define MMA_BF16(Cc, Aa, Bb) asm volatile( \
    "mma.sync.aligned.m16n8k16.row.col.f32.bf16.bf16.f32 " \
    "{%0,%1,%2,%3},{%4,%5,%6,%7},{%8,%9},{%0,%1,%2,%3};\n" \
    : "+f"(Cc[0]), "+f"(Cc[1]), "+f"(Cc[2]), "+f"(Cc[3]) \
    : "r"(Aa[0]), "r"(Aa[1]), "r"(Aa[2]), "r"(Aa[3]), "r"(Bb[0]), "r"(Bb[1]))

__device__ __forceinline__ void ldsm_x4(uint32_t* r, uint32_t addr) {
    asm volatile("ldmatrix.sync.aligned.m8n8.x4.shared.b16 {%0,%1,%2,%3}, [%4];"
        : "=r"(r[0]), "=r"(r[1]), "=r"(r[2]), "=r"(r[3]) : "r"(addr));
}
__device__ __forceinline__ void ldsm_x2(uint32_t* r, uint32_t addr) {
    asm volatile("ldmatrix.sync.aligned.m8n8.x2.shared.b16 {%0,%1}, [%2];"
        : "=r"(r[0]), "=r"(r[1]) : "r"(addr));
}

__device__ __forceinline__ uint32_t pack2(float x0, float x1, uint32_t& lo_out) {
    __nv_bfloat16 h0 = __float2bfloat16(x0);
    __nv_bfloat16 h1 = __float2bfloat16(x1);
    __nv_bfloat16 l0 = __float2bfloat16(x0 - __bfloat162float(h0));
    __nv_bfloat16 l1 = __float2bfloat16(x1 - __bfloat162float(h1));
    __nv_bfloat162 H = __halves2bfloat162(h0, h1);
    __nv_bfloat162 L = __halves2bfloat162(l0, l1);
    lo_out = *(uint32_t*)&L;
    return *(uint32_t*)&H;
}

// ---------------- merged split: x + wq + wk + wv + wo -----------------------
#define NX   (MROWS * HID)
#define NWQ  (HID * HID)
#define NWKV (KVD * HID)
#define SEG1 (NX)
#define SEG2 (SEG1 + NWQ)
#define SEG3 (SEG2 + NWKV)
#define SEG4 (SEG3 + NWKV)
#define SEG5 (SEG4 + NWQ)

__global__ void split_all(
    const float* __restrict__ x,  const float* __restrict__ wq,
    const float* __restrict__ wk, const float* __restrict__ wv,
    const float* __restrict__ wo,
    __nv_bfloat16* __restrict__ xh,  __nv_bfloat16* __restrict__ xl,
    __nv_bfloat16* __restrict__ wqh, __nv_bfloat16* __restrict__ wql,
    __nv_bfloat16* __restrict__ wkh, __nv_bfloat16* __restrict__ wkl,
    __nv_bfloat16* __restrict__ wvh, __nv_bfloat16* __restrict__ wvl,
    __nv_bfloat16* __restrict__ woh, __nv_bfloat16* __restrict__ wol)
{
    int i = (blockIdx.x * blockDim.x + threadIdx.x) * 2;
    if (i >= SEG5) return;
    const float* src; __nv_bfloat16 *hi, *lo; int off;
    if      (i < SEG1) { src = x;  hi = xh;  lo = xl;  off = i; }
    else if (i < SEG2) { src = wq; hi = wqh; lo = wql; off = i - SEG1; }
    else if (i < SEG3) { src = wk; hi = wkh; lo = wkl; off = i - SEG2; }
    else if (i < SEG4) { src = wv; hi = wvh; lo = wvl; off = i - SEG3; }
    else               { src = wo; hi = woh; lo = wol; off = i - SEG4; }
    float2 v = *(const float2*)&src[off];
    uint32_t lw, hw = pack2(v.x, v.y, lw);
    *(uint32_t*)&hi[off] = hw;
    *(uint32_t*)&lo[off] = lw;
}

// ---------------- 3x bf16-split GEMM core macros (LDSM fragments) -----------
#define LDG_   40
#define GSTAGE (4 * 128 * LDG_)
#define GEMM_SMEM (2 * GSTAGE * 2)

#define G_PROLOG()                                                           \
    const int tid  = threadIdx.x;                                            \
    const int lane = tid & 31;                                               \
    const int w    = tid >> 5;                                               \
    const int wm   = w >> 2;                                                 \
    const int wn   = w & 3;                                                  \
    const int grp  = lane >> 2;                                              \
    const int tig  = lane & 3;                                               \
    const int lrow16 = lane & 15;                                            \
    const int lcol8  = (lane >> 4) * 8;                                      \
    const int lrow8  = lane & 7;                                             \
    const int bcol8  = ((lane >> 3) & 1) * 8;                                \
    float c[4][4][4];                                                        \
    _Pragma("unroll")                                                        \
    for (int mt = 0; mt < 4; mt++)                                           \
        _Pragma("unroll")                                                    \
        for (int nt = 0; nt < 4; nt++)                                       \
            _Pragma("unroll")                                                \
            for (int i = 0; i < 4; i++) c[mt][nt][i] = 0.f;

#define G_LOAD_STAGE(sidx, k0) do {                                          \
    __nv_bfloat16* Ash_ = smb + (sidx) * GSTAGE;                             \
    __nv_bfloat16* Asl_ = Ash_ + 128 * LDG_;                                 \
    __nv_bfloat16* Wsh_ = Asl_ + 128 * LDG_;                                 \
    __nv_bfloat16* Wsl_ = Wsh_ + 128 * LDG_;                                 \
    _Pragma("unroll")                                                        \
    for (int j_ = 0; j_ < 2; j_++) {                                         \
        int cch_ = tid + j_ * 256;                                           \
        int r_   = cch_ >> 2;                                                \
        int off_ = (cch_ & 3) * 8;                                           \
        cp_async16(Ash_ + r_ * LDG_ + off_, Ah + (size_t)(m0 + r_) * K + (k0) + off_); \
        cp_async16(Asl_ + r_ * LDG_ + off_, Al + (size_t)(m0 + r_) * K + (k0) + off_); \
        cp_async16(Wsh_ + r_ * LDG_ + off_, Wh + (size_t)(n0 + r_) * K + (k0) + off_); \
        cp_async16(Wsl_ + r_ * LDG_ + off_, Wl + (size_t)(n0 + r_) * K + (k0) + off_); \
    }                                                                        \
    CP_COMMIT();                                                             \
} while (0)

#define G_MAINLOOP()                                                         \
    const uint32_t smu_ = (uint32_t)__cvta_generic_to_shared(smb);           \
    G_LOAD_STAGE(0, 0);                                                      \
    const int NIT = K >> 5;                                                  \
    for (int it = 0; it < NIT; it++) {                                       \
        int s = it & 1;                                                      \
        if (it + 1 < NIT) { G_LOAD_STAGE(s ^ 1, (it + 1) << 5); CP_WAIT(1); }\
        else             { CP_WAIT(0); }                                     \
        __syncthreads();                                                     \
        const uint32_t stg_  = smu_ + s * (GSTAGE * 2);                      \
        const uint32_t ashu_ = stg_;                                         \
        const uint32_t aslu_ = stg_ + 128 * LDG_ * 2;                        \
        const uint32_t wshu_ = stg_ + 2 * 128 * LDG_ * 2;                    \
        const uint32_t wslu_ = stg_ + 3 * 128 * LDG_ * 2;                    \
        _Pragma("unroll")                                                    \
        for (int kk = 0; kk < 2; kk++) {                                     \
            uint32_t bh[4][2], bl[4][2];                                     \
            _Pragma("unroll")                                                \
            for (int nt = 0; nt < 4; nt++) {                                 \
                uint32_t bo_ = ((wn * 32 + nt * 8 + lrow8) * LDG_ + kk * 16 + bcol8) * 2; \
                ldsm_x2(bh[nt], wshu_ + bo_);                                \
                ldsm_x2(bl[nt], wslu_ + bo_);                                \
            }                                                                \
            _Pragma("unroll")                                                \
            for (int mt = 0; mt < 4; mt++) {                                 \
                uint32_t ao_ = ((wm * 64 + mt * 16 + lrow16) * LDG_ + kk * 16 + lcol8) * 2; \
                uint32_t ah[4], al[4];                                       \
                ldsm_x4(ah, ashu_ + ao_);                                    \
                ldsm_x4(al, aslu_ + ao_);                                    \
                _Pragma("unroll")                                            \
                for (int nt = 0; nt < 4; nt++) {                             \
                    MMA_BF16(c[mt][nt], ah, bh[nt]);                         \
                    MMA_BF16(c[mt][nt], ah, bl[nt]);                         \
                    MMA_BF16(c[mt][nt], al, bh[nt]);                         \
                }                                                            \
            }                                                                \
        }                                                                    \
        __syncthreads();                                                     \
    }

// ---------------- UNIFIED Q/K/V projection (one launch, 768 CTAs) ----------
__global__ __launch_bounds__(256, 2) void gemm_qkv(
    const __nv_bfloat16* __restrict__ xh,  const __nv_bfloat16* __restrict__ xl,
    const __nv_bfloat16* __restrict__ wqh, const __nv_bfloat16* __restrict__ wql,
    const float* __restrict__ bq,
    const __nv_bfloat16* __restrict__ wkh, const __nv_bfloat16* __restrict__ wkl,
    const float* __restrict__ bk,
    const __nv_bfloat16* __restrict__ wvh, const __nv_bfloat16* __restrict__ wvl,
    const float* __restrict__ bv,
    const float* __restrict__ freqs,
    __nv_bfloat16* __restrict__ qrh, __nv_bfloat16* __restrict__ qrl,
    __nv_bfloat16* __restrict__ krh, __nv_bfloat16* __restrict__ krl,
    float* __restrict__ vout)
{
    extern __shared__ __nv_bfloat16 smb[];
    const int id = blockIdx.x;
    const __nv_bfloat16 *Ah = xh, *Al = xl, *Wh, *Wl;
    const float* bias;
    int m0, n0, role;
    if (id < 512)      { role = 0; m0 = (id >> 4) * 128; n0 = (id & 15) * 128;
                         Wh = wqh; Wl = wql; bias = bq; }
    else if (id < 640) { int t = id - 512; role = 1; m0 = (t >> 2) * 128; n0 = (t & 3) * 128;
                         Wh = wkh; Wl = wkl; bias = bk; }
    else               { int t = id - 640; role = 2; m0 = (t >> 2) * 128; n0 = (t & 3) * 128;
                         Wh = wvh; Wl = wvl; bias = bv; }
    const int K = HID;

    G_PROLOG();
    G_MAINLOOP();

    if (role == 2) {
#pragma unroll
        for (int mt = 0; mt < 4; mt++) {
#pragma unroll
            for (int nt = 0; nt < 4; nt++) {
                int row = m0 + wm * 64 + mt * 16 + grp;
                int col = n0 + wn * 32 + nt * 8 + tig * 2;
                float2 bv2 = *(const float2*)&bias[col];
                *(float2*)&vout[(size_t)row * KVD + col] =
                    make_float2(c[mt][nt][0] + bv2.x, c[mt][nt][1] + bv2.y);
                *(float2*)&vout[(size_t)(row + 8) * KVD + col] =
                    make_float2(c[mt][nt][2] + bv2.x, c[mt][nt][3] + bv2.y);
            }
        }
    } else {
        const int nheads = (role == 0) ? NH : NG;
        __nv_bfloat16* dsth = (role == 0) ? qrh : krh;
        __nv_bfloat16* dstl = (role == 0) ? qrl : krl;
#pragma unroll
        for (int mt = 0; mt < 4; mt++) {
            int row = m0 + wm * 64 + mt * 16 + grp;
            int b_  = row >> 11;
            int s_  = row & (SEQ - 1);
#pragma unroll
            for (int nt = 0; nt < 4; nt++) {
                int col = n0 + wn * 32 + nt * 8 + tig * 2;
                int h_  = col >> 6;
                int d_  = col & 63;
                float2 bv2 = *(const float2*)&bias[col];
                float2 f0 = *(const float2*)&freqs[s_ * HD + d_];
                float2 f1 = *(const float2*)&freqs[(s_ + 8) * HD + d_];
                float v0 = c[mt][nt][0] + bv2.x, v1 = c[mt][nt][1] + bv2.y;
                float v2 = c[mt][nt][2] + bv2.x, v3 = c[mt][nt][3] + bv2.y;
                uint32_t lw0, hw0 = pack2(v0 * f0.x - v1 * f0.y, v0 * f0.y + v1 * f0.x, lw0);
                uint32_t lw1, hw1 = pack2(v2 * f1.x - v3 * f1.y, v2 * f1.y + v3 * f1.x, lw1);
                size_t o0 = ((size_t)(b_ * nheads + h_) * SEQ + s_) * HD + d_;
                size_t o1 = o0 + (size_t)8 * HD;
                *(uint32_t*)&dsth[o0] = hw0;
                *(uint32_t*)&dstl[o0] = lw0;
                *(uint32_t*)&dsth[o1] = hw1;
                *(uint32_t*)&dstl[o1] = lw1;
            }
        }
    }
}

// ---------------- O projection ----------------------------------------------
__global__ __launch_bounds__(256, 2) void gemm_bf16x3(
    const __nv_bfloat16* __restrict__ Ah, const __nv_bfloat16* __restrict__ Al,
    const __nv_bfloat16* __restrict__ Wh, const __nv_bfloat16* __restrict__ Wl,
    const float* __restrict__ bias, float* __restrict__ C,
    int M, int N, int K)
{
    extern __shared__ __nv_bfloat16 smb[];
    const int m0 = blockIdx.y * 128;
    const int n0 = blockIdx.x * 128;
    G_PROLOG();
    G_MAINLOOP();
#pragma unroll
    for (int mt = 0; mt < 4; mt++) {
#pragma unroll
        for (int nt = 0; nt < 4; nt++) {
            int row = m0 + wm * 64 + mt * 16 + grp;
            int col = n0 + wn * 32 + nt * 8 + tig * 2;
            float2 bv = *(const float2*)&bias[col];
            *(float2*)&C[(size_t)row * N + col] =
                make_float2(c[mt][nt][0] + bv.x, c[mt][nt][1] + bv.y);
            *(float2*)&C[(size_t)(row + 8) * N + col] =
                make_float2(c[mt][nt][2] + bv.x, c[mt][nt][3] + bv.y);
        }
    }
}

// V: [b,s,g*64+d] fp32  ->  [b,g,d,s] bf16 hi/lo
__global__ void transpose_v_split(const float* __restrict__ vlin,
                                  __nv_bfloat16* __restrict__ vhi,
                                  __nv_bfloat16* __restrict__ vlo)
{
    int idx = blockIdx.x * blockDim.x + threadIdx.x;
    if (idx >= BSZ * NG * HD * (SEQ / 2)) return;
    int s2 = idx & (SEQ / 2 - 1);
    int d  = (idx >> 10) & (HD - 1);
    int g  = (idx >> 16) & (NG - 1);
    int b  = idx >> 19;
    int s  = s2 * 2;
    float v0 = vlin[(size_t)(b * SEQ + s)     * KVD + g * HD + d];
    float v1 = vlin[(size_t)(b * SEQ + s + 1) * KVD + g * HD + d];
    size_t off = ((size_t)(b * NG + g) * HD + d) * SEQ + s;
    uint32_t lw, hw = pack2(v0, v1, lw);
    *(uint32_t*)&vhi[off] = hw;
    *(uint32_t*)&vlo[off] = lw;
}

// ---------------- flash attention: LDSM + in-register P, 2 CTAs/SM ----------
#define LDB_ 72
#define ATT_SMEM ((2 * 128 * LDB_ + 4 * 64 * LDB_) * 2)

__global__ __launch_bounds__(256, 2) void flash_attn_bf16(
    const __nv_bfloat16* __restrict__ qhi, const __nv_bfloat16* __restrict__ qlo,
    const __nv_bfloat16* __restrict__ khi, const __nv_bfloat16* __restrict__ klo,
    const __nv_bfloat16* __restrict__ vhi, const __nv_bfloat16* __restrict__ vlo,
    __nv_bfloat16* __restrict__ ath, __nv_bfloat16* __restrict__ atl)
{
    extern __shared__ __nv_bfloat16 smb[];
    __nv_bfloat16* Qh = smb;
    __nv_bfloat16* Ql = Qh + 128 * LDB_;
    __nv_bfloat16* Kh = Ql + 128 * LDB_;
    __nv_bfloat16* Kl = Kh + 64 * LDB_;
    __nv_bfloat16* Vh = Kl + 64 * LDB_;
    __nv_bfloat16* Vl = Vh + 64 * LDB_;

    const int tid  = threadIdx.x;
    const int lane = tid & 31;
    const int w    = tid >> 5;
    const int grp  = lane >> 2;
    const int tig  = lane & 3;
    const int lrow16 = lane & 15;
    const int lcol8  = (lane >> 4) * 8;
    const int lrow8  = lane & 7;
    const int bcol8  = ((lane >> 3) & 1) * 8;
    const int qb   = gridDim.x - 1 - blockIdx.x;   // heavy tiles first
    const int bh_  = blockIdx.y;
    const int b    = bh_ >> 5;
    const int h    = bh_ & 31;
    const int g    = h >> 2;
    const int q0   = qb * 128;
    const size_t qoff  = ((size_t)(b * NH + h) * SEQ + q0) * HD;
    const size_t kvoff = (size_t)(b * NG + g) * SEQ * HD;
    const size_t vtoff = (size_t)(b * NG + g) * HD * SEQ;

    const uint32_t smu = (uint32_t)__cvta_generic_to_shared(smb);
    const uint32_t qhu = smu;
    const uint32_t qlu = smu + 128 * LDB_ * 2;
    const uint32_t khu = smu + 256 * LDB_ * 2;
    const uint32_t klu = smu + 320 * LDB_ * 2;
    const uint32_t vhu = smu + 384 * LDB_ * 2;
    const uint32_t vlu = smu + 448 * LDB_ * 2;

    for (int i = tid; i < 1024; i += 256) {
        int r = i >> 3, off = (i & 7) * 8;
        *(uint4*)&Qh[r * LDB_ + off] = *(const uint4*)&qhi[qoff + (size_t)r * HD + off];
        *(uint4*)&Ql[r * LDB_ + off] = *(const uint4*)&qlo[qoff + (size_t)r * HD + off];
    }
    __syncthreads();

    float oacc[8][4];
#pragma unroll
    for (int nt = 0; nt < 8; nt++)
#pragma unroll
        for (int i = 0; i < 4; i++) oacc[nt][i] = 0.f;

    float m0 = -1e30f, m1 = -1e30f, l0 = 0.f, l1 = 0.f;
    const int gq0 = q0 + w * 16 + grp;
    const int gq1 = gq0 + 8;
    const float scale = 0.125f;

    const int nkb = 2 * qb + 2;
    for (int kb = 0; kb < nkb; kb++) {
        const int j0 = kb * 64;
        __syncthreads();
        for (int i = tid; i < 512; i += 256) {
            int r = i >> 3, off = (i & 7) * 8;
            *(uint4*)&Kh[r * LDB_ + off] = *(const uint4*)&khi[kvoff + (size_t)(j0 + r) * HD + off];
            *(uint4*)&Kl[r * LDB_ + off] = *(const uint4*)&klo[kvoff + (size_t)(j0 + r) * HD + off];
            *(uint4*)&Vh[r * LDB_ + off] = *(const uint4*)&vhi[vtoff + (size_t)r * SEQ + j0 + off];
            *(uint4*)&Vl[r * LDB_ + off] = *(const uint4*)&vlo[vtoff + (size_t)r * SEQ + j0 + off];
        }
        __syncthreads();

        // ---- S = Q K^T (all fragments via ldmatrix) ----
        float sacc[8][4];
#pragma unroll
        for (int nt = 0; nt < 8; nt++)
#pragma unroll
            for (int i = 0; i < 4; i++) sacc[nt][i] = 0.f;

#pragma unroll
        for (int kk = 0; kk < 4; kk++) {
            uint32_t qo = ((w * 16 + lrow16) * LDB_ + kk * 16 + lcol8) * 2;
            uint32_t qh2[4], ql2[4];
            ldsm_x4(qh2, qhu + qo);
            ldsm_x4(ql2, qlu + qo);
#pragma unroll
            for (int nt = 0; nt < 8; nt++) {
                uint32_t ko = ((nt * 8 + lrow8) * LDB_ + kk * 16 + bcol8) * 2;
                uint32_t bh2[2], bl2[2];
                ldsm_x2(bh2, khu + ko);
                ldsm_x2(bl2, klu + ko);
                MMA_BF16(sacc[nt], qh2, bh2);
                MMA_BF16(sacc[nt], qh2, bl2);
                MMA_BF16(sacc[nt], ql2, bh2);
            }
        }

        // ---- scale + causal mask ----
        const int colb = j0 + tig * 2;
#pragma unroll
        for (int nt = 0; nt < 8; nt++) {
            int c0g = colb + nt * 8, c1g = c0g + 1;
            sacc[nt][0] = sacc[nt][0] * scale + ((c0g <= gq0) ? 0.f : -1e9f);
            sacc[nt][1] = sacc[nt][1] * scale + ((c1g <= gq0) ? 0.f : -1e9f);
            sacc[nt][2] = sacc[nt][2] * scale + ((c0g <= gq1) ? 0.f : -1e9f);
            sacc[nt][3] = sacc[nt][3] * scale + ((c1g <= gq1) ? 0.f : -1e9f);
        }

        // ---- online softmax ----
        float mx0 = -1e30f, mx1 = -1e30f;
#pragma unroll
        for (int nt = 0; nt < 8; nt++) {
            mx0 = fmaxf(mx0, fmaxf(sacc[nt][0], sacc[nt][1]));
            mx1 = fmaxf(mx1, fmaxf(sacc[nt][2], sacc[nt][3]));
        }
        mx0 = fmaxf(mx0, __shfl_xor_sync(0xffffffffu, mx0, 1));
        mx0 = fmaxf(mx0, __shfl_xor_sync(0xffffffffu, mx0, 2));
        mx1 = fmaxf(mx1, __shfl_xor_sync(0xffffffffu, mx1, 1));
        mx1 = fmaxf(mx1, __shfl_xor_sync(0xffffffffu, mx1, 2));

        float mn0 = fmaxf(m0, mx0), mn1 = fmaxf(m1, mx1);
        float al0 = __expf(m0 - mn0), al1 = __expf(m1 - mn1);
        m0 = mn0; m1 = mn1;

        float ls0 = 0.f, ls1 = 0.f;
#pragma unroll
        for (int nt = 0; nt < 8; nt++) {
            float p00 = __expf(sacc[nt][0] - mn0);
            float p01 = __expf(sacc[nt][1] - mn0);
            float p10 = __expf(sacc[nt][2] - mn1);
            float p11 = __expf(sacc[nt][3] - mn1);
            sacc[nt][0] = p00; sacc[nt][1] = p01;
            sacc[nt][2] = p10; sacc[nt][3] = p11;
            ls0 += p00 + p01; ls1 += p10 + p11;
        }
        ls0 += __shfl_xor_sync(0xffffffffu, ls0, 1);
        ls0 += __shfl_xor_sync(0xffffffffu, ls0, 2);
        ls1 += __shfl_xor_sync(0xffffffffu, ls1, 1);
        ls1 += __shfl_xor_sync(0xffffffffu, ls1, 2);
        l0 = l0 * al0 + ls0;
        l1 = l1 * al1 + ls1;

#pragma unroll
        for (int nt = 0; nt < 8; nt++) {
            oacc[nt][0] *= al0; oacc[nt][1] *= al0;
            oacc[nt][2] *= al1; oacc[nt][3] *= al1;
        }

        // ---- O += P V (P from registers, V via ldmatrix) ----
#pragma unroll
        for (int kk = 0; kk < 4; kk++) {
            uint32_t ah[4], al_[4];
            ah[0] = pack2(sacc[2*kk][0],   sacc[2*kk][1],   al_[0]);
            ah[1] = pack2(sacc[2*kk][2],   sacc[2*kk][3],   al_[1]);
            ah[2] = pack2(sacc[2*kk+1][0], sacc[2*kk+1][1], al_[2]);
            ah[3] = pack2(sacc[2*kk+1][2], sacc[2*kk+1][3], al_[3]);
#pragma unroll
            for (int nt = 0; nt < 8; nt++) {
                uint32_t vo = ((nt * 8 + lrow8) * LDB_ + kk * 16 + bcol8) * 2;
                uint32_t bh2[2], bl2[2];
                ldsm_x2(bh2, vhu + vo);
                ldsm_x2(bl2, vlu + vo);
                MMA_BF16(oacc[nt], ah, bh2);
                MMA_BF16(oacc[nt], ah, bl2);
                MMA_BF16(oacc[nt], al_, bh2);
            }
        }
    }

    // ---- epilogue: normalize + split directly (feeds O-projection) ----
    float inv0 = 1.f / l0, inv1 = 1.f / l1;
    int row0 = q0 + w * 16 + grp;
#pragma unroll
    for (int nt = 0; nt < 8; nt++) {
        int col = h * HD + nt * 8 + tig * 2;
        size_t i0 = (size_t)(b * SEQ + row0) * HID + col;
        size_t i1 = (size_t)(b * SEQ + row0 + 8) * HID + col;
        uint32_t lw0, hw0 = pack2(oacc[nt][0] * inv0, oacc[nt][1] * inv0, lw0);
        uint32_t lw1, hw1 = pack2(oacc[nt][2] * inv1, oacc[nt][3] * inv1, lw1);
        *(uint32_t*)&ath[i0] = hw0;
        *(uint32_t*)&atl[i0] = lw0;
        *(uint32_t*)&ath[i1] = hw1;
        *(uint32_t*)&atl[i1] = lw1;
    }
}

// ---------------- launch ----------------------------------------------------
extern "C" void kernel_launch(void* const* d_in, const int* in_sizes, int n_in,
                              void* d_out, int out_size)
{
    const float* x     = (const float*)d_in[0];
    const float* freqs = (const float*)d_in[1];
    const float* wq = (const float*)d_in[3];
    const float* bq = (const float*)d_in[4];
    const float* wk = (const float*)d_in[5];
    const float* bk = (const float*)d_in[6];
    const float* wv = (const float*)d_in[7];
    const float* bv = (const float*)d_in[8];
    const float* wo = (const float*)d_in[9];
    const float* bo = (const float*)d_in[10];
    float* out = (float*)d_out;

    __nv_bfloat16 *xh, *xl, *wqh, *wql, *wkh, *wkl, *wvh, *wvl, *woh, *wol;
    __nv_bfloat16 *qrh, *qrl, *krh, *krl, *vth, *vtl, *ath, *atl;
    float *pv;
    cudaGetSymbolAddress((void**)&xh,  s_x_hi);  cudaGetSymbolAddress((void**)&xl,  s_x_lo);
    cudaGetSymbolAddress((void**)&wqh, s_wq_hi); cudaGetSymbolAddress((void**)&wql, s_wq_lo);
    cudaGetSymbolAddress((void**)&wkh, s_wk_hi); cudaGetSymbolAddress((void**)&wkl, s_wk_lo);
    cudaGetSymbolAddress((void**)&wvh, s_wv_hi); cudaGetSymbolAddress((void**)&wvl, s_wv_lo);
    cudaGetSymbolAddress((void**)&woh, s_wo_hi); cudaGetSymbolAddress((void**)&wol, s_wo_lo);
    cudaGetSymbolAddress((void**)&qrh, s_qr_hi); cudaGetSymbolAddress((void**)&qrl, s_qr_lo);
    cudaGetSymbolAddress((void**)&krh, s_kr_hi); cudaGetSymbolAddress((void**)&krl, s_kr_lo);
    cudaGetSymbolAddress((void**)&vth, s_vt_hi); cudaGetSymbolAddress((void**)&vtl, s_vt_lo);
    cudaGetSymbolAddress((void**)&ath, s_at_hi); cudaGetSymbolAddress((void**)&atl, s_at_lo);
    cudaGetSymbolAddress((void**)&pv,  g_v);

    cudaFuncSetAttribute(gemm_qkv,
                         cudaFuncAttributeMaxDynamicSharedMemorySize, GEMM_SMEM);
    cudaFuncSetAttribute(gemm_bf16x3,
                         cudaFuncAttributeMaxDynamicSharedMemorySize, GEMM_SMEM);
    cudaFuncSetAttribute(flash_attn_bf16,
                         cudaFuncAttributeMaxDynamicSharedMemorySize, ATT_SMEM);

    split_all<<<(SEG5 / 2 + 255) / 256, 256>>>(
        x, wq, wk, wv, wo,
        xh, xl, wqh, wql, wkh, wkl, wvh, wvl, woh, wol);

    gemm_qkv<<<768, 256, GEMM_SMEM>>>(
        xh, xl, wqh, wql, bq, wkh, wkl, bk, wvh, wvl, bv,
        freqs, qrh, qrl, krh, krl, pv);

    transpose_v_split<<<(BSZ * NG * HD * (SEQ / 2)) / 256, 256>>>(pv, vth, vtl);

    flash_attn_bf16<<<dim3(SEQ / 128, BSZ * NH), 256, ATT_SMEM>>>(
        qrh, qrl, krh, krl, vth, vtl, ath, atl);

    gemm_bf16x3<<<dim3(HID / 128, MROWS / 128), 256, GEMM_SMEM>>>(
        ath, atl, woh, wol, bo, out, MROWS, HID, HID);
}

// round 15
// speedup vs baseline: 1.7677x; 1.0155x over previous
#include <cuda_runtime.h>
#include <cuda_bf16.h>
#include <math.h>
#include <stdint.h>

#define BSZ   2
#define SEQ   2048
#define HID   2048
#define NH    32
#define NG    8
#define HD    64
#define KVD   512
#define MROWS 4096

// ---------------- scratch ---------------------------------------------------
__device__ __nv_bfloat16 s_x_hi [MROWS * HID];
__device__ __nv_bfloat16 s_x_lo [MROWS * HID];
__device__ __nv_bfloat16 s_wq_hi[HID * HID];
__device__ __nv_bfloat16 s_wq_lo[HID * HID];
__device__ __nv_bfloat16 s_wk_hi[KVD * HID];
__device__ __nv_bfloat16 s_wk_lo[KVD * HID];
__device__ __nv_bfloat16 s_wv_hi[KVD * HID];
__device__ __nv_bfloat16 s_wv_lo[KVD * HID];
__device__ __nv_bfloat16 s_wo_hi[HID * HID];
__device__ __nv_bfloat16 s_wo_lo[HID * HID];
__device__ float g_v  [MROWS * KVD];
__device__ __nv_bfloat16 s_qr_hi[BSZ * NH * SEQ * HD];
__device__ __nv_bfloat16 s_qr_lo[BSZ * NH * SEQ * HD];
__device__ __nv_bfloat16 s_kr_hi[BSZ * NG * SEQ * HD];
__device__ __nv_bfloat16 s_kr_lo[BSZ * NG * SEQ * HD];
__device__ __nv_bfloat16 s_vt_hi[BSZ * NG * HD * SEQ];   // [b,g,d,s]
__device__ __nv_bfloat16 s_vt_lo[BSZ * NG * HD * SEQ];
__device__ __nv_bfloat16 s_at_hi[MROWS * HID];
__device__ __nv_bfloat16 s_at_lo[MROWS * HID];

// ---------------- helpers ---------------------------------------------------
__device__ __forceinline__ void cp_async16(void* smem_ptr, const void* gptr) {
    uint32_t s = (uint32_t)__cvta_generic_to_shared(smem_ptr);
    asm volatile("cp.async.cg.shared.global [%0], [%1], 16;\n" :: "r"(s), "l"(gptr));
}
#define CP_COMMIT()  asm volatile("cp.async.commit_group;\n" ::: "memory")
#define CP_WAIT(n)   asm volatile("cp.async.wait_group %0;\n" :: "n"(n) : "memory")

#define MMA_BF16(Cc, Aa, Bb) asm volatile( \
    "mma.sync.aligned.m16n8k16.row.col.f32.bf16.bf16.f32 " \
    "{%0,%1,%2,%3},{%4,%5,%6,%7},{%8,%9},{%0,%1,%2,%3};\n" \
    : "+f"(Cc[0]), "+f"(Cc[1]), "+f"(Cc[2]), "+f"(Cc[3]) \
    : "r"(Aa[0]), "r"(Aa[1]), "r"(Aa[2]), "r"(Aa[3]), "r"(Bb[0]), "r"(Bb[1]))

__device__ __forceinline__ void ldsm_x4(uint32_t* r, uint32_t addr) {
    asm volatile("ldmatrix.sync.aligned.m8n8.x4.shared.b16 {%0,%1,%2,%3}, [%4];"
        : "=r"(r[0]), "=r"(r[1]), "=r"(r[2]), "=r"(r[3]) : "r"(addr));
}
__device__ __forceinline__ void ldsm_x2(uint32_t* r, uint32_t addr) {
    asm volatile("ldmatrix.sync.aligned.m8n8.x2.shared.b16 {%0,%1}, [%2];"
        : "=r"(r[0]), "=r"(r[1]) : "r"(addr));
}

__device__ __forceinline__ float ex2(float x) {
    float r; asm("ex2.approx.f32 %0, %1;" : "=f"(r) : "f"(x)); return r;
}

__device__ __forceinline__ uint32_t pack2(float x0, float x1, uint32_t& lo_out) {
    __nv_bfloat16 h0 = __float2bfloat16(x0);
    __nv_bfloat16 h1 = __float2bfloat16(x1);
    __nv_bfloat16 l0 = __float2bfloat16(x0 - __bfloat162float(h0));
    __nv_bfloat16 l1 = __float2bfloat16(x1 - __bfloat162float(h1));
    __nv_bfloat162 H = __halves2bfloat162(h0, h1);
    __nv_bfloat162 L = __halves2bfloat162(l0, l1);
    lo_out = *(uint32_t*)&L;
    return *(uint32_t*)&H;
}

// ---------------- merged split: x + wq + wk + wv + wo -----------------------
#define NX   (MROWS * HID)
#define NWQ  (HID * HID)
#define NWKV (KVD * HID)
#define SEG1 (NX)
#define SEG2 (SEG1 + NWQ)
#define SEG3 (SEG2 + NWKV)
#define SEG4 (SEG3 + NWKV)
#define SEG5 (SEG4 + NWQ)

__global__ void split_all(
    const float* __restrict__ x,  const float* __restrict__ wq,
    const float* __restrict__ wk, const float* __restrict__ wv,
    const float* __restrict__ wo,
    __nv_bfloat16* __restrict__ xh,  __nv_bfloat16* __restrict__ xl,
    __nv_bfloat16* __restrict__ wqh, __nv_bfloat16* __restrict__ wql,
    __nv_bfloat16* __restrict__ wkh, __nv_bfloat16* __restrict__ wkl,
    __nv_bfloat16* __restrict__ wvh, __nv_bfloat16* __restrict__ wvl,
    __nv_bfloat16* __restrict__ woh, __nv_bfloat16* __restrict__ wol)
{
    int i = (blockIdx.x * blockDim.x + threadIdx.x) * 2;
    if (i >= SEG5) return;
    const float* src; __nv_bfloat16 *hi, *lo; int off;
    if      (i < SEG1) { src = x;  hi = xh;  lo = xl;  off = i; }
    else if (i < SEG2) { src = wq; hi = wqh; lo = wql; off = i - SEG1; }
    else if (i < SEG3) { src = wk; hi = wkh; lo = wkl; off = i - SEG2; }
    else if (i < SEG4) { src = wv; hi = wvh; lo = wvl; off = i - SEG3; }
    else               { src = wo; hi = woh; lo = wol; off = i - SEG4; }
    float2 v = *(const float2*)&src[off];
    uint32_t lw, hw = pack2(v.x, v.y, lw);
    *(uint32_t*)&hi[off] = hw;
    *(uint32_t*)&lo[off] = lw;
}

// ---------------- 3x bf16-split GEMM core macros (LDSM fragments) -----------
#define LDG_   40
#define GSTAGE (4 * 128 * LDG_)
#define GEMM_SMEM (2 * GSTAGE * 2)

#define G_PROLOG()                                                           \
    const int tid  = threadIdx.x;                                            \
    const int lane = tid & 31;                                               \
    const int w    = tid >> 5;                                               \
    const int wm   = w >> 2;                                                 \
    const int wn   = w & 3;                                                  \
    const int grp  = lane >> 2;                                              \
    const int tig  = lane & 3;                                               \
    const int lrow16 = lane & 15;                                            \
    const int lcol8  = (lane >> 4) * 8;                                      \
    const int lrow8  = lane & 7;                                             \
    const int bcol8  = ((lane >> 3) & 1) * 8;                                \
    float c[4][4][4];                                                        \
    _Pragma("unroll")                                                        \
    for (int mt = 0; mt < 4; mt++)                                           \
        _Pragma("unroll")                                                    \
        for (int nt = 0; nt < 4; nt++)                                       \
            _Pragma("unroll")                                                \
            for (int i = 0; i < 4; i++) c[mt][nt][i] = 0.f;

#define G_LOAD_STAGE(sidx, k0) do {                                          \
    __nv_bfloat16* Ash_ = smb + (sidx) * GSTAGE;                             \
    __nv_bfloat16* Asl_ = Ash_ + 128 * LDG_;                                 \
    __nv_bfloat16* Wsh_ = Asl_ + 128 * LDG_;                                 \
    __nv_bfloat16* Wsl_ = Wsh_ + 128 * LDG_;                                 \
    _Pragma("unroll")                                                        \
    for (int j_ = 0; j_ < 2; j_++) {                                         \
        int cch_ = tid + j_ * 256;                                           \
        int r_   = cch_ >> 2;                                                \
        int off_ = (cch_ & 3) * 8;                                           \
        cp_async16(Ash_ + r_ * LDG_ + off_, Ah + (size_t)(m0 + r_) * K + (k0) + off_); \
        cp_async16(Asl_ + r_ * LDG_ + off_, Al + (size_t)(m0 + r_) * K + (k0) + off_); \
        cp_async16(Wsh_ + r_ * LDG_ + off_, Wh + (size_t)(n0 + r_) * K + (k0) + off_); \
        cp_async16(Wsl_ + r_ * LDG_ + off_, Wl + (size_t)(n0 + r_) * K + (k0) + off_); \
    }                                                                        \
    CP_COMMIT();                                                             \
} while (0)

#define G_MAINLOOP()                                                         \
    const uint32_t smu_ = (uint32_t)__cvta_generic_to_shared(smb);           \
    G_LOAD_STAGE(0, 0);                                                      \
    const int NIT = K >> 5;                                                  \
    for (int it = 0; it < NIT; it++) {                                       \
        int s = it & 1;                                                      \
        if (it + 1 < NIT) { G_LOAD_STAGE(s ^ 1, (it + 1) << 5); CP_WAIT(1); }\
        else             { CP_WAIT(0); }                                     \
        __syncthreads();                                                     \
        const uint32_t stg_  = smu_ + s * (GSTAGE * 2);                      \
        const uint32_t ashu_ = stg_;                                         \
        const uint32_t aslu_ = stg_ + 128 * LDG_ * 2;                        \
        const uint32_t wshu_ = stg_ + 2 * 128 * LDG_ * 2;                    \
        const uint32_t wslu_ = stg_ + 3 * 128 * LDG_ * 2;                    \
        _Pragma("unroll")                                                    \
        for (int kk = 0; kk < 2; kk++) {                                     \
            uint32_t bh[4][2], bl[4][2];                                     \
            _Pragma("unroll")                                                \
            for (int nt = 0; nt < 4; nt++) {                                 \
                uint32_t bo_ = ((wn * 32 + nt * 8 + lrow8) * LDG_ + kk * 16 + bcol8) * 2; \
                ldsm_x2(bh[nt], wshu_ + bo_);                                \
                ldsm_x2(bl[nt], wslu_ + bo_);                                \
            }                                                                \
            _Pragma("unroll")                                                \
            for (int mt = 0; mt < 4; mt++) {                                 \
                uint32_t ao_ = ((wm * 64 + mt * 16 + lrow16) * LDG_ + kk * 16 + lcol8) * 2; \
                uint32_t ah[4], al[4];                                       \
                ldsm_x4(ah, ashu_ + ao_);                                    \
                ldsm_x4(al, aslu_ + ao_);                                    \
                _Pragma("unroll")                                            \
                for (int nt = 0; nt < 4; nt++) {                             \
                    MMA_BF16(c[mt][nt], ah, bh[nt]);                         \
                    MMA_BF16(c[mt][nt], ah, bl[nt]);                         \
                    MMA_BF16(c[mt][nt], al, bh[nt]);                         \
                }                                                            \
            }                                                                \
        }                                                                    \
        __syncthreads();                                                     \
    }

// ---------------- UNIFIED Q/K/V projection (one launch, 768 CTAs) ----------
__global__ __launch_bounds__(256, 2) void gemm_qkv(
    const __nv_bfloat16* __restrict__ xh,  const __nv_bfloat16* __restrict__ xl,
    const __nv_bfloat16* __restrict__ wqh, const __nv_bfloat16* __restrict__ wql,
    const float* __restrict__ bq,
    const __nv_bfloat16* __restrict__ wkh, const __nv_bfloat16* __restrict__ wkl,
    const float* __restrict__ bk,
    const __nv_bfloat16* __restrict__ wvh, const __nv_bfloat16* __restrict__ wvl,
    const float* __restrict__ bv,
    const float* __restrict__ freqs,
    __nv_bfloat16* __restrict__ qrh, __nv_bfloat16* __restrict__ qrl,
    __nv_bfloat16* __restrict__ krh, __nv_bfloat16* __restrict__ krl,
    float* __restrict__ vout)
{
    extern __shared__ __nv_bfloat16 smb[];
    const int id = blockIdx.x;
    const __nv_bfloat16 *Ah = xh, *Al = xl, *Wh, *Wl;
    const float* bias;
    int m0, n0, role;
    if (id < 512)      { role = 0; m0 = (id >> 4) * 128; n0 = (id & 15) * 128;
                         Wh = wqh; Wl = wql; bias = bq; }
    else if (id < 640) { int t = id - 512; role = 1; m0 = (t >> 2) * 128; n0 = (t & 3) * 128;
                         Wh = wkh; Wl = wkl; bias = bk; }
    else               { int t = id - 640; role = 2; m0 = (t >> 2) * 128; n0 = (t & 3) * 128;
                         Wh = wvh; Wl = wvl; bias = bv; }
    const int K = HID;

    G_PROLOG();
    G_MAINLOOP();

    if (role == 2) {
#pragma unroll
        for (int mt = 0; mt < 4; mt++) {
#pragma unroll
            for (int nt = 0; nt < 4; nt++) {
                int row = m0 + wm * 64 + mt * 16 + grp;
                int col = n0 + wn * 32 + nt * 8 + tig * 2;
                float2 bv2 = *(const float2*)&bias[col];
                *(float2*)&vout[(size_t)row * KVD + col] =
                    make_float2(c[mt][nt][0] + bv2.x, c[mt][nt][1] + bv2.y);
                *(float2*)&vout[(size_t)(row + 8) * KVD + col] =
                    make_float2(c[mt][nt][2] + bv2.x, c[mt][nt][3] + bv2.y);
            }
        }
    } else {
        const int nheads = (role == 0) ? NH : NG;
        __nv_bfloat16* dsth = (role == 0) ? qrh : krh;
        __nv_bfloat16* dstl = (role == 0) ? qrl : krl;
#pragma unroll
        for (int mt = 0; mt < 4; mt++) {
            int row = m0 + wm * 64 + mt * 16 + grp;
            int b_  = row >> 11;
            int s_  = row & (SEQ - 1);
#pragma unroll
            for (int nt = 0; nt < 4; nt++) {
                int col = n0 + wn * 32 + nt * 8 + tig * 2;
                int h_  = col >> 6;
                int d_  = col & 63;
                float2 bv2 = *(const float2*)&bias[col];
                float2 f0 = *(const float2*)&freqs[s_ * HD + d_];
                float2 f1 = *(const float2*)&freqs[(s_ + 8) * HD + d_];
                float v0 = c[mt][nt][0] + bv2.x, v1 = c[mt][nt][1] + bv2.y;
                float v2 = c[mt][nt][2] + bv2.x, v3 = c[mt][nt][3] + bv2.y;
                uint32_t lw0, hw0 = pack2(v0 * f0.x - v1 * f0.y, v0 * f0.y + v1 * f0.x, lw0);
                uint32_t lw1, hw1 = pack2(v2 * f1.x - v3 * f1.y, v2 * f1.y + v3 * f1.x, lw1);
                size_t o0 = ((size_t)(b_ * nheads + h_) * SEQ + s_) * HD + d_;
                size_t o1 = o0 + (size_t)8 * HD;
                *(uint32_t*)&dsth[o0] = hw0;
                *(uint32_t*)&dstl[o0] = lw0;
                *(uint32_t*)&dsth[o1] = hw1;
                *(uint32_t*)&dstl[o1] = lw1;
            }
        }
    }
}

// ---------------- O projection ----------------------------------------------
__global__ __launch_bounds__(256, 2) void gemm_bf16x3(
    const __nv_bfloat16* __restrict__ Ah, const __nv_bfloat16* __restrict__ Al,
    const __nv_bfloat16* __restrict__ Wh, const __nv_bfloat16* __restrict__ Wl,
    const float* __restrict__ bias, float* __restrict__ C,
    int M, int N, int K)
{
    extern __shared__ __nv_bfloat16 smb[];
    const int m0 = blockIdx.y * 128;
    const int n0 = blockIdx.x * 128;
    G_PROLOG();
    G_MAINLOOP();
#pragma unroll
    for (int mt = 0; mt < 4; mt++) {
#pragma unroll
        for (int nt = 0; nt < 4; nt++) {
            int row = m0 + wm * 64 + mt * 16 + grp;
            int col = n0 + wn * 32 + nt * 8 + tig * 2;
            float2 bv = *(const float2*)&bias[col];
            *(float2*)&C[(size_t)row * N + col] =
                make_float2(c[mt][nt][0] + bv.x, c[mt][nt][1] + bv.y);
            *(float2*)&C[(size_t)(row + 8) * N + col] =
                make_float2(c[mt][nt][2] + bv.x, c[mt][nt][3] + bv.y);
        }
    }
}

// V: [b,s,g*64+d] fp32  ->  [b,g,d,s] bf16 hi/lo
__global__ void transpose_v_split(const float* __restrict__ vlin,
                                  __nv_bfloat16* __restrict__ vhi,
                                  __nv_bfloat16* __restrict__ vlo)
{
    int idx = blockIdx.x * blockDim.x + threadIdx.x;
    if (idx >= BSZ * NG * HD * (SEQ / 2)) return;
    int s2 = idx & (SEQ / 2 - 1);
    int d  = (idx >> 10) & (HD - 1);
    int g  = (idx >> 16) & (NG - 1);
    int b  = idx >> 19;
    int s  = s2 * 2;
    float v0 = vlin[(size_t)(b * SEQ + s)     * KVD + g * HD + d];
    float v1 = vlin[(size_t)(b * SEQ + s + 1) * KVD + g * HD + d];
    size_t off = ((size_t)(b * NG + g) * HD + d) * SEQ + s;
    uint32_t lw, hw = pack2(v0, v1, lw);
    *(uint32_t*)&vhi[off] = hw;
    *(uint32_t*)&vlo[off] = lw;
}

// ---------------- flash attention: cp.async K/V pipeline, LDSM, 2 CTAs/SM ---
#define LDB_ 72
// Q (hi+lo): 256*72, 2 stages x (Kh,Kl,Vh,Vl): 2*4*64*72
#define ATT_SMEM ((256 * LDB_ + 2 * 4 * 64 * LDB_) * 2)

__global__ __launch_bounds__(256, 2) void flash_attn_bf16(
    const __nv_bfloat16* __restrict__ qhi, const __nv_bfloat16* __restrict__ qlo,
    const __nv_bfloat16* __restrict__ khi, const __nv_bfloat16* __restrict__ klo,
    const __nv_bfloat16* __restrict__ vhi, const __nv_bfloat16* __restrict__ vlo,
    __nv_bfloat16* __restrict__ ath, __nv_bfloat16* __restrict__ atl)
{
    extern __shared__ __nv_bfloat16 smb[];
    __nv_bfloat16* Qh = smb;
    __nv_bfloat16* Ql = Qh + 128 * LDB_;

    const int tid  = threadIdx.x;
    const int lane = tid & 31;
    const int w    = tid >> 5;
    const int grp  = lane >> 2;
    const int tig  = lane & 3;
    const int lrow16 = lane & 15;
    const int lcol8  = (lane >> 4) * 8;
    const int lrow8  = lane & 7;
    const int bcol8  = ((lane >> 3) & 1) * 8;
    const int qb   = gridDim.x - 1 - blockIdx.x;   // heavy tiles first
    const int bh_  = blockIdx.y;
    const int b    = bh_ >> 5;
    const int h    = bh_ & 31;
    const int g    = h >> 2;
    const int q0   = qb * 128;
    const size_t qoff  = ((size_t)(b * NH + h) * SEQ + q0) * HD;
    const size_t kvoff = (size_t)(b * NG + g) * SEQ * HD;
    const size_t vtoff = (size_t)(b * NG + g) * HD * SEQ;

    const uint32_t smu = (uint32_t)__cvta_generic_to_shared(smb);
    const uint32_t qhu = smu;
    const uint32_t qlu = smu + 128 * LDB_ * 2;

#define A_PREFETCH(sidx, jj) do {                                            \
    __nv_bfloat16* sb_ = smb + 256 * LDB_ + (sidx) * 4 * 64 * LDB_;          \
    for (int i_ = tid; i_ < 512; i_ += 256) {                                \
        int r_ = i_ >> 3, off_ = (i_ & 7) * 8;                               \
        cp_async16(sb_ + r_ * LDB_ + off_,         khi + kvoff + (size_t)((jj) + r_) * HD + off_); \
        cp_async16(sb_ + (64 + r_) * LDB_ + off_,  klo + kvoff + (size_t)((jj) + r_) * HD + off_); \
        cp_async16(sb_ + (128 + r_) * LDB_ + off_, vhi + vtoff + (size_t)r_ * SEQ + (jj) + off_);  \
        cp_async16(sb_ + (192 + r_) * LDB_ + off_, vlo + vtoff + (size_t)r_ * SEQ + (jj) + off_);  \
    }                                                                        \
    CP_COMMIT();                                                             \
} while (0)

    // prologue: stage 0 prefetch overlaps Q load
    A_PREFETCH(0, 0);
    for (int i = tid; i < 1024; i += 256) {
        int r = i >> 3, off = (i & 7) * 8;
        *(uint4*)&Qh[r * LDB_ + off] = *(const uint4*)&qhi[qoff + (size_t)r * HD + off];
        *(uint4*)&Ql[r * LDB_ + off] = *(const uint4*)&qlo[qoff + (size_t)r * HD + off];
    }

    float oacc[8][4];
#pragma unroll
    for (int nt = 0; nt < 8; nt++)
#pragma unroll
        for (int i = 0; i < 4; i++) oacc[nt][i] = 0.f;

    float m0 = -1e30f, m1 = -1e30f, l0 = 0.f, l1 = 0.f;
    const int gq0 = q0 + w * 16 + grp;
    const int gq1 = gq0 + 8;
    const float scl2 = 0.125f * 1.44269504089f;   // scale * log2(e)

    const int nkb = 2 * qb + 2;
    for (int kb = 0; kb < nkb; kb++) {
        const int j0 = kb * 64;
        const int s  = kb & 1;
        CP_WAIT(0);
        __syncthreads();
        if (kb + 1 < nkb) A_PREFETCH(s ^ 1, (kb + 1) * 64);

        const uint32_t stb = smu + (256 * LDB_ + s * 4 * 64 * LDB_) * 2;
        const uint32_t khu = stb;
        const uint32_t klu = stb + 64 * LDB_ * 2;
        const uint32_t vhu = stb + 128 * LDB_ * 2;
        const uint32_t vlu = stb + 192 * LDB_ * 2;

        // ---- S = Q K^T (all fragments via ldmatrix) ----
        float sacc[8][4];
#pragma unroll
        for (int nt = 0; nt < 8; nt++)
#pragma unroll
            for (int i = 0; i < 4; i++) sacc[nt][i] = 0.f;

#pragma unroll
        for (int kk = 0; kk < 4; kk++) {
            uint32_t qo = ((w * 16 + lrow16) * LDB_ + kk * 16 + lcol8) * 2;
            uint32_t qh2[4], ql2[4];
            ldsm_x4(qh2, qhu + qo);
            ldsm_x4(ql2, qlu + qo);
#pragma unroll
            for (int nt = 0; nt < 8; nt++) {
                uint32_t ko = ((nt * 8 + lrow8) * LDB_ + kk * 16 + bcol8) * 2;
                uint32_t bh2[2], bl2[2];
                ldsm_x2(bh2, khu + ko);
                ldsm_x2(bl2, klu + ko);
                MMA_BF16(sacc[nt], qh2, bh2);
                MMA_BF16(sacc[nt], qh2, bl2);
                MMA_BF16(sacc[nt], ql2, bh2);
            }
        }

        // ---- scale (log2 domain) + causal mask ----
        const int colb = j0 + tig * 2;
#pragma unroll
        for (int nt = 0; nt < 8; nt++) {
            int c0g = colb + nt * 8, c1g = c0g + 1;
            sacc[nt][0] = sacc[nt][0] * scl2 + ((c0g <= gq0) ? 0.f : -1e9f);
            sacc[nt][1] = sacc[nt][1] * scl2 + ((c1g <= gq0) ? 0.f : -1e9f);
            sacc[nt][2] = sacc[nt][2] * scl2 + ((c0g <= gq1) ? 0.f : -1e9f);
            sacc[nt][3] = sacc[nt][3] * scl2 + ((c1g <= gq1) ? 0.f : -1e9f);
        }

        // ---- online softmax (log2 domain) ----
        float mx0 = -1e30f, mx1 = -1e30f;
#pragma unroll
        for (int nt = 0; nt < 8; nt++) {
            mx0 = fmaxf(mx0, fmaxf(sacc[nt][0], sacc[nt][1]));
            mx1 = fmaxf(mx1, fmaxf(sacc[nt][2], sacc[nt][3]));
        }
        mx0 = fmaxf(mx0, __shfl_xor_sync(0xffffffffu, mx0, 1));
        mx0 = fmaxf(mx0, __shfl_xor_sync(0xffffffffu, mx0, 2));
        mx1 = fmaxf(mx1, __shfl_xor_sync(0xffffffffu, mx1, 1));
        mx1 = fmaxf(mx1, __shfl_xor_sync(0xffffffffu, mx1, 2));

        float mn0 = fmaxf(m0, mx0), mn1 = fmaxf(m1, mx1);
        float al0 = ex2(m0 - mn0), al1 = ex2(m1 - mn1);
        m0 = mn0; m1 = mn1;

        float ls0 = 0.f, ls1 = 0.f;
#pragma unroll
        for (int nt = 0; nt < 8; nt++) {
            float p00 = ex2(sacc[nt][0] - mn0);
            float p01 = ex2(sacc[nt][1] - mn0);
            float p10 = ex2(sacc[nt][2] - mn1);
            float p11 = ex2(sacc[nt][3] - mn1);
            sacc[nt][0] = p00; sacc[nt][1] = p01;
            sacc[nt][2] = p10; sacc[nt][3] = p11;
            ls0 += p00 + p01; ls1 += p10 + p11;
        }
        ls0 += __shfl_xor_sync(0xffffffffu, ls0, 1);
        ls0 += __shfl_xor_sync(0xffffffffu, ls0, 2);
        ls1 += __shfl_xor_sync(0xffffffffu, ls1, 1);
        ls1 += __shfl_xor_sync(0xffffffffu, ls1, 2);
        l0 = l0 * al0 + ls0;
        l1 = l1 * al1 + ls1;

#pragma unroll
        for (int nt = 0; nt < 8; nt++) {
            oacc[nt][0] *= al0; oacc[nt][1] *= al0;
            oacc[nt][2] *= al1; oacc[nt][3] *= al1;
        }

        // ---- O += P V (P from registers, V via ldmatrix) ----
#pragma unroll
        for (int kk = 0; kk < 4; kk++) {
            uint32_t ah[4], al_[4];
            ah[0] = pack2(sacc[2*kk][0],   sacc[2*kk][1],   al_[0]);
            ah[1] = pack2(sacc[2*kk][2],   sacc[2*kk][3],   al_[1]);
            ah[2] = pack2(sacc[2*kk+1][0], sacc[2*kk+1][1], al_[2]);
            ah[3] = pack2(sacc[2*kk+1][2], sacc[2*kk+1][3], al_[3]);
#pragma unroll
            for (int nt = 0; nt < 8; nt++) {
                uint32_t vo = ((nt * 8 + lrow8) * LDB_ + kk * 16 + bcol8) * 2;
                uint32_t bh2[2], bl2[2];
                ldsm_x2(bh2, vhu + vo);
                ldsm_x2(bl2, vlu + vo);
                MMA_BF16(oacc[nt], ah, bh2);
                MMA_BF16(oacc[nt], ah, bl2);
                MMA_BF16(oacc[nt], al_, bh2);
            }
        }
    }

    // ---- epilogue: normalize + split directly (feeds O-projection) ----
    float inv0 = 1.f / l0, inv1 = 1.f / l1;
    int row0 = q0 + w * 16 + grp;
#pragma unroll
    for (int nt = 0; nt < 8; nt++) {
        int col = h * HD + nt * 8 + tig * 2;
        size_t i0 = (size_t)(b * SEQ + row0) * HID + col;
        size_t i1 = (size_t)(b * SEQ + row0 + 8) * HID + col;
        uint32_t lw0, hw0 = pack2(oacc[nt][0] * inv0, oacc[nt][1] * inv0, lw0);
        uint32_t lw1, hw1 = pack2(oacc[nt][2] * inv1, oacc[nt][3] * inv1, lw1);
        *(uint32_t*)&ath[i0] = hw0;
        *(uint32_t*)&atl[i0] = lw0;
        *(uint32_t*)&ath[i1] = hw1;
        *(uint32_t*)&atl[i1] = lw1;
    }
}

// ---------------- launch ----------------------------------------------------
extern "C" void kernel_launch(void* const* d_in, const int* in_sizes, int n_in,
                              void* d_out, int out_size)
{
    const float* x     = (const float*)d_in[0];
    const float* freqs = (const float*)d_in[1];
    const float* wq = (const float*)d_in[3];
    const float* bq = (const float*)d_in[4];
    const float* wk = (const float*)d_in[5];
    const float* bk = (const float*)d_in[6];
    const float* wv = (const float*)d_in[7];
    const float* bv = (const float*)d_in[8];
    const float* wo = (const float*)d_in[9];
    const float* bo = (const float*)d_in[10];
    float* out = (float*)d_out;

    __nv_bfloat16 *xh, *xl, *wqh, *wql, *wkh, *wkl, *wvh, *wvl, *woh, *wol;
    __nv_bfloat16 *qrh, *qrl, *krh, *krl, *vth, *vtl, *ath, *atl;
    float *pv;
    cudaGetSymbolAddress((void**)&xh,  s_x_hi);  cudaGetSymbolAddress((void**)&xl,  s_x_lo);
    cudaGetSymbolAddress((void**)&wqh, s_wq_hi); cudaGetSymbolAddress((void**)&wql, s_wq_lo);
    cudaGetSymbolAddress((void**)&wkh, s_wk_hi); cudaGetSymbolAddress((void**)&wkl, s_wk_lo);
    cudaGetSymbolAddress((void**)&wvh, s_wv_hi); cudaGetSymbolAddress((void**)&wvl, s_wv_lo);
    cudaGetSymbolAddress((void**)&woh, s_wo_hi); cudaGetSymbolAddress((void**)&wol, s_wo_lo);
    cudaGetSymbolAddress((void**)&qrh, s_qr_hi); cudaGetSymbolAddress((void**)&qrl, s_qr_lo);
    cudaGetSymbolAddress((void**)&krh, s_kr_hi); cudaGetSymbolAddress((void**)&krl, s_kr_lo);
    cudaGetSymbolAddress((void**)&vth, s_vt_hi); cudaGetSymbolAddress((void**)&vtl, s_vt_lo);
    cudaGetSymbolAddress((void**)&ath, s_at_hi); cudaGetSymbolAddress((void**)&atl, s_at_lo);
    cudaGetSymbolAddress((void**)&pv,  g_v);

    cudaFuncSetAttribute(gemm_qkv,
                         cudaFuncAttributeMaxDynamicSharedMemorySize, GEMM_SMEM);
    cudaFuncSetAttribute(gemm_bf16x3,
                         cudaFuncAttributeMaxDynamicSharedMemorySize, GEMM_SMEM);
    cudaFuncSetAttribute(flash_attn_bf16,
                         cudaFuncAttributeMaxDynamicSharedMemorySize, ATT_SMEM);

    split_all<<<(SEG5 / 2 + 255) / 256, 256>>>(
        x, wq, wk, wv, wo,
        xh, xl, wqh, wql, wkh, wkl, wvh, wvl, woh, wol);

    gemm_qkv<<<768, 256, GEMM_SMEM>>>(
        xh, xl, wqh, wql, bq, wkh, wkl, bk, wvh, wvl, bv,
        freqs, qrh, qrl, krh, krl, pv);

    transpose_v_split<<<(BSZ * NG * HD * (SEQ / 2)) / 256, 256>>>(pv, vth, vtl);

    flash_attn_bf16<<<dim3(SEQ / 128, BSZ * NH), 256, ATT_SMEM>>>(
        qrh, qrl, krh, krl, vth, vtl, ath, atl);

    gemm_bf16x3<<<dim3(HID / 128, MROWS / 128), 256, GEMM_SMEM>>>(
        ath, atl, woh, wol, bo, out, MROWS, HID, HID);
}

// round 16
// speedup vs baseline: 1.8116x; 1.0248x over previous
#include <cuda_runtime.h>
#include <cuda_bf16.h>
#include <math.h>
#include <stdint.h>

#define BSZ   2
#define SEQ   2048
#define HID   2048
#define NH    32
#define NG    8
#define HD    64
#define KVD   512
#define MROWS 4096

// ---------------- scratch ---------------------------------------------------
__device__ __nv_bfloat16 s_x_hi [MROWS * HID];
__device__ __nv_bfloat16 s_x_lo [MROWS * HID];
__device__ __nv_bfloat16 s_wq_hi[HID * HID];
__device__ __nv_bfloat16 s_wq_lo[HID * HID];
__device__ __nv_bfloat16 s_wk_hi[KVD * HID];
__device__ __nv_bfloat16 s_wk_lo[KVD * HID];
__device__ __nv_bfloat16 s_wv_hi[KVD * HID];
__device__ __nv_bfloat16 s_wv_lo[KVD * HID];
__device__ __nv_bfloat16 s_wo_hi[HID * HID];
__device__ __nv_bfloat16 s_wo_lo[HID * HID];
__device__ float g_v  [MROWS * KVD];
__device__ __nv_bfloat16 s_qr_hi[BSZ * NH * SEQ * HD];
__device__ __nv_bfloat16 s_qr_lo[BSZ * NH * SEQ * HD];
__device__ __nv_bfloat16 s_kr_hi[BSZ * NG * SEQ * HD];
__device__ __nv_bfloat16 s_kr_lo[BSZ * NG * SEQ * HD];
__device__ __nv_bfloat16 s_vt_hi[BSZ * NG * HD * SEQ];   // [b,g,d,s]
__device__ __nv_bfloat16 s_vt_lo[BSZ * NG * HD * SEQ];
__device__ __nv_bfloat16 s_at_hi[MROWS * HID];
__device__ __nv_bfloat16 s_at_lo[MROWS * HID];

// ---------------- helpers ---------------------------------------------------
__device__ __forceinline__ void cp_async16(void* smem_ptr, const void* gptr) {
    uint32_t s = (uint32_t)__cvta_generic_to_shared(smem_ptr);
    asm volatile("cp.async.cg.shared.global [%0], [%1], 16;\n" :: "r"(s), "l"(gptr));
}
#define CP_COMMIT()  asm volatile("cp.async.commit_group;\n" ::: "memory")
#define CP_WAIT(n)   asm volatile("cp.async.wait_group %0;\n" :: "n"(n) : "memory")

// non-volatile: register-pure, lets the compiler interleave chains
#define MMA_BF16(Cc, Aa, Bb) asm( \
    "mma.sync.aligned.m16n8k16.row.col.f32.bf16.bf16.f32 " \
    "{%0,%1,%2,%3},{%4,%5,%6,%7},{%8,%9},{%0,%1,%2,%3};\n" \
    : "+f"(Cc[0]), "+f"(Cc[1]), "+f"(Cc[2]), "+f"(Cc[3]) \
    : "r"(Aa[0]), "r"(Aa[1]), "r"(Aa[2]), "r"(Aa[3]), "r"(Bb[0]), "r"(Bb[1]))

__device__ __forceinline__ void ldsm_x4(uint32_t* r, uint32_t addr) {
    asm volatile("ldmatrix.sync.aligned.m8n8.x4.shared.b16 {%0,%1,%2,%3}, [%4];"
        : "=r"(r[0]), "=r"(r[1]), "=r"(r[2]), "=r"(r[3]) : "r"(addr));
}

__device__ __forceinline__ float ex2(float x) {
    float r; asm("ex2.approx.f32 %0, %1;" : "=f"(r) : "f"(x)); return r;
}

__device__ __forceinline__ uint32_t pack2(float x0, float x1, uint32_t& lo_out) {
    __nv_bfloat16 h0 = __float2bfloat16(x0);
    __nv_bfloat16 h1 = __float2bfloat16(x1);
    __nv_bfloat16 l0 = __float2bfloat16(x0 - __bfloat162float(h0));
    __nv_bfloat16 l1 = __float2bfloat16(x1 - __bfloat162float(h1));
    __nv_bfloat162 H = __halves2bfloat162(h0, h1);
    __nv_bfloat162 L = __halves2bfloat162(l0, l1);
    lo_out = *(uint32_t*)&L;
    return *(uint32_t*)&H;
}

// ---------------- merged split: x + wq + wk + wv + wo -----------------------
#define NX   (MROWS * HID)
#define NWQ  (HID * HID)
#define NWKV (KVD * HID)
#define SEG1 (NX)
#define SEG2 (SEG1 + NWQ)
#define SEG3 (SEG2 + NWKV)
#define SEG4 (SEG3 + NWKV)
#define SEG5 (SEG4 + NWQ)

__global__ void split_all(
    const float* __restrict__ x,  const float* __restrict__ wq,
    const float* __restrict__ wk, const float* __restrict__ wv,
    const float* __restrict__ wo,
    __nv_bfloat16* __restrict__ xh,  __nv_bfloat16* __restrict__ xl,
    __nv_bfloat16* __restrict__ wqh, __nv_bfloat16* __restrict__ wql,
    __nv_bfloat16* __restrict__ wkh, __nv_bfloat16* __restrict__ wkl,
    __nv_bfloat16* __restrict__ wvh, __nv_bfloat16* __restrict__ wvl,
    __nv_bfloat16* __restrict__ woh, __nv_bfloat16* __restrict__ wol)
{
    int i = (blockIdx.x * blockDim.x + threadIdx.x) * 2;
    if (i >= SEG5) return;
    const float* src; __nv_bfloat16 *hi, *lo; int off;
    if      (i < SEG1) { src = x;  hi = xh;  lo = xl;  off = i; }
    else if (i < SEG2) { src = wq; hi = wqh; lo = wql; off = i - SEG1; }
    else if (i < SEG3) { src = wk; hi = wkh; lo = wkl; off = i - SEG2; }
    else if (i < SEG4) { src = wv; hi = wvh; lo = wvl; off = i - SEG3; }
    else               { src = wo; hi = woh; lo = wol; off = i - SEG4; }
    float2 v = *(const float2*)&src[off];
    uint32_t lw, hw = pack2(v.x, v.y, lw);
    *(uint32_t*)&hi[off] = hw;
    *(uint32_t*)&lo[off] = lw;
}

// ---------------- 3x bf16-split GEMM core macros (LDSM x4 fragments) --------
#define LDG_   40
#define GSTAGE (4 * 128 * LDG_)
#define GEMM_SMEM (2 * GSTAGE * 2)

#define G_PROLOG()                                                           \
    const int tid  = threadIdx.x;                                            \
    const int lane = tid & 31;                                               \
    const int w    = tid >> 5;                                               \
    const int wm   = w >> 2;                                                 \
    const int wn   = w & 3;                                                  \
    const int grp  = lane >> 2;                                              \
    const int tig  = lane & 3;                                               \
    const int lrow16 = lane & 15;                                            \
    const int lcol8  = (lane >> 4) * 8;                                      \
    const int b4row  = ((lane >> 4) & 1) * 8 + (lane & 7);                   \
    const int b4col  = ((lane >> 3) & 1) * 8;                                \
    float c[4][4][4];                                                        \
    _Pragma("unroll")                                                        \
    for (int mt = 0; mt < 4; mt++)                                           \
        _Pragma("unroll")                                                    \
        for (int nt = 0; nt < 4; nt++)                                       \
            _Pragma("unroll")                                                \
            for (int i = 0; i < 4; i++) c[mt][nt][i] = 0.f;

#define G_LOAD_STAGE(sidx, k0) do {                                          \
    __nv_bfloat16* Ash_ = smb + (sidx) * GSTAGE;                             \
    __nv_bfloat16* Asl_ = Ash_ + 128 * LDG_;                                 \
    __nv_bfloat16* Wsh_ = Asl_ + 128 * LDG_;                                 \
    __nv_bfloat16* Wsl_ = Wsh_ + 128 * LDG_;                                 \
    _Pragma("unroll")                                                        \
    for (int j_ = 0; j_ < 2; j_++) {                                         \
        int cch_ = tid + j_ * 256;                                           \
        int r_   = cch_ >> 2;                                                \
        int off_ = (cch_ & 3) * 8;                                           \
        cp_async16(Ash_ + r_ * LDG_ + off_, Ah + (size_t)(m0 + r_) * K + (k0) + off_); \
        cp_async16(Asl_ + r_ * LDG_ + off_, Al + (size_t)(m0 + r_) * K + (k0) + off_); \
        cp_async16(Wsh_ + r_ * LDG_ + off_, Wh + (size_t)(n0 + r_) * K + (k0) + off_); \
        cp_async16(Wsl_ + r_ * LDG_ + off_, Wl + (size_t)(n0 + r_) * K + (k0) + off_); \
    }                                                                        \
    CP_COMMIT();                                                             \
} while (0)

#define G_MAINLOOP()                                                         \
    const uint32_t smu_ = (uint32_t)__cvta_generic_to_shared(smb);           \
    G_LOAD_STAGE(0, 0);                                                      \
    const int NIT = K >> 5;                                                  \
    for (int it = 0; it < NIT; it++) {                                       \
        int s = it & 1;                                                      \
        if (it + 1 < NIT) { G_LOAD_STAGE(s ^ 1, (it + 1) << 5); CP_WAIT(1); }\
        else             { CP_WAIT(0); }                                     \
        __syncthreads();                                                     \
        const uint32_t stg_  = smu_ + s * (GSTAGE * 2);                      \
        const uint32_t ashu_ = stg_;                                         \
        const uint32_t aslu_ = stg_ + 128 * LDG_ * 2;                        \
        const uint32_t wshu_ = stg_ + 2 * 128 * LDG_ * 2;                    \
        const uint32_t wslu_ = stg_ + 3 * 128 * LDG_ * 2;                    \
        _Pragma("unroll")                                                    \
        for (int kk = 0; kk < 2; kk++) {                                     \
            uint32_t bh[8], bl[8];                                           \
            _Pragma("unroll")                                                \
            for (int np = 0; np < 2; np++) {                                 \
                uint32_t bo_ = ((wn * 32 + np * 16 + b4row) * LDG_ + kk * 16 + b4col) * 2; \
                ldsm_x4(bh + np * 4, wshu_ + bo_);                           \
                ldsm_x4(bl + np * 4, wslu_ + bo_);                           \
            }                                                                \
            _Pragma("unroll")                                                \
            for (int mt = 0; mt < 4; mt++) {                                 \
                uint32_t ao_ = ((wm * 64 + mt * 16 + lrow16) * LDG_ + kk * 16 + lcol8) * 2; \
                uint32_t ah[4], al[4];                                       \
                ldsm_x4(ah, ashu_ + ao_);                                    \
                ldsm_x4(al, aslu_ + ao_);                                    \
                _Pragma("unroll")                                            \
                for (int nt = 0; nt < 4; nt++) MMA_BF16(c[mt][nt], ah, (bh + nt * 2)); \
                _Pragma("unroll")                                            \
                for (int nt = 0; nt < 4; nt++) MMA_BF16(c[mt][nt], ah, (bl + nt * 2)); \
                _Pragma("unroll")                                            \
                for (int nt = 0; nt < 4; nt++) MMA_BF16(c[mt][nt], al, (bh + nt * 2)); \
            }                                                                \
        }                                                                    \
        __syncthreads();                                                     \
    }

// ---------------- UNIFIED Q/K/V projection (one launch, 768 CTAs) ----------
__global__ __launch_bounds__(256, 2) void gemm_qkv(
    const __nv_bfloat16* __restrict__ xh,  const __nv_bfloat16* __restrict__ xl,
    const __nv_bfloat16* __restrict__ wqh, const __nv_bfloat16* __restrict__ wql,
    const float* __restrict__ bq,
    const __nv_bfloat16* __restrict__ wkh, const __nv_bfloat16* __restrict__ wkl,
    const float* __restrict__ bk,
    const __nv_bfloat16* __restrict__ wvh, const __nv_bfloat16* __restrict__ wvl,
    const float* __restrict__ bv,
    const float* __restrict__ freqs,
    __nv_bfloat16* __restrict__ qrh, __nv_bfloat16* __restrict__ qrl,
    __nv_bfloat16* __restrict__ krh, __nv_bfloat16* __restrict__ krl,
    float* __restrict__ vout)
{
    extern __shared__ __nv_bfloat16 smb[];
    const int id = blockIdx.x;
    const __nv_bfloat16 *Ah = xh, *Al = xl, *Wh, *Wl;
    const float* bias;
    int m0, n0, role;
    if (id < 512)      { role = 0; m0 = (id >> 4) * 128; n0 = (id & 15) * 128;
                         Wh = wqh; Wl = wql; bias = bq; }
    else if (id < 640) { int t = id - 512; role = 1; m0 = (t >> 2) * 128; n0 = (t & 3) * 128;
                         Wh = wkh; Wl = wkl; bias = bk; }
    else               { int t = id - 640; role = 2; m0 = (t >> 2) * 128; n0 = (t & 3) * 128;
                         Wh = wvh; Wl = wvl; bias = bv; }
    const int K = HID;

    G_PROLOG();
    G_MAINLOOP();

    if (role == 2) {
#pragma unroll
        for (int mt = 0; mt < 4; mt++) {
#pragma unroll
            for (int nt = 0; nt < 4; nt++) {
                int row = m0 + wm * 64 + mt * 16 + grp;
                int col = n0 + wn * 32 + nt * 8 + tig * 2;
                float2 bv2 = *(const float2*)&bias[col];
                *(float2*)&vout[(size_t)row * KVD + col] =
                    make_float2(c[mt][nt][0] + bv2.x, c[mt][nt][1] + bv2.y);
                *(float2*)&vout[(size_t)(row + 8) * KVD + col] =
                    make_float2(c[mt][nt][2] + bv2.x, c[mt][nt][3] + bv2.y);
            }
        }
    } else {
        const int nheads = (role == 0) ? NH : NG;
        __nv_bfloat16* dsth = (role == 0) ? qrh : krh;
        __nv_bfloat16* dstl = (role == 0) ? qrl : krl;
#pragma unroll
        for (int mt = 0; mt < 4; mt++) {
            int row = m0 + wm * 64 + mt * 16 + grp;
            int b_  = row >> 11;
            int s_  = row & (SEQ - 1);
#pragma unroll
            for (int nt = 0; nt < 4; nt++) {
                int col = n0 + wn * 32 + nt * 8 + tig * 2;
                int h_  = col >> 6;
                int d_  = col & 63;
                float2 bv2 = *(const float2*)&bias[col];
                float2 f0 = *(const float2*)&freqs[s_ * HD + d_];
                float2 f1 = *(const float2*)&freqs[(s_ + 8) * HD + d_];
                float v0 = c[mt][nt][0] + bv2.x, v1 = c[mt][nt][1] + bv2.y;
                float v2 = c[mt][nt][2] + bv2.x, v3 = c[mt][nt][3] + bv2.y;
                uint32_t lw0, hw0 = pack2(v0 * f0.x - v1 * f0.y, v0 * f0.y + v1 * f0.x, lw0);
                uint32_t lw1, hw1 = pack2(v2 * f1.x - v3 * f1.y, v2 * f1.y + v3 * f1.x, lw1);
                size_t o0 = ((size_t)(b_ * nheads + h_) * SEQ + s_) * HD + d_;
                size_t o1 = o0 + (size_t)8 * HD;
                *(uint32_t*)&dsth[o0] = hw0;
                *(uint32_t*)&dstl[o0] = lw0;
                *(uint32_t*)&dsth[o1] = hw1;
                *(uint32_t*)&dstl[o1] = lw1;
            }
        }
    }
}

// ---------------- O projection ----------------------------------------------
__global__ __launch_bounds__(256, 2) void gemm_bf16x3(
    const __nv_bfloat16* __restrict__ Ah, const __nv_bfloat16* __restrict__ Al,
    const __nv_bfloat16* __restrict__ Wh, const __nv_bfloat16* __restrict__ Wl,
    const float* __restrict__ bias, float* __restrict__ C,
    int M, int N, int K)
{
    extern __shared__ __nv_bfloat16 smb[];
    const int m0 = blockIdx.y * 128;
    const int n0 = blockIdx.x * 128;
    G_PROLOG();
    G_MAINLOOP();
#pragma unroll
    for (int mt = 0; mt < 4; mt++) {
#pragma unroll
        for (int nt = 0; nt < 4; nt++) {
            int row = m0 + wm * 64 + mt * 16 + grp;
            int col = n0 + wn * 32 + nt * 8 + tig * 2;
            float2 bv = *(const float2*)&bias[col];
            *(float2*)&C[(size_t)row * N + col] =
                make_float2(c[mt][nt][0] + bv.x, c[mt][nt][1] + bv.y);
            *(float2*)&C[(size_t)(row + 8) * N + col] =
                make_float2(c[mt][nt][2] + bv.x, c[mt][nt][3] + bv.y);
        }
    }
}

// V: [b,s,g*64+d] fp32  ->  [b,g,d,s] bf16 hi/lo
__global__ void transpose_v_split(const float* __restrict__ vlin,
                                  __nv_bfloat16* __restrict__ vhi,
                                  __nv_bfloat16* __restrict__ vlo)
{
    int idx = blockIdx.x * blockDim.x + threadIdx.x;
    if (idx >= BSZ * NG * HD * (SEQ / 2)) return;
    int s2 = idx & (SEQ / 2 - 1);
    int d  = (idx >> 10) & (HD - 1);
    int g  = (idx >> 16) & (NG - 1);
    int b  = idx >> 19;
    int s  = s2 * 2;
    float v0 = vlin[(size_t)(b * SEQ + s)     * KVD + g * HD + d];
    float v1 = vlin[(size_t)(b * SEQ + s + 1) * KVD + g * HD + d];
    size_t off = ((size_t)(b * NG + g) * HD + d) * SEQ + s;
    uint32_t lw, hw = pack2(v0, v1, lw);
    *(uint32_t*)&vhi[off] = hw;
    *(uint32_t*)&vlo[off] = lw;
}

// ---------------- flash attention: cp.async pipeline + x4 LDSM --------------
#define LDB_ 72
#define ATT_SMEM ((256 * LDB_ + 2 * 4 * 64 * LDB_) * 2)

__global__ __launch_bounds__(256, 2) void flash_attn_bf16(
    const __nv_bfloat16* __restrict__ qhi, const __nv_bfloat16* __restrict__ qlo,
    const __nv_bfloat16* __restrict__ khi, const __nv_bfloat16* __restrict__ klo,
    const __nv_bfloat16* __restrict__ vhi, const __nv_bfloat16* __restrict__ vlo,
    __nv_bfloat16* __restrict__ ath, __nv_bfloat16* __restrict__ atl)
{
    extern __shared__ __nv_bfloat16 smb[];
    __nv_bfloat16* Qh = smb;
    __nv_bfloat16* Ql = Qh + 128 * LDB_;

    const int tid  = threadIdx.x;
    const int lane = tid & 31;
    const int w    = tid >> 5;
    const int grp  = lane >> 2;
    const int tig  = lane & 3;
    const int lrow16 = lane & 15;
    const int lcol8  = (lane >> 4) * 8;
    const int b4row  = ((lane >> 4) & 1) * 8 + (lane & 7);
    const int b4col  = ((lane >> 3) & 1) * 8;
    const int qb   = gridDim.x - 1 - blockIdx.x;   // heavy tiles first
    const int bh_  = blockIdx.y;
    const int b    = bh_ >> 5;
    const int h    = bh_ & 31;
    const int g    = h >> 2;
    const int q0   = qb * 128;
    const size_t qoff  = ((size_t)(b * NH + h) * SEQ + q0) * HD;
    const size_t kvoff = (size_t)(b * NG + g) * SEQ * HD;
    const size_t vtoff = (size_t)(b * NG + g) * HD * SEQ;

    const uint32_t smu = (uint32_t)__cvta_generic_to_shared(smb);
    const uint32_t qhu = smu;
    const uint32_t qlu = smu + 128 * LDB_ * 2;

#define A_PREFETCH(sidx, jj) do {                                            \
    __nv_bfloat16* sb_ = smb + 256 * LDB_ + (sidx) * 4 * 64 * LDB_;          \
    for (int i_ = tid; i_ < 512; i_ += 256) {                                \
        int r_ = i_ >> 3, off_ = (i_ & 7) * 8;                               \
        cp_async16(sb_ + r_ * LDB_ + off_,         khi + kvoff + (size_t)((jj) + r_) * HD + off_); \
        cp_async16(sb_ + (64 + r_) * LDB_ + off_,  klo + kvoff + (size_t)((jj) + r_) * HD + off_); \
        cp_async16(sb_ + (128 + r_) * LDB_ + off_, vhi + vtoff + (size_t)r_ * SEQ + (jj) + off_);  \
        cp_async16(sb_ + (192 + r_) * LDB_ + off_, vlo + vtoff + (size_t)r_ * SEQ + (jj) + off_);  \
    }                                                                        \
    CP_COMMIT();                                                             \
} while (0)

    A_PREFETCH(0, 0);
    for (int i = tid; i < 1024; i += 256) {
        int r = i >> 3, off = (i & 7) * 8;
        *(uint4*)&Qh[r * LDB_ + off] = *(const uint4*)&qhi[qoff + (size_t)r * HD + off];
        *(uint4*)&Ql[r * LDB_ + off] = *(const uint4*)&qlo[qoff + (size_t)r * HD + off];
    }

    float oacc[8][4];
#pragma unroll
    for (int nt = 0; nt < 8; nt++)
#pragma unroll
        for (int i = 0; i < 4; i++) oacc[nt][i] = 0.f;

    float m0 = -1e30f, m1 = -1e30f, l0 = 0.f, l1 = 0.f;
    const int gq0 = q0 + w * 16 + grp;
    const int gq1 = gq0 + 8;
    const float scl2 = 0.125f * 1.44269504089f;

    const int nkb = 2 * qb + 2;
    for (int kb = 0; kb < nkb; kb++) {
        const int j0 = kb * 64;
        const int s  = kb & 1;
        CP_WAIT(0);
        __syncthreads();
        if (kb + 1 < nkb) A_PREFETCH(s ^ 1, (kb + 1) * 64);

        const uint32_t stb = smu + (256 * LDB_ + s * 4 * 64 * LDB_) * 2;
        const uint32_t khu = stb;
        const uint32_t klu = stb + 64 * LDB_ * 2;
        const uint32_t vhu = stb + 128 * LDB_ * 2;
        const uint32_t vlu = stb + 192 * LDB_ * 2;

        // ---- S = Q K^T (A x4; B x4 over nt-pairs) ----
        float sacc[8][4];
#pragma unroll
        for (int nt = 0; nt < 8; nt++)
#pragma unroll
            for (int i = 0; i < 4; i++) sacc[nt][i] = 0.f;

#pragma unroll
        for (int kk = 0; kk < 4; kk++) {
            uint32_t qo = ((w * 16 + lrow16) * LDB_ + kk * 16 + lcol8) * 2;
            uint32_t qh2[4], ql2[4];
            ldsm_x4(qh2, qhu + qo);
            ldsm_x4(ql2, qlu + qo);
#pragma unroll
            for (int np = 0; np < 4; np++) {
                uint32_t ko = ((np * 16 + b4row) * LDB_ + kk * 16 + b4col) * 2;
                uint32_t th[4], tl[4];
                ldsm_x4(th, khu + ko);
                ldsm_x4(tl, klu + ko);
                MMA_BF16(sacc[2*np],   qh2, (th));
                MMA_BF16(sacc[2*np+1], qh2, (th + 2));
                MMA_BF16(sacc[2*np],   qh2, (tl));
                MMA_BF16(sacc[2*np+1], qh2, (tl + 2));
                MMA_BF16(sacc[2*np],   ql2, (th));
                MMA_BF16(sacc[2*np+1], ql2, (th + 2));
            }
        }

        // ---- scale (log2 domain) + causal mask ----
        const int colb = j0 + tig * 2;
#pragma unroll
        for (int nt = 0; nt < 8; nt++) {
            int c0g = colb + nt * 8, c1g = c0g + 1;
            sacc[nt][0] = sacc[nt][0] * scl2 + ((c0g <= gq0) ? 0.f : -1e9f);
            sacc[nt][1] = sacc[nt][1] * scl2 + ((c1g <= gq0) ? 0.f : -1e9f);
            sacc[nt][2] = sacc[nt][2] * scl2 + ((c0g <= gq1) ? 0.f : -1e9f);
            sacc[nt][3] = sacc[nt][3] * scl2 + ((c1g <= gq1) ? 0.f : -1e9f);
        }

        // ---- online softmax (log2 domain) ----
        float mx0 = -1e30f, mx1 = -1e30f;
#pragma unroll
        for (int nt = 0; nt < 8; nt++) {
            mx0 = fmaxf(mx0, fmaxf(sacc[nt][0], sacc[nt][1]));
            mx1 = fmaxf(mx1, fmaxf(sacc[nt][2], sacc[nt][3]));
        }
        mx0 = fmaxf(mx0, __shfl_xor_sync(0xffffffffu, mx0, 1));
        mx0 = fmaxf(mx0, __shfl_xor_sync(0xffffffffu, mx0, 2));
        mx1 = fmaxf(mx1, __shfl_xor_sync(0xffffffffu, mx1, 1));
        mx1 = fmaxf(mx1, __shfl_xor_sync(0xffffffffu, mx1, 2));

        float mn0 = fmaxf(m0, mx0), mn1 = fmaxf(m1, mx1);
        float al0 = ex2(m0 - mn0), al1 = ex2(m1 - mn1);
        m0 = mn0; m1 = mn1;

        float ls0 = 0.f, ls1 = 0.f;
#pragma unroll
        for (int nt = 0; nt < 8; nt++) {
            float p00 = ex2(sacc[nt][0] - mn0);
            float p01 = ex2(sacc[nt][1] - mn0);
            float p10 = ex2(sacc[nt][2] - mn1);
            float p11 = ex2(sacc[nt][3] - mn1);
            sacc[nt][0] = p00; sacc[nt][1] = p01;
            sacc[nt][2] = p10; sacc[nt][3] = p11;
            ls0 += p00 + p01; ls1 += p10 + p11;
        }
        ls0 += __shfl_xor_sync(0xffffffffu, ls0, 1);
        ls0 += __shfl_xor_sync(0xffffffffu, ls0, 2);
        ls1 += __shfl_xor_sync(0xffffffffu, ls1, 1);
        ls1 += __shfl_xor_sync(0xffffffffu, ls1, 2);
        l0 = l0 * al0 + ls0;
        l1 = l1 * al1 + ls1;

#pragma unroll
        for (int nt = 0; nt < 8; nt++) {
            oacc[nt][0] *= al0; oacc[nt][1] *= al0;
            oacc[nt][2] *= al1; oacc[nt][3] *= al1;
        }

        // ---- O += P V (P in registers; V x4 over nt-pairs) ----
#pragma unroll
        for (int kk = 0; kk < 4; kk++) {
            uint32_t ah[4], al_[4];
            ah[0] = pack2(sacc[2*kk][0],   sacc[2*kk][1],   al_[0]);
            ah[1] = pack2(sacc[2*kk][2],   sacc[2*kk][3],   al_[1]);
            ah[2] = pack2(sacc[2*kk+1][0], sacc[2*kk+1][1], al_[2]);
            ah[3] = pack2(sacc[2*kk+1][2], sacc[2*kk+1][3], al_[3]);
#pragma unroll
            for (int np = 0; np < 4; np++) {
                uint32_t vo = ((np * 16 + b4row) * LDB_ + kk * 16 + b4col) * 2;
                uint32_t th[4], tl[4];
                ldsm_x4(th, vhu + vo);
                ldsm_x4(tl, vlu + vo);
                MMA_BF16(oacc[2*np],   ah,  (th));
                MMA_BF16(oacc[2*np+1], ah,  (th + 2));
                MMA_BF16(oacc[2*np],   ah,  (tl));
                MMA_BF16(oacc[2*np+1], ah,  (tl + 2));
                MMA_BF16(oacc[2*np],   al_, (th));
                MMA_BF16(oacc[2*np+1], al_, (th + 2));
            }
        }
    }

    // ---- epilogue: normalize + split directly (feeds O-projection) ----
    float inv0 = 1.f / l0, inv1 = 1.f / l1;
    int row0 = q0 + w * 16 + grp;
#pragma unroll
    for (int nt = 0; nt < 8; nt++) {
        int col = h * HD + nt * 8 + tig * 2;
        size_t i0 = (size_t)(b * SEQ + row0) * HID + col;
        size_t i1 = (size_t)(b * SEQ + row0 + 8) * HID + col;
        uint32_t lw0, hw0 = pack2(oacc[nt][0] * inv0, oacc[nt][1] * inv0, lw0);
        uint32_t lw1, hw1 = pack2(oacc[nt][2] * inv1, oacc[nt][3] * inv1, lw1);
        *(uint32_t*)&ath[i0] = hw0;
        *(uint32_t*)&atl[i0] = lw0;
        *(uint32_t*)&ath[i1] = hw1;
        *(uint32_t*)&atl[i1] = lw1;
    }
}

// ---------------- launch ----------------------------------------------------
extern "C" void kernel_launch(void* const* d_in, const int* in_sizes, int n_in,
                              void* d_out, int out_size)
{
    const float* x     = (const float*)d_in[0];
    const float* freqs = (const float*)d_in[1];
    const float* wq = (const float*)d_in[3];
    const float* bq = (const float*)d_in[4];
    const float* wk = (const float*)d_in[5];
    const float* bk = (const float*)d_in[6];
    const float* wv = (const float*)d_in[7];
    const float* bv = (const float*)d_in[8];
    const float* wo = (const float*)d_in[9];
    const float* bo = (const float*)d_in[10];
    float* out = (float*)d_out;

    __nv_bfloat16 *xh, *xl, *wqh, *wql, *wkh, *wkl, *wvh, *wvl, *woh, *wol;
    __nv_bfloat16 *qrh, *qrl, *krh, *krl, *vth, *vtl, *ath, *atl;
    float *pv;
    cudaGetSymbolAddress((void**)&xh,  s_x_hi);  cudaGetSymbolAddress((void**)&xl,  s_x_lo);
    cudaGetSymbolAddress((void**)&wqh, s_wq_hi); cudaGetSymbolAddress((void**)&wql, s_wq_lo);
    cudaGetSymbolAddress((void**)&wkh, s_wk_hi); cudaGetSymbolAddress((void**)&wkl, s_wk_lo);
    cudaGetSymbolAddress((void**)&wvh, s_wv_hi); cudaGetSymbolAddress((void**)&wvl, s_wv_lo);
    cudaGetSymbolAddress((void**)&woh, s_wo_hi); cudaGetSymbolAddress((void**)&wol, s_wo_lo);
    cudaGetSymbolAddress((void**)&qrh, s_qr_hi); cudaGetSymbolAddress((void**)&qrl, s_qr_lo);
    cudaGetSymbolAddress((void**)&krh, s_kr_hi); cudaGetSymbolAddress((void**)&krl, s_kr_lo);
    cudaGetSymbolAddress((void**)&vth, s_vt_hi); cudaGetSymbolAddress((void**)&vtl, s_vt_lo);
    cudaGetSymbolAddress((void**)&ath, s_at_hi); cudaGetSymbolAddress((void**)&atl, s_at_lo);
    cudaGetSymbolAddress((void**)&pv,  g_v);

    cudaFuncSetAttribute(gemm_qkv,
                         cudaFuncAttributeMaxDynamicSharedMemorySize, GEMM_SMEM);
    cudaFuncSetAttribute(gemm_bf16x3,
                         cudaFuncAttributeMaxDynamicSharedMemorySize, GEMM_SMEM);
    cudaFuncSetAttribute(flash_attn_bf16,
                         cudaFuncAttributeMaxDynamicSharedMemorySize, ATT_SMEM);

    split_all<<<(SEG5 / 2 + 255) / 256, 256>>>(
        x, wq, wk, wv, wo,
        xh, xl, wqh, wql, wkh, wkl, wvh, wvl, woh, wol);

    gemm_qkv<<<768, 256, GEMM_SMEM>>>(
        xh, xl, wqh, wql, bq, wkh, wkl, bk, wvh, wvl, bv,
        freqs, qrh, qrl, krh, krl, pv);

    transpose_v_split<<<(BSZ * NG * HD * (SEQ / 2)) / 256, 256>>>(pv, vth, vtl);

    flash_attn_bf16<<<dim3(SEQ / 128, BSZ * NH), 256, ATT_SMEM>>>(
        qrh, qrl, krh, krl, vth, vtl, ath, atl);

    gemm_bf16x3<<<dim3(HID / 128, MROWS / 128), 256, GEMM_SMEM>>>(
        ath, atl, woh, wol, bo, out, MROWS, HID, HID);
}